// round 6
// baseline (speedup 1.0000x reference)
#include <cuda_runtime.h>
#include <cuda_bf16.h>
#include <math.h>
#include <stdint.h>
#include <stddef.h>

// ---------------- problem constants ----------------
#define Bv      16
#define Kv      2
#define Ev      768
#define Hv      12
#define HSv     64
#define Lv      12
#define Tv      621
#define TP      640          // padded T for attention tiles
#define NPATCH  588
#define QKVLD   2304
#define E4      3072
#define AOUTv   64
#define MTv     (Bv*Tv)      // 9936
#define MPATCH  (Bv*NPATCH)  // 9408
#define ZH      (Bv*Hv)      // 192
#define SCALE_QK 0.036084391824351615f

#define CDIV(a,b) (((a)+(b)-1)/(b))
#define TGSMEM   98304       // 2 stages x 48KB
#define QKSMEM   65536
#define PVSMEM   49152

typedef __nv_bfloat16 bf16;

// ---------------- scratch ----------------
__device__ __align__(128) float g_POS[Tv*Ev];
__device__ __align__(128) float g_X  [(size_t)MTv*Ev];
__device__ __align__(128) float g_S  [(size_t)ZH*TP*TP];     // scores fp32 (also dummy-gemm dump)
__device__ __align__(128) float g_Z  [Bv*Ev];

__device__ __align__(128) bf16 g_Hhi [(size_t)MTv*Ev];
__device__ __align__(128) bf16 g_Hlo [(size_t)MTv*Ev];
__device__ __align__(128) bf16 g_Ohi [(size_t)MTv*Ev];
__device__ __align__(128) bf16 g_Olo [(size_t)MTv*Ev];
__device__ __align__(128) bf16 g_Fhi [(size_t)MTv*E4];
__device__ __align__(128) bf16 g_Flo [(size_t)MTv*E4];
__device__ __align__(128) bf16 g_XPhi[(size_t)MPATCH*Ev];
__device__ __align__(128) bf16 g_XPlo[(size_t)MPATCH*Ev];
__device__ __align__(128) bf16 g_QKVh[(size_t)MTv*QKVLD];
__device__ __align__(128) bf16 g_QKVl[(size_t)MTv*QKVLD];
__device__ __align__(128) bf16 g_Ph  [(size_t)ZH*TP*TP];     // probs hi (pad rows/cols stay 0)
__device__ __align__(128) bf16 g_Pl  [(size_t)ZH*TP*TP];
__device__ __align__(128) bf16 g_Vth [(size_t)ZH*HSv*TP];    // V transposed [z][d][s]
__device__ __align__(128) bf16 g_Vtl [(size_t)ZH*HSv*TP];

__device__ __align__(128) bf16 g_Wqkv_h[(size_t)Lv*QKVLD*Ev];
__device__ __align__(128) bf16 g_Wqkv_l[(size_t)Lv*QKVLD*Ev];
__device__ __align__(128) bf16 g_Wprj_h[(size_t)Lv*Ev*Ev];
__device__ __align__(128) bf16 g_Wprj_l[(size_t)Lv*Ev*Ev];
__device__ __align__(128) bf16 g_Wf1_h [(size_t)Lv*E4*Ev];
__device__ __align__(128) bf16 g_Wf1_l [(size_t)Lv*E4*Ev];
__device__ __align__(128) bf16 g_Wf2_h [(size_t)Lv*Ev*E4];
__device__ __align__(128) bf16 g_Wf2_l [(size_t)Lv*Ev*E4];
__device__ __align__(128) bf16 g_Wpat_h[(size_t)Ev*Ev];
__device__ __align__(128) bf16 g_Wpat_l[(size_t)Ev*Ev];

// ---------------- helpers ----------------
__device__ __forceinline__ uint32_t smem_u32(const void* p) {
    uint32_t a;
    asm("{ .reg .u64 t; cvta.to.shared.u64 t, %1; cvt.u32.u64 %0, t; }" : "=r"(a) : "l"(p));
    return a;
}
__device__ __forceinline__ void cp16(uint32_t sa, const void* ga, bool v) {
    int sz = v ? 16 : 0;
    asm volatile("cp.async.cg.shared.global [%0], [%1], 16, %2;" :: "r"(sa), "l"(ga), "r"(sz) : "memory");
}
#define CP_COMMIT() asm volatile("cp.async.commit_group;" ::: "memory")
#define CP_WAIT0()  asm volatile("cp.async.wait_group 0;" ::: "memory")

#define LDSM4(r, a) \
    asm volatile("ldmatrix.sync.aligned.m8n8.x4.shared.b16 {%0,%1,%2,%3}, [%4];" \
        : "=r"((r)[0]),"=r"((r)[1]),"=r"((r)[2]),"=r"((r)[3]) : "r"(a))

__device__ __forceinline__ void mma16816(float* d, const uint32_t* a, const uint32_t* b) {
    asm volatile("mma.sync.aligned.m16n8k16.row.col.f32.bf16.bf16.f32 "
        "{%0,%1,%2,%3}, {%4,%5,%6,%7}, {%8,%9}, {%0,%1,%2,%3};"
        : "+f"(d[0]),"+f"(d[1]),"+f"(d[2]),"+f"(d[3])
        : "r"(a[0]),"r"(a[1]),"r"(a[2]),"r"(a[3]), "r"(b[0]),"r"(b[1]));
}

__device__ __forceinline__ void bf_split(float v, bf16* hi, bf16* lo) {
    bf16 h = __float2bfloat16(v);
    *hi = h;
    *lo = __float2bfloat16(v - __bfloat162float(h));
}

// ---------------- mask ----------------
__device__ __forceinline__ bool keep_fn(int t, int s) {
    bool v = (t == s);
    if (s < 32) v = !(t >= 32 && t < 228);
    if (t >= 228 && s >= 228 && s < 424) v = true;
    if (t >= 424 && s >= 424 && s < 620) v = true;
    return v;
}

// ---------------- positional embedding ----------------
__global__ void pos_kernel(float* POS) {
    int idx = blockIdx.x * 256 + threadIdx.x;
    if (idx >= Tv * Ev) return;
    int t = idx / Ev, j = idx % Ev;
    double expo = (double)(j & ~1) / (double)Ev;
    double ang  = (double)t / pow(10000.0, expo);
    POS[idx] = (float)((j & 1) ? cos(ang) : sin(ang));
}

// ---------------- transpose+convert weights ----------------
__global__ void transpose_conv(const float* __restrict__ src, bf16* __restrict__ dhi,
                               bf16* __restrict__ dlo, int R, int C) {
    __shared__ float t[32][33];
    int z = blockIdx.z;
    src += (size_t)z * R * C; dhi += (size_t)z * R * C; dlo += (size_t)z * R * C;
    int c0 = blockIdx.x * 32, r0 = blockIdx.y * 32;
    int tx = threadIdx.x, ty = threadIdx.y;
    #pragma unroll
    for (int i = 0; i < 4; i++)
        t[ty + 8*i][tx] = src[(size_t)(r0 + ty + 8*i) * C + c0 + tx];
    __syncthreads();
    #pragma unroll
    for (int i = 0; i < 4; i++) {
        float v = t[tx][ty + 8*i];
        size_t o = (size_t)(c0 + ty + 8*i) * R + r0 + tx;
        bf_split(v, dhi + o, dlo + o);
    }
}

__global__ void conv_wqkv(const float* __restrict__ wq, const float* __restrict__ wk,
                          const float* __restrict__ wv, bf16* __restrict__ dhi, bf16* __restrict__ dlo) {
    __shared__ float t[32][33];
    int z = blockIdx.z;
    int h = z % Hv, which = (z / Hv) % 3, l = z / (3 * Hv);
    const float* src = (which == 0) ? wq : (which == 1) ? wk : wv;
    src += ((size_t)l * Hv + h) * Ev * HSv;
    int d0 = blockIdx.x * 32, e0 = blockIdx.y * 32;
    int tx = threadIdx.x, ty = threadIdx.y;
    #pragma unroll
    for (int i = 0; i < 4; i++)
        t[ty + 8*i][tx] = src[(size_t)(e0 + ty + 8*i) * HSv + d0 + tx];
    __syncthreads();
    #pragma unroll
    for (int i = 0; i < 4; i++) {
        int d = d0 + ty + 8*i, e = e0 + tx;
        float v = t[tx][ty + 8*i];
        size_t o = ((size_t)l * QKVLD + which * Ev + h * HSv + d) * Ev + e;
        bf_split(v, dhi + o, dlo + o);
    }
}

// ---------------- gather patches ----------------
__global__ void gather_patches(const float* __restrict__ images, const float* __restrict__ goal_imgs,
                               bf16* __restrict__ Xhi, bf16* __restrict__ Xlo) {
    int idx = blockIdx.x * 256 + threadIdx.x;
    if (idx >= MPATCH * Ev) return;
    int f = idx % Ev;
    int r = idx / Ev;
    int p = r % NPATCH;
    int b = r / NPATCH;
    int py = f / 48, px = (f % 48) / 3, c = f % 3;
    float val;
    if (p < 196) {
        int pr = p / 14, pc = p % 14;
        int y = pr * 16 + py, x = pc * 16 + px;
        val = goal_imgs[(((size_t)b * 224 + y) * 224 + x) * 3 + c];
    } else {
        int q = p - 196;
        int k = q / 196, pp = q % 196;
        int pr = pp / 14, pc = pp % 14;
        int y = pr * 16 + py, x = pc * 16 + px;
        val = images[((((size_t)b * Kv + k) * 224 + y) * 224 + x) * 3 + c];
    }
    bf_split(val, Xhi + idx, Xlo + idx);
}

// ---------------- text + action embed (+POS) ----------------
__global__ void embed_txt_act(const int* __restrict__ goals_txt, const float* __restrict__ text_emb,
                              const float* __restrict__ action_emb, const float* __restrict__ POS,
                              float* __restrict__ X) {
    int idx = blockIdx.x * 256 + threadIdx.x;
    if (idx >= Bv * 33 * Ev) return;
    int e  = idx % Ev;
    int r  = idx / Ev;
    int tt = r % 33;
    int b  = r / 33;
    int t  = (tt < 32) ? tt : 620;
    float v = (tt < 32) ? text_emb[(size_t)goals_txt[b * 32 + tt] * Ev + e] : action_emb[e];
    X[((size_t)b * Tv + t) * Ev + e] = v + POS[(size_t)t * Ev + e];
}

// ---------------- layernorm -> hi/lo bf16 ----------------
__global__ void ln_kernel(const float* __restrict__ X, bf16* __restrict__ Ohi, bf16* __restrict__ Olo,
                          const float* __restrict__ sc, const float* __restrict__ bi) {
    int row = blockIdx.x;
    const float* x = X + (size_t)row * Ev;
    __shared__ float r1[256], r2[256];
    int tid = threadIdx.x;
    float s = 0.f, ss = 0.f;
    for (int e = tid; e < Ev; e += 256) { float v = x[e]; s += v; ss += v * v; }
    r1[tid] = s; r2[tid] = ss;
    __syncthreads();
    for (int off = 128; off; off >>= 1) {
        if (tid < off) { r1[tid] += r1[tid + off]; r2[tid] += r2[tid + off]; }
        __syncthreads();
    }
    float m   = r1[0] * (1.f / Ev);
    float var = r2[0] * (1.f / Ev) - m * m;
    float inv = 1.f / sqrtf(var + 1e-5f);
    for (int e = tid; e < Ev; e += 256) {
        float v = (x[e] - m) * inv * sc[e] + bi[e];
        size_t o = (size_t)row * Ev + e;
        bf_split(v, Ohi + o, Olo + o);
    }
}

// =====================================================================
// bf16x3 linear GEMM (mma.sync), 256x128 tile, warp tile 64x64, Kc=32
// stage: Ahi 16K @0, Alo 16K @16K, Bhi 8K @32K, Blo 8K @40K  (48K/stage)
// =====================================================================
__global__ void __launch_bounds__(256, 1)
tgemm(int M, int N, int K,
      const bf16* __restrict__ Ahi, const bf16* __restrict__ Alo,
      const bf16* __restrict__ Bhi, const bf16* __restrict__ Blo,
      const float* __restrict__ bias,
      const float* __restrict__ rowmat, int ldrm, int rmode,
      float* outF, int ldo, int accf, int reluf,
      bf16* outHi, bf16* outLo)
{
    extern __shared__ char sm[];
    uint32_t sbase = smem_u32(sm);
    int tid = threadIdx.x, lane = tid & 31, wid = tid >> 5;
    int m0 = blockIdx.y * 256, n0 = blockIdx.x * 128;
    int wm = wid & 3, wn = wid >> 2;   // warp rows: wm*64, warp cols: wn*64

    float acc[4][8][4];
    #pragma unroll
    for (int i = 0; i < 4; i++)
        #pragma unroll
        for (int j = 0; j < 8; j++)
            #pragma unroll
            for (int q = 0; q < 4; q++) acc[i][j][q] = 0.f;

    int nc = K >> 5;

    auto ld_st = [&](int c, int st) {
        uint32_t sb = sbase + st * 49152;
        int k0 = c * 32;
        #pragma unroll
        for (int i = 0; i < 4; i++) {              // A: 256 rows x 4 segs
            int u = i * 256 + tid;
            int row = u >> 2, seg = u & 3;
            uint32_t off = (uint32_t)(row * 64 + ((seg ^ ((row >> 1) & 3)) << 4));
            bool av = (m0 + row) < M;
            size_t ao = (size_t)(av ? (m0 + row) : 0) * K + k0 + seg * 8;
            cp16(sb + off,         Ahi + ao, av);
            cp16(sb + 16384 + off, Alo + ao, av);
        }
        #pragma unroll
        for (int i = 0; i < 2; i++) {              // B: 128 rows x 4 segs
            int u = i * 256 + tid;
            int row = u >> 2, seg = u & 3;
            uint32_t off = (uint32_t)(row * 64 + ((seg ^ ((row >> 1) & 3)) << 4));
            size_t bo = (size_t)(n0 + row) * K + k0 + seg * 8;
            cp16(sb + 32768 + off, Bhi + bo, true);
            cp16(sb + 40960 + off, Blo + bo, true);
        }
        CP_COMMIT();
    };

    ld_st(0, 0);

    for (int c = 0; c < nc; c++) {
        int s = c & 1;
        CP_WAIT0();
        __syncthreads();
        if (c + 1 < nc) ld_st(c + 1, 1 - s);

        uint32_t sA_hi = sbase + s * 49152;
        uint32_t sA_lo = sA_hi + 16384;
        uint32_t sB_hi = sA_hi + 32768;
        uint32_t sB_lo = sA_hi + 40960;

        #pragma unroll
        for (int ks = 0; ks < 2; ks++) {
            uint32_t afh[4][4], afl[4][4];
            #pragma unroll
            for (int mt = 0; mt < 4; mt++) {
                int matA = lane >> 3;
                int arow = wm * 64 + mt * 16 + (lane & 7) + (matA & 1) * 8;
                int aseg = ks * 2 + (matA >> 1);
                uint32_t off = (uint32_t)(arow * 64 + ((aseg ^ ((arow >> 1) & 3)) << 4));
                LDSM4(afh[mt], sA_hi + off);
                LDSM4(afl[mt], sA_lo + off);
            }
            #pragma unroll
            for (int np = 0; np < 4; np++) {
                uint32_t bfh[4], bfl[4];
                int matB = lane >> 3;
                int brow = wn * 64 + np * 16 + ((matB >> 1) << 3) + (lane & 7);
                int bseg = ks * 2 + (matB & 1);
                uint32_t boff = (uint32_t)(brow * 64 + ((bseg ^ ((brow >> 1) & 3)) << 4));
                LDSM4(bfh, sB_hi + boff);
                LDSM4(bfl, sB_lo + boff);
                // term-major: 8 independent MMAs per group
                #pragma unroll
                for (int t = 0; t < 2; t++)
                    #pragma unroll
                    for (int mt = 0; mt < 4; mt++)
                        mma16816(acc[mt][np * 2 + t], afh[mt], bfh + 2 * t);
                #pragma unroll
                for (int t = 0; t < 2; t++)
                    #pragma unroll
                    for (int mt = 0; mt < 4; mt++)
                        mma16816(acc[mt][np * 2 + t], afh[mt], bfl + 2 * t);
                #pragma unroll
                for (int t = 0; t < 2; t++)
                    #pragma unroll
                    for (int mt = 0; mt < 4; mt++)
                        mma16816(acc[mt][np * 2 + t], afl[mt], bfh + 2 * t);
            }
        }
    }

    int r_l = lane >> 2, c_l = (lane & 3) * 2;
    #pragma unroll
    for (int mt = 0; mt < 4; mt++) {
        #pragma unroll
        for (int h = 0; h < 2; h++) {
            int rr = m0 + wm * 64 + mt * 16 + h * 8 + r_l;
            if (rr >= M) continue;
            int orow = rr, prow = rr;
            if (rmode) {
                int b = rr / NPATCH, p = rr - b * NPATCH;
                orow = b * Tv + 32 + p;
                prow = 32 + p;
            }
            #pragma unroll
            for (int j = 0; j < 8; j++) {
                int col = n0 + wn * 64 + j * 8 + c_l;
                float v0 = acc[mt][j][2 * h];
                float v1 = acc[mt][j][2 * h + 1];
                if (bias)   { v0 += bias[col]; v1 += bias[col + 1]; }
                if (rowmat) { const float* rp = rowmat + (size_t)prow * ldrm + col; v0 += rp[0]; v1 += rp[1]; }
                if (accf)   { const float* op = outF + (size_t)orow * ldo + col;   v0 += op[0]; v1 += op[1]; }
                if (reluf)  { v0 = fmaxf(v0, 0.f); v1 = fmaxf(v1, 0.f); }
                if (outF)   *(float2*)(outF + (size_t)orow * ldo + col) = make_float2(v0, v1);
                if (outHi) {
                    size_t o = (size_t)rr * N + col;
                    bf_split(v0, outHi + o, outLo + o);
                    bf_split(v1, outHi + o + 1, outLo + o + 1);
                }
            }
        }
    }
}

// =====================================================================
// qk_mma: S[z][t][s] = (Q K^T)*scale ; 128x128 tile, K=64 one-shot
// =====================================================================
__global__ void __launch_bounds__(256, 2)
qk_mma(const bf16* __restrict__ Qh, const bf16* __restrict__ Ql, float* __restrict__ S)
{
    extern __shared__ char sm[];
    uint32_t sbase = smem_u32(sm);     // +0 Qhi, +16K Qlo, +32K Khi, +48K Klo (128 rows x 128B)
    int tid = threadIdx.x, lane = tid & 31, wid = tid >> 5;
    int z = blockIdx.z, b = z / Hv, h = z % Hv;
    int t0 = blockIdx.y * 128, s0 = blockIdx.x * 128;

    #pragma unroll
    for (int i = 0; i < 4; i++) {
        int u = i * 256 + tid;
        int row = u >> 3, seg = u & 7;
        uint32_t off = (uint32_t)(row * 128 + ((seg ^ (row & 7)) << 4));
        bool qv = (t0 + row) < Tv;
        bool kv = (s0 + row) < Tv;
        size_t qo = (size_t)(b * Tv + (qv ? t0 + row : 0)) * QKVLD + h * HSv + seg * 8;
        size_t ko = (size_t)(b * Tv + (kv ? s0 + row : 0)) * QKVLD + Ev + h * HSv + seg * 8;
        cp16(sbase + off,         Qh + qo, qv);
        cp16(sbase + 16384 + off, Ql + qo, qv);
        cp16(sbase + 32768 + off, Qh + ko, kv);
        cp16(sbase + 49152 + off, Ql + ko, kv);
    }
    CP_COMMIT();
    CP_WAIT0();
    __syncthreads();

    int wm = wid & 3, wn = wid >> 2;
    float acc[2][8][4];
    #pragma unroll
    for (int i = 0; i < 2; i++)
        #pragma unroll
        for (int j = 0; j < 8; j++)
            #pragma unroll
            for (int q = 0; q < 4; q++) acc[i][j][q] = 0.f;

    #pragma unroll
    for (int ks = 0; ks < 4; ks++) {
        uint32_t afh[2][4], afl[2][4];
        #pragma unroll
        for (int mt = 0; mt < 2; mt++) {
            int matA = lane >> 3;
            int arow = wm * 32 + mt * 16 + (lane & 7) + (matA & 1) * 8;
            int aseg = ks * 2 + (matA >> 1);
            uint32_t off = (uint32_t)(arow * 128 + ((aseg ^ (arow & 7)) << 4));
            LDSM4(afh[mt], sbase + off);
            LDSM4(afl[mt], sbase + 16384 + off);
        }
        #pragma unroll
        for (int np = 0; np < 4; np++) {
            uint32_t bfh[4], bfl[4];
            int matB = lane >> 3;
            int brow = wn * 64 + np * 16 + ((matB >> 1) << 3) + (lane & 7);
            int bseg = ks * 2 + (matB & 1);
            uint32_t boff = (uint32_t)(brow * 128 + ((bseg ^ (brow & 7)) << 4));
            LDSM4(bfh, sbase + 32768 + boff);
            LDSM4(bfl, sbase + 49152 + boff);
            #pragma unroll
            for (int t = 0; t < 2; t++)
                #pragma unroll
                for (int mt = 0; mt < 2; mt++)
                    mma16816(acc[mt][np * 2 + t], afh[mt], bfh + 2 * t);
            #pragma unroll
            for (int t = 0; t < 2; t++)
                #pragma unroll
                for (int mt = 0; mt < 2; mt++)
                    mma16816(acc[mt][np * 2 + t], afh[mt], bfl + 2 * t);
            #pragma unroll
            for (int t = 0; t < 2; t++)
                #pragma unroll
                for (int mt = 0; mt < 2; mt++)
                    mma16816(acc[mt][np * 2 + t], afl[mt], bfh + 2 * t);
        }
    }

    int r_l = lane >> 2, c_l = (lane & 3) * 2;
    #pragma unroll
    for (int mt = 0; mt < 2; mt++)
        #pragma unroll
        for (int h2 = 0; h2 < 2; h2++) {
            int rr = t0 + wm * 32 + mt * 16 + h2 * 8 + r_l;
            #pragma unroll
            for (int j = 0; j < 8; j++) {
                int col = s0 + wn * 64 + j * 8 + c_l;
                float2 v = make_float2(acc[mt][j][2 * h2] * SCALE_QK,
                                       acc[mt][j][2 * h2 + 1] * SCALE_QK);
                *(float2*)(S + ((size_t)z * TP + rr) * TP + col) = v;
            }
        }
}

// ---------------- masked softmax: S fp32 -> P hi/lo bf16 (cols padded 0) ----------------
__global__ void softmax_kernel(const float* __restrict__ S,
                               bf16* __restrict__ Ph, bf16* __restrict__ Pl)
{
    int t = blockIdx.x, z = blockIdx.y;
    const float* row = S + ((size_t)z * TP + t) * TP;
    bf16* ph = Ph + ((size_t)z * TP + t) * TP;
    bf16* pl = Pl + ((size_t)z * TP + t) * TP;
    __shared__ float red[256];
    int tid = threadIdx.x;
    float mx = -3.0e38f;
    #pragma unroll
    for (int i = 0; i < 3; i++) {
        int s = tid + i * 256;
        if (s < TP && keep_fn(t, s)) mx = fmaxf(mx, row[s]);
    }
    red[tid] = mx; __syncthreads();
    for (int off = 128; off; off >>= 1) {
        if (tid < off) red[tid] = fmaxf(red[tid], red[tid + off]);
        __syncthreads();
    }
    mx = red[0]; __syncthreads();
    float pv[3]; float sum = 0.f;
    #pragma unroll
    for (int i = 0; i < 3; i++) {
        int s = tid + i * 256;
        float p = 0.f;
        if (s < TP && keep_fn(t, s)) p = expf(row[s] - mx);
        pv[i] = p; sum += p;
    }
    red[tid] = sum; __syncthreads();
    for (int off = 128; off; off >>= 1) {
        if (tid < off) red[tid] += red[tid + off];
        __syncthreads();
    }
    float inv = 1.f / red[0];
    #pragma unroll
    for (int i = 0; i < 3; i++) {
        int s = tid + i * 256;
        if (s < TP) bf_split(pv[i] * inv, ph + s, pl + s);
    }
}

// ---------------- V repack: QKV v-part -> Vt[z][d][s] hi/lo (s padded 0) ----------------
__global__ void repack_v(const bf16* __restrict__ Qh, const bf16* __restrict__ Ql,
                         bf16* __restrict__ Vth, bf16* __restrict__ Vtl)
{
    __shared__ bf16 th[32][33], tl[32][33];
    int z = blockIdx.z, b = z / Hv, h = z % Hv;
    int s0 = blockIdx.x * 32, d0 = blockIdx.y * 32;
    int tx = threadIdx.x, ty = threadIdx.y;
    #pragma unroll
    for (int i = 0; i < 4; i++) {
        int s = s0 + ty + 8 * i;
        bf16 vh = __float2bfloat16(0.f), vl = vh;
        if (s < Tv) {
            size_t o = (size_t)(b * Tv + s) * QKVLD + 2 * Ev + h * HSv + d0 + tx;
            vh = Qh[o]; vl = Ql[o];
        }
        th[ty + 8 * i][tx] = vh;
        tl[ty + 8 * i][tx] = vl;
    }
    __syncthreads();
    #pragma unroll
    for (int i = 0; i < 4; i++) {
        size_t o = ((size_t)z * HSv + d0 + ty + 8 * i) * TP + s0 + tx;
        Vth[o] = th[tx][ty + 8 * i];
        Vtl[o] = tl[tx][ty + 8 * i];
    }
}

// =====================================================================
// pv_mma: O[z][t][d] = P @ V^T-layout ; tile 128x64, Kc=32, 20 chunks
// =====================================================================
__global__ void __launch_bounds__(256, 2)
pv_mma(const bf16* __restrict__ Ph, const bf16* __restrict__ Pl,
       const bf16* __restrict__ Vth, const bf16* __restrict__ Vtl,
       bf16* __restrict__ Ohi, bf16* __restrict__ Olo)
{
    extern __shared__ char sm[];
    uint32_t sbase = smem_u32(sm);
    // stage layout (24KB): +0 P_hi 8K, +8K P_lo 8K, +16K V_hi 4K, +20K V_lo 4K
    int tid = threadIdx.x, lane = tid & 31, wid = tid >> 5;
    int z = blockIdx.y, b = z / Hv, h = z % Hv;
    int t0 = blockIdx.x * 128;
    int wm = wid & 3, wn = wid >> 2;

    float acc[2][4][4];
    #pragma unroll
    for (int i = 0; i < 2; i++)
        #pragma unroll
        for (int j = 0; j < 4; j++)
            #pragma unroll
            for (int q = 0; q < 4; q++) acc[i][j][q] = 0.f;

    auto ld_st = [&](int c, int st) {
        uint32_t sb = sbase + st * 24576;
        int k0 = c * 32;
        {
            int u = tid;
            int row = u >> 1, seg0 = (u & 1) * 2;
            #pragma unroll
            for (int q = 0; q < 2; q++) {
                int seg = seg0 + q;
                uint32_t off = (uint32_t)(row * 64 + ((seg ^ ((row >> 1) & 3)) << 4));
                size_t po = ((size_t)z * TP + t0 + row) * TP + k0 + seg * 8;
                cp16(sb + off,        Ph + po, true);
                cp16(sb + 8192 + off, Pl + po, true);
            }
        }
        {
            int row = tid >> 2, seg = tid & 3;
            uint32_t off = (uint32_t)(row * 64 + ((seg ^ ((row >> 1) & 3)) << 4));
            size_t vo = ((size_t)z * HSv + row) * TP + k0 + seg * 8;
            cp16(sb + 16384 + off, Vth + vo, true);
            cp16(sb + 20480 + off, Vtl + vo, true);
        }
        CP_COMMIT();
    };

    ld_st(0, 0);

    for (int c = 0; c < TP / 32; c++) {
        int s = c & 1;
        CP_WAIT0();
        __syncthreads();
        if (c + 1 < TP / 32) ld_st(c + 1, 1 - s);

        uint32_t sP_hi = sbase + s * 24576;
        uint32_t sP_lo = sP_hi + 8192;
        uint32_t sV_hi = sP_hi + 16384;
        uint32_t sV_lo = sP_hi + 20480;

        #pragma unroll
        for (int ks = 0; ks < 2; ks++) {
            uint32_t afh[2][4], afl[2][4];
            #pragma unroll
            for (int mt = 0; mt < 2; mt++) {
                int matA = lane >> 3;
                int arow = wm * 32 + mt * 16 + (lane & 7) + (matA & 1) * 8;
                int aseg = ks * 2 + (matA >> 1);
                uint32_t off = (uint32_t)(arow * 64 + ((aseg ^ ((arow >> 1) & 3)) << 4));
                LDSM4(afh[mt], sP_hi + off);
                LDSM4(afl[mt], sP_lo + off);
            }
            #pragma unroll
            for (int np = 0; np < 2; np++) {
                uint32_t bfh[4], bfl[4];
                int matB = lane >> 3;
                int brow = wn * 32 + np * 16 + ((matB >> 1) << 3) + (lane & 7);
                int bseg = ks * 2 + (matB & 1);
                uint32_t boff = (uint32_t)(brow * 64 + ((bseg ^ ((brow >> 1) & 3)) << 4));
                LDSM4(bfh, sV_hi + boff);
                LDSM4(bfl, sV_lo + boff);
                #pragma unroll
                for (int t = 0; t < 2; t++)
                    #pragma unroll
                    for (int mt = 0; mt < 2; mt++)
                        mma16816(acc[mt][np * 2 + t], afh[mt], bfh + 2 * t);
                #pragma unroll
                for (int t = 0; t < 2; t++)
                    #pragma unroll
                    for (int mt = 0; mt < 2; mt++)
                        mma16816(acc[mt][np * 2 + t], afh[mt], bfl + 2 * t);
                #pragma unroll
                for (int t = 0; t < 2; t++)
                    #pragma unroll
                    for (int mt = 0; mt < 2; mt++)
                        mma16816(acc[mt][np * 2 + t], afl[mt], bfh + 2 * t);
            }
        }
    }

    int r_l = lane >> 2, c_l = (lane & 3) * 2;
    #pragma unroll
    for (int mt = 0; mt < 2; mt++)
        #pragma unroll
        for (int h2 = 0; h2 < 2; h2++) {
            int rr = t0 + wm * 32 + mt * 16 + h2 * 8 + r_l;
            if (rr >= Tv) continue;
            #pragma unroll
            for (int j = 0; j < 4; j++) {
                int col = wn * 32 + j * 8 + c_l;
                size_t o = ((size_t)(b * Tv + rr)) * Ev + h * HSv + col;
                bf_split(acc[mt][j][2 * h2],     Ohi + o,     Olo + o);
                bf_split(acc[mt][j][2 * h2 + 1], Ohi + o + 1, Olo + o + 1);
            }
        }
}

// ---------------- fp32 GEMM (head only) ----------------
__global__ void __launch_bounds__(256, 2)
sgemm128(int M, int N, int K,
         const float* __restrict__ A, int lda,
         const float* __restrict__ B, int ldb,
         float* __restrict__ C, int ldc,
         const float* __restrict__ bias, int reluflag)
{
    __shared__ __align__(16) float As[8][128];
    __shared__ __align__(16) float Bs[8][128];
    int n0 = blockIdx.x * 128, m0 = blockIdx.y * 128;
    int tid = threadIdx.x;
    int tx = tid & 15, ty = tid >> 4;
    int arow = tid >> 1,  akk  = (tid & 1) * 4;
    int bkk  = tid >> 5,  bcol = (tid & 31) * 4;
    bool aval = (m0 + arow) < M;
    bool bval = (n0 + bcol) < N;
    const float* Aptr = A + (size_t)(m0 + arow) * lda + akk;
    const float* Bptr = B + (size_t)bkk * ldb + n0 + bcol;
    float acc[8][8];
    #pragma unroll
    for (int i = 0; i < 8; i++)
        #pragma unroll
        for (int j = 0; j < 8; j++) acc[i][j] = 0.f;
    for (int k0 = 0; k0 < K; k0 += 8) {
        float4 av = make_float4(0.f,0.f,0.f,0.f), bv = make_float4(0.f,0.f,0.f,0.f);
        if (aval) av = *(const float4*)(Aptr + k0);
        if (bval) bv = *(const float4*)(Bptr + (size_t)k0 * ldb);
        __syncthreads();
        As[akk+0][arow] = av.x; As[akk+1][arow] = av.y;
        As[akk+2][arow] = av.z; As[akk+3][arow] = av.w;
        *(float4*)&Bs[bkk][bcol] = bv;
        __syncthreads();
        #pragma unroll
        for (int kk = 0; kk < 8; kk++) {
            float a[8], b2[8];
            *(float4*)(a)    = *(const float4*)&As[kk][ty*8];
            *(float4*)(a+4)  = *(const float4*)&As[kk][ty*8+4];
            *(float4*)(b2)   = *(const float4*)&Bs[kk][tx*8];
            *(float4*)(b2+4) = *(const float4*)&Bs[kk][tx*8+4];
            #pragma unroll
            for (int i = 0; i < 8; i++)
                #pragma unroll
                for (int j = 0; j < 8; j++)
                    acc[i][j] += a[i] * b2[j];
        }
    }
    #pragma unroll
    for (int i = 0; i < 8; i++) {
        int r = m0 + ty*8 + i;
        if (r >= M) continue;
        #pragma unroll
        for (int j = 0; j < 8; j++) {
            int c = n0 + tx*8 + j;
            if (c >= N) continue;
            float v = acc[i][j];
            if (bias) v += bias[c];
            if (reluflag) v = fmaxf(v, 0.f);
            C[(size_t)r * ldc + c] = v;
        }
    }
}

// ---------------- launch ----------------
extern "C" void kernel_launch(void* const* d_in, const int* in_sizes, int n_in,
                              void* d_out, int out_size) {
    const float* images     = (const float*)d_in[0];
    const int*   goals_txt  = (const int*)  d_in[1];
    const float* goal_imgs  = (const float*)d_in[2];
    const float* patch_w    = (const float*)d_in[3];
    const float* patch_b    = (const float*)d_in[4];
    const float* text_emb   = (const float*)d_in[5];
    const float* action_emb = (const float*)d_in[6];
    const float* wq         = (const float*)d_in[7];
    const float* wk         = (const float*)d_in[8];
    const float* wv         = (const float*)d_in[9];
    const float* proj_w     = (const float*)d_in[10];
    const float* proj_b     = (const float*)d_in[11];
    const float* ln1_s      = (const float*)d_in[12];
    const float* ln1_b      = (const float*)d_in[13];
    const float* ln2_s      = (const float*)d_in[14];
    const float* ln2_b      = (const float*)d_in[15];
    const float* ff_w1      = (const float*)d_in[16];
    const float* ff_b1      = (const float*)d_in[17];
    const float* ff_w2      = (const float*)d_in[18];
    const float* ff_b2      = (const float*)d_in[19];
    const float* hw1        = (const float*)d_in[20];
    const float* hb1        = (const float*)d_in[21];
    const float* hw2        = (const float*)d_in[22];
    const float* hb2        = (const float*)d_in[23];
    float* out = (float*)d_out;

    cudaFuncSetAttribute(tgemm,  cudaFuncAttributeMaxDynamicSharedMemorySize, TGSMEM);
    cudaFuncSetAttribute(qk_mma, cudaFuncAttributeMaxDynamicSharedMemorySize, QKSMEM);
    cudaFuncSetAttribute(pv_mma, cudaFuncAttributeMaxDynamicSharedMemorySize, PVSMEM);

    float *pPOS, *pX, *pS, *pZ;
    bf16 *pHh,*pHl,*pOh,*pOl,*pFh,*pFl,*pXPh,*pXPl,*pQh,*pQl,*pPh,*pPl,*pVth,*pVtl;
    bf16 *pWqh,*pWql,*pWph,*pWpl,*pW1h,*pW1l,*pW2h,*pW2l,*pWth,*pWtl;
    cudaGetSymbolAddress((void**)&pPOS, g_POS);
    cudaGetSymbolAddress((void**)&pX,   g_X);
    cudaGetSymbolAddress((void**)&pS,   g_S);
    cudaGetSymbolAddress((void**)&pZ,   g_Z);
    cudaGetSymbolAddress((void**)&pHh,  g_Hhi);  cudaGetSymbolAddress((void**)&pHl, g_Hlo);
    cudaGetSymbolAddress((void**)&pOh,  g_Ohi);  cudaGetSymbolAddress((void**)&pOl, g_Olo);
    cudaGetSymbolAddress((void**)&pFh,  g_Fhi);  cudaGetSymbolAddress((void**)&pFl, g_Flo);
    cudaGetSymbolAddress((void**)&pXPh, g_XPhi); cudaGetSymbolAddress((void**)&pXPl,g_XPlo);
    cudaGetSymbolAddress((void**)&pQh,  g_QKVh); cudaGetSymbolAddress((void**)&pQl, g_QKVl);
    cudaGetSymbolAddress((void**)&pPh,  g_Ph);   cudaGetSymbolAddress((void**)&pPl, g_Pl);
    cudaGetSymbolAddress((void**)&pVth, g_Vth);  cudaGetSymbolAddress((void**)&pVtl,g_Vtl);
    cudaGetSymbolAddress((void**)&pWqh, g_Wqkv_h); cudaGetSymbolAddress((void**)&pWql, g_Wqkv_l);
    cudaGetSymbolAddress((void**)&pWph, g_Wprj_h); cudaGetSymbolAddress((void**)&pWpl, g_Wprj_l);
    cudaGetSymbolAddress((void**)&pW1h, g_Wf1_h);  cudaGetSymbolAddress((void**)&pW1l, g_Wf1_l);
    cudaGetSymbolAddress((void**)&pW2h, g_Wf2_h);  cudaGetSymbolAddress((void**)&pW2l, g_Wf2_l);
    cudaGetSymbolAddress((void**)&pWth, g_Wpat_h); cudaGetSymbolAddress((void**)&pWtl, g_Wpat_l);

    // ---- prep (launch #4 = dummy QKV-shaped tgemm; ncu -s 5 -c 1 captures my 4th launch) ----
    pos_kernel    <<<CDIV(Tv*Ev, 256), 256>>>(pPOS);                                  // 1
    conv_wqkv     <<<dim3(2, 24, Lv*3*Hv), dim3(32,8)>>>(wq, wk, wv, pWqh, pWql);     // 2
    transpose_conv<<<dim3(24, 24, Lv), dim3(32,8)>>>(proj_w, pWph, pWpl, Ev, Ev);     // 3
    tgemm<<<dim3(QKVLD/128, 10), 256, TGSMEM>>>(                                       // 4 (profiling probe)
        2560, QKVLD, Ev, pXPh, pXPl, pWqh, pWql,
        nullptr, nullptr, 0, 0, pS, QKVLD, 0, 0, nullptr, nullptr);
    transpose_conv<<<dim3(96, 24, Lv), dim3(32,8)>>>(ff_w1, pW1h, pW1l, Ev, E4);      // 5
    transpose_conv<<<dim3(24, 96, Lv), dim3(32,8)>>>(ff_w2, pW2h, pW2l, E4, Ev);      // 6
    transpose_conv<<<dim3(24, 24, 1),  dim3(32,8)>>>(patch_w, pWth, pWtl, Ev, Ev);
    gather_patches<<<CDIV(MPATCH*Ev, 256), 256>>>(images, goal_imgs, pXPh, pXPl);
    embed_txt_act <<<CDIV(Bv*33*Ev, 256), 256>>>(goals_txt, text_emb, action_emb, pPOS, pX);

    // patch embed -> X rows 32..619 (+bias +POS)
    tgemm<<<dim3(Ev/128, CDIV(MPATCH,256)), 256, TGSMEM>>>(
        MPATCH, Ev, Ev, pXPh, pXPl, pWth, pWtl,
        patch_b, pPOS, Ev, 1,
        pX, Ev, 0, 0, nullptr, nullptr);

    for (int l = 0; l < Lv; l++) {
        ln_kernel<<<MTv, 256>>>(pX, pHh, pHl, ln1_s + l*Ev, ln1_b + l*Ev);

        tgemm<<<dim3(QKVLD/128, CDIV(MTv,256)), 256, TGSMEM>>>(   // QKV -> bf16 hi/lo
            MTv, QKVLD, Ev, pHh, pHl,
            pWqh + (size_t)l*QKVLD*Ev, pWql + (size_t)l*QKVLD*Ev,
            nullptr, nullptr, 0, 0,
            nullptr, 0, 0, 0, pQh, pQl);

        qk_mma        <<<dim3(TP/128, TP/128, ZH), 256, QKSMEM>>>(pQh, pQl, pS);
        softmax_kernel<<<dim3(Tv, ZH), 256>>>(pS, pPh, pPl);
        repack_v      <<<dim3(TP/32, HSv/32, ZH), dim3(32,8)>>>(pQh, pQl, pVth, pVtl);
        pv_mma        <<<dim3(TP/128, ZH), 256, PVSMEM>>>(pPh, pPl, pVth, pVtl, pOh, pOl);

        tgemm<<<dim3(Ev/128, CDIV(MTv,256)), 256, TGSMEM>>>(   // X += O @ proj + b
            MTv, Ev, Ev, pOh, pOl,
            pWph + (size_t)l*Ev*Ev, pWpl + (size_t)l*Ev*Ev,
            proj_b + l*Ev, nullptr, 0, 0,
            pX, Ev, 1, 0, nullptr, nullptr);

        ln_kernel<<<MTv, 256>>>(pX, pHh, pHl, ln2_s + l*Ev, ln2_b + l*Ev);

        tgemm<<<dim3(E4/128, CDIV(MTv,256)), 256, TGSMEM>>>(   // F = relu(h@W1+b1)
            MTv, E4, Ev, pHh, pHl,
            pW1h + (size_t)l*E4*Ev, pW1l + (size_t)l*E4*Ev,
            ff_b1 + l*E4, nullptr, 0, 0,
            nullptr, 0, 0, 1, pFh, pFl);

        tgemm<<<dim3(Ev/128, CDIV(MTv,256)), 256, TGSMEM>>>(   // X += F @ W2 + b2
            MTv, Ev, E4, pFh, pFl,
            pW2h + (size_t)l*Ev*E4, pW2l + (size_t)l*Ev*E4,
            ff_b2 + l*Ev, nullptr, 0, 0,
            pX, Ev, 1, 0, nullptr, nullptr);
    }

    // head
    sgemm128<<<dim3(Ev/128, 1), 256>>>(
        Bv, Ev, Ev, pX + (size_t)620*Ev, Tv*Ev, hw1, Ev, pZ, Ev, hb1, 1);
    sgemm128<<<dim3(1, 1), 256>>>(
        Bv, AOUTv, Ev, pZ, Ev, hw2, AOUTv, out, AOUTv, hb2, 0);

    (void)in_sizes; (void)n_in; (void)out_size;
}

// round 7
// speedup vs baseline: 1.0316x; 1.0316x over previous
#include <cuda_runtime.h>
#include <cuda_bf16.h>
#include <math.h>
#include <stdint.h>
#include <stddef.h>

// ---------------- problem constants ----------------
#define Bv      16
#define Kv      2
#define Ev      768
#define Hv      12
#define HSv     64
#define Lv      12
#define Tv      621
#define TP      640          // padded T for attention tiles
#define NPATCH  588
#define QKVLD   2304
#define E4      3072
#define AOUTv   64
#define MTv     (Bv*Tv)      // 9936
#define MPATCH  (Bv*NPATCH)  // 9408
#define ZH      (Bv*Hv)      // 192
#define SCALE_QK 0.036084391824351615f

#define CDIV(a,b) (((a)+(b)-1)/(b))
#define TGSMEM   147456      // 3 stages x 48KB
#define QKSMEM   65536
#define PVSMEM   73728       // 3 stages x 24KB

typedef __nv_bfloat16 bf16;

// ---------------- scratch ----------------
__device__ __align__(128) float g_POS[Tv*Ev];
__device__ __align__(128) float g_X  [(size_t)MTv*Ev];
__device__ __align__(128) float g_S  [(size_t)ZH*TP*TP];     // scores fp32 (also dummy-gemm dump)
__device__ __align__(128) float g_Z  [Bv*Ev];

__device__ __align__(128) bf16 g_Hhi [(size_t)MTv*Ev];
__device__ __align__(128) bf16 g_Hlo [(size_t)MTv*Ev];
__device__ __align__(128) bf16 g_Ohi [(size_t)MTv*Ev];
__device__ __align__(128) bf16 g_Olo [(size_t)MTv*Ev];
__device__ __align__(128) bf16 g_Fhi [(size_t)MTv*E4];
__device__ __align__(128) bf16 g_Flo [(size_t)MTv*E4];
__device__ __align__(128) bf16 g_XPhi[(size_t)MPATCH*Ev];
__device__ __align__(128) bf16 g_XPlo[(size_t)MPATCH*Ev];
__device__ __align__(128) bf16 g_QKVh[(size_t)MTv*QKVLD];
__device__ __align__(128) bf16 g_QKVl[(size_t)MTv*QKVLD];
__device__ __align__(128) bf16 g_Ph  [(size_t)ZH*TP*TP];     // probs hi (pad rows/cols stay 0)
__device__ __align__(128) bf16 g_Pl  [(size_t)ZH*TP*TP];
__device__ __align__(128) bf16 g_Vth [(size_t)ZH*HSv*TP];    // V transposed [z][d][s]
__device__ __align__(128) bf16 g_Vtl [(size_t)ZH*HSv*TP];

__device__ __align__(128) bf16 g_Wqkv_h[(size_t)Lv*QKVLD*Ev];
__device__ __align__(128) bf16 g_Wqkv_l[(size_t)Lv*QKVLD*Ev];
__device__ __align__(128) bf16 g_Wprj_h[(size_t)Lv*Ev*Ev];
__device__ __align__(128) bf16 g_Wprj_l[(size_t)Lv*Ev*Ev];
__device__ __align__(128) bf16 g_Wf1_h [(size_t)Lv*E4*Ev];
__device__ __align__(128) bf16 g_Wf1_l [(size_t)Lv*E4*Ev];
__device__ __align__(128) bf16 g_Wf2_h [(size_t)Lv*Ev*E4];
__device__ __align__(128) bf16 g_Wf2_l [(size_t)Lv*Ev*E4];
__device__ __align__(128) bf16 g_Wpat_h[(size_t)Ev*Ev];
__device__ __align__(128) bf16 g_Wpat_l[(size_t)Ev*Ev];

// ---------------- helpers ----------------
__device__ __forceinline__ uint32_t smem_u32(const void* p) {
    uint32_t a;
    asm("{ .reg .u64 t; cvta.to.shared.u64 t, %1; cvt.u32.u64 %0, t; }" : "=r"(a) : "l"(p));
    return a;
}
__device__ __forceinline__ void cp16(uint32_t sa, const void* ga, bool v) {
    int sz = v ? 16 : 0;
    asm volatile("cp.async.cg.shared.global [%0], [%1], 16, %2;" :: "r"(sa), "l"(ga), "r"(sz) : "memory");
}
#define CP_COMMIT() asm volatile("cp.async.commit_group;" ::: "memory")
#define CP_WAIT0()  asm volatile("cp.async.wait_group 0;" ::: "memory")
#define CP_WAIT1()  asm volatile("cp.async.wait_group 1;" ::: "memory")

#define LDSM4(r, a) \
    asm volatile("ldmatrix.sync.aligned.m8n8.x4.shared.b16 {%0,%1,%2,%3}, [%4];" \
        : "=r"((r)[0]),"=r"((r)[1]),"=r"((r)[2]),"=r"((r)[3]) : "r"(a))

__device__ __forceinline__ void mma16816(float* d, const uint32_t* a, const uint32_t* b) {
    asm volatile("mma.sync.aligned.m16n8k16.row.col.f32.bf16.bf16.f32 "
        "{%0,%1,%2,%3}, {%4,%5,%6,%7}, {%8,%9}, {%0,%1,%2,%3};"
        : "+f"(d[0]),"+f"(d[1]),"+f"(d[2]),"+f"(d[3])
        : "r"(a[0]),"r"(a[1]),"r"(a[2]),"r"(a[3]), "r"(b[0]),"r"(b[1]));
}

__device__ __forceinline__ void bf_split(float v, bf16* hi, bf16* lo) {
    bf16 h = __float2bfloat16(v);
    *hi = h;
    *lo = __float2bfloat16(v - __bfloat162float(h));
}

// ---------------- mask ----------------
__device__ __forceinline__ bool keep_fn(int t, int s) {
    bool v = (t == s);
    if (s < 32) v = !(t >= 32 && t < 228);
    if (t >= 228 && s >= 228 && s < 424) v = true;
    if (t >= 424 && s >= 424 && s < 620) v = true;
    return v;
}

// ---------------- positional embedding ----------------
__global__ void pos_kernel(float* POS) {
    int idx = blockIdx.x * 256 + threadIdx.x;
    if (idx >= Tv * Ev) return;
    int t = idx / Ev, j = idx % Ev;
    double expo = (double)(j & ~1) / (double)Ev;
    double ang  = (double)t / pow(10000.0, expo);
    POS[idx] = (float)((j & 1) ? cos(ang) : sin(ang));
}

// ---------------- transpose+convert weights ----------------
__global__ void transpose_conv(const float* __restrict__ src, bf16* __restrict__ dhi,
                               bf16* __restrict__ dlo, int R, int C) {
    __shared__ float t[32][33];
    int z = blockIdx.z;
    src += (size_t)z * R * C; dhi += (size_t)z * R * C; dlo += (size_t)z * R * C;
    int c0 = blockIdx.x * 32, r0 = blockIdx.y * 32;
    int tx = threadIdx.x, ty = threadIdx.y;
    #pragma unroll
    for (int i = 0; i < 4; i++)
        t[ty + 8*i][tx] = src[(size_t)(r0 + ty + 8*i) * C + c0 + tx];
    __syncthreads();
    #pragma unroll
    for (int i = 0; i < 4; i++) {
        float v = t[tx][ty + 8*i];
        size_t o = (size_t)(c0 + ty + 8*i) * R + r0 + tx;
        bf_split(v, dhi + o, dlo + o);
    }
}

__global__ void conv_wqkv(const float* __restrict__ wq, const float* __restrict__ wk,
                          const float* __restrict__ wv, bf16* __restrict__ dhi, bf16* __restrict__ dlo) {
    __shared__ float t[32][33];
    int z = blockIdx.z;
    int h = z % Hv, which = (z / Hv) % 3, l = z / (3 * Hv);
    const float* src = (which == 0) ? wq : (which == 1) ? wk : wv;
    src += ((size_t)l * Hv + h) * Ev * HSv;
    int d0 = blockIdx.x * 32, e0 = blockIdx.y * 32;
    int tx = threadIdx.x, ty = threadIdx.y;
    #pragma unroll
    for (int i = 0; i < 4; i++)
        t[ty + 8*i][tx] = src[(size_t)(e0 + ty + 8*i) * HSv + d0 + tx];
    __syncthreads();
    #pragma unroll
    for (int i = 0; i < 4; i++) {
        int d = d0 + ty + 8*i, e = e0 + tx;
        float v = t[tx][ty + 8*i];
        size_t o = ((size_t)l * QKVLD + which * Ev + h * HSv + d) * Ev + e;
        bf_split(v, dhi + o, dlo + o);
    }
}

// ---------------- gather patches ----------------
__global__ void gather_patches(const float* __restrict__ images, const float* __restrict__ goal_imgs,
                               bf16* __restrict__ Xhi, bf16* __restrict__ Xlo) {
    int idx = blockIdx.x * 256 + threadIdx.x;
    if (idx >= MPATCH * Ev) return;
    int f = idx % Ev;
    int r = idx / Ev;
    int p = r % NPATCH;
    int b = r / NPATCH;
    int py = f / 48, px = (f % 48) / 3, c = f % 3;
    float val;
    if (p < 196) {
        int pr = p / 14, pc = p % 14;
        int y = pr * 16 + py, x = pc * 16 + px;
        val = goal_imgs[(((size_t)b * 224 + y) * 224 + x) * 3 + c];
    } else {
        int q = p - 196;
        int k = q / 196, pp = q % 196;
        int pr = pp / 14, pc = pp % 14;
        int y = pr * 16 + py, x = pc * 16 + px;
        val = images[((((size_t)b * Kv + k) * 224 + y) * 224 + x) * 3 + c];
    }
    bf_split(val, Xhi + idx, Xlo + idx);
}

// ---------------- text + action embed (+POS) ----------------
__global__ void embed_txt_act(const int* __restrict__ goals_txt, const float* __restrict__ text_emb,
                              const float* __restrict__ action_emb, const float* __restrict__ POS,
                              float* __restrict__ X) {
    int idx = blockIdx.x * 256 + threadIdx.x;
    if (idx >= Bv * 33 * Ev) return;
    int e  = idx % Ev;
    int r  = idx / Ev;
    int tt = r % 33;
    int b  = r / 33;
    int t  = (tt < 32) ? tt : 620;
    float v = (tt < 32) ? text_emb[(size_t)goals_txt[b * 32 + tt] * Ev + e] : action_emb[e];
    X[((size_t)b * Tv + t) * Ev + e] = v + POS[(size_t)t * Ev + e];
}

// ---------------- layernorm -> hi/lo bf16 ----------------
__global__ void ln_kernel(const float* __restrict__ X, bf16* __restrict__ Ohi, bf16* __restrict__ Olo,
                          const float* __restrict__ sc, const float* __restrict__ bi) {
    int row = blockIdx.x;
    const float* x = X + (size_t)row * Ev;
    __shared__ float r1[256], r2[256];
    int tid = threadIdx.x;
    float s = 0.f, ss = 0.f;
    for (int e = tid; e < Ev; e += 256) { float v = x[e]; s += v; ss += v * v; }
    r1[tid] = s; r2[tid] = ss;
    __syncthreads();
    for (int off = 128; off; off >>= 1) {
        if (tid < off) { r1[tid] += r1[tid + off]; r2[tid] += r2[tid + off]; }
        __syncthreads();
    }
    float m   = r1[0] * (1.f / Ev);
    float var = r2[0] * (1.f / Ev) - m * m;
    float inv = 1.f / sqrtf(var + 1e-5f);
    for (int e = tid; e < Ev; e += 256) {
        float v = (x[e] - m) * inv * sc[e] + bi[e];
        size_t o = (size_t)row * Ev + e;
        bf_split(v, Ohi + o, Olo + o);
    }
}

// =====================================================================
// bf16x3 linear GEMM (mma.sync), 256x128 tile, warp tile 64x64, Kc=32,
// 3-stage cp.async pipeline (wait_group 1 -> loads run 2 chunks ahead)
// stage: Ahi 16K @0, Alo 16K @16K, Bhi 8K @32K, Blo 8K @40K  (48K/stage)
// =====================================================================
__global__ void __launch_bounds__(256, 1)
tgemm(int M, int N, int K,
      const bf16* __restrict__ Ahi, const bf16* __restrict__ Alo,
      const bf16* __restrict__ Bhi, const bf16* __restrict__ Blo,
      const float* __restrict__ bias,
      const float* __restrict__ rowmat, int ldrm, int rmode,
      float* outF, int ldo, int accf, int reluf,
      bf16* outHi, bf16* outLo)
{
    extern __shared__ char sm[];
    uint32_t sbase = smem_u32(sm);
    int tid = threadIdx.x, lane = tid & 31, wid = tid >> 5;
    int m0 = blockIdx.y * 256, n0 = blockIdx.x * 128;
    int wm = wid & 3, wn = wid >> 2;   // warp rows: wm*64, warp cols: wn*64

    float acc[4][8][4];
    #pragma unroll
    for (int i = 0; i < 4; i++)
        #pragma unroll
        for (int j = 0; j < 8; j++)
            #pragma unroll
            for (int q = 0; q < 4; q++) acc[i][j][q] = 0.f;

    int nc = K >> 5;

    // always commits a group; loads only when active
    auto ld_st = [&](int c, int st, bool active) {
        if (active) {
            uint32_t sb = sbase + st * 49152;
            int k0 = c * 32;
            #pragma unroll
            for (int i = 0; i < 4; i++) {              // A: 256 rows x 4 segs
                int u = i * 256 + tid;
                int row = u >> 2, seg = u & 3;
                uint32_t off = (uint32_t)(row * 64 + ((seg ^ ((row >> 1) & 3)) << 4));
                bool av = (m0 + row) < M;
                size_t ao = (size_t)(av ? (m0 + row) : 0) * K + k0 + seg * 8;
                cp16(sb + off,         Ahi + ao, av);
                cp16(sb + 16384 + off, Alo + ao, av);
            }
            #pragma unroll
            for (int i = 0; i < 2; i++) {              // B: 128 rows x 4 segs
                int u = i * 256 + tid;
                int row = u >> 2, seg = u & 3;
                uint32_t off = (uint32_t)(row * 64 + ((seg ^ ((row >> 1) & 3)) << 4));
                size_t bo = (size_t)(n0 + row) * K + k0 + seg * 8;
                cp16(sb + 32768 + off, Bhi + bo, true);
                cp16(sb + 40960 + off, Blo + bo, true);
            }
        }
        CP_COMMIT();
    };

    ld_st(0, 0, true);
    ld_st(1, 1, 1 < nc);

    for (int c = 0; c < nc; c++) {
        CP_WAIT1();
        __syncthreads();

        int st = c % 3;
        uint32_t sA_hi = sbase + st * 49152;
        uint32_t sA_lo = sA_hi + 16384;
        uint32_t sB_hi = sA_hi + 32768;
        uint32_t sB_lo = sA_hi + 40960;

        #pragma unroll
        for (int ks = 0; ks < 2; ks++) {
            uint32_t afh[4][4], afl[4][4];
            #pragma unroll
            for (int mt = 0; mt < 4; mt++) {
                int matA = lane >> 3;
                int arow = wm * 64 + mt * 16 + (lane & 7) + (matA & 1) * 8;
                int aseg = ks * 2 + (matA >> 1);
                uint32_t off = (uint32_t)(arow * 64 + ((aseg ^ ((arow >> 1) & 3)) << 4));
                LDSM4(afh[mt], sA_hi + off);
                LDSM4(afl[mt], sA_lo + off);
            }
            #pragma unroll
            for (int np = 0; np < 4; np++) {
                uint32_t bfh[4], bfl[4];
                int matB = lane >> 3;
                int brow = wn * 64 + np * 16 + ((matB >> 1) << 3) + (lane & 7);
                int bseg = ks * 2 + (matB & 1);
                uint32_t boff = (uint32_t)(brow * 64 + ((bseg ^ ((brow >> 1) & 3)) << 4));
                LDSM4(bfh, sB_hi + boff);
                LDSM4(bfl, sB_lo + boff);
                // term-major: 8 independent MMAs per group
                #pragma unroll
                for (int t = 0; t < 2; t++)
                    #pragma unroll
                    for (int mt = 0; mt < 4; mt++)
                        mma16816(acc[mt][np * 2 + t], afh[mt], bfh + 2 * t);
                #pragma unroll
                for (int t = 0; t < 2; t++)
                    #pragma unroll
                    for (int mt = 0; mt < 4; mt++)
                        mma16816(acc[mt][np * 2 + t], afh[mt], bfl + 2 * t);
                #pragma unroll
                for (int t = 0; t < 2; t++)
                    #pragma unroll
                    for (int mt = 0; mt < 4; mt++)
                        mma16816(acc[mt][np * 2 + t], afl[mt], bfh + 2 * t);
            }
        }
        ld_st(c + 2, (c + 2) % 3, c + 2 < nc);
    }

    int r_l = lane >> 2, c_l = (lane & 3) * 2;
    #pragma unroll
    for (int mt = 0; mt < 4; mt++) {
        #pragma unroll
        for (int h = 0; h < 2; h++) {
            int rr = m0 + wm * 64 + mt * 16 + h * 8 + r_l;
            if (rr >= M) continue;
            int orow = rr, prow = rr;
            if (rmode) {
                int b = rr / NPATCH, p = rr - b * NPATCH;
                orow = b * Tv + 32 + p;
                prow = 32 + p;
            }
            #pragma unroll
            for (int j = 0; j < 8; j++) {
                int col = n0 + wn * 64 + j * 8 + c_l;
                float v0 = acc[mt][j][2 * h];
                float v1 = acc[mt][j][2 * h + 1];
                if (bias)   { v0 += bias[col]; v1 += bias[col + 1]; }
                if (rowmat) { const float* rp = rowmat + (size_t)prow * ldrm + col; v0 += rp[0]; v1 += rp[1]; }
                if (accf)   { const float* op = outF + (size_t)orow * ldo + col;   v0 += op[0]; v1 += op[1]; }
                if (reluf)  { v0 = fmaxf(v0, 0.f); v1 = fmaxf(v1, 0.f); }
                if (outF)   *(float2*)(outF + (size_t)orow * ldo + col) = make_float2(v0, v1);
                if (outHi) {
                    size_t o = (size_t)rr * N + col;
                    bf_split(v0, outHi + o, outLo + o);
                    bf_split(v1, outHi + o + 1, outLo + o + 1);
                }
            }
        }
    }
}

// =====================================================================
// qk_mma: S[z][t][s] = (Q K^T)*scale ; 128x128 tile, K=64 one-shot
// =====================================================================
__global__ void __launch_bounds__(256, 2)
qk_mma(const bf16* __restrict__ Qh, const bf16* __restrict__ Ql, float* __restrict__ S)
{
    extern __shared__ char sm[];
    uint32_t sbase = smem_u32(sm);     // +0 Qhi, +16K Qlo, +32K Khi, +48K Klo (128 rows x 128B)
    int tid = threadIdx.x, lane = tid & 31, wid = tid >> 5;
    int z = blockIdx.z, b = z / Hv, h = z % Hv;
    int t0 = blockIdx.y * 128, s0 = blockIdx.x * 128;

    #pragma unroll
    for (int i = 0; i < 4; i++) {
        int u = i * 256 + tid;
        int row = u >> 3, seg = u & 7;
        uint32_t off = (uint32_t)(row * 128 + ((seg ^ (row & 7)) << 4));
        bool qv = (t0 + row) < Tv;
        bool kv = (s0 + row) < Tv;
        size_t qo = (size_t)(b * Tv + (qv ? t0 + row : 0)) * QKVLD + h * HSv + seg * 8;
        size_t ko = (size_t)(b * Tv + (kv ? s0 + row : 0)) * QKVLD + Ev + h * HSv + seg * 8;
        cp16(sbase + off,         Qh + qo, qv);
        cp16(sbase + 16384 + off, Ql + qo, qv);
        cp16(sbase + 32768 + off, Qh + ko, kv);
        cp16(sbase + 49152 + off, Ql + ko, kv);
    }
    CP_COMMIT();
    CP_WAIT0();
    __syncthreads();

    int wm = wid & 3, wn = wid >> 2;
    float acc[2][8][4];
    #pragma unroll
    for (int i = 0; i < 2; i++)
        #pragma unroll
        for (int j = 0; j < 8; j++)
            #pragma unroll
            for (int q = 0; q < 4; q++) acc[i][j][q] = 0.f;

    #pragma unroll
    for (int ks = 0; ks < 4; ks++) {
        uint32_t afh[2][4], afl[2][4];
        #pragma unroll
        for (int mt = 0; mt < 2; mt++) {
            int matA = lane >> 3;
            int arow = wm * 32 + mt * 16 + (lane & 7) + (matA & 1) * 8;
            int aseg = ks * 2 + (matA >> 1);
            uint32_t off = (uint32_t)(arow * 128 + ((aseg ^ (arow & 7)) << 4));
            LDSM4(afh[mt], sbase + off);
            LDSM4(afl[mt], sbase + 16384 + off);
        }
        #pragma unroll
        for (int np = 0; np < 4; np++) {
            uint32_t bfh[4], bfl[4];
            int matB = lane >> 3;
            int brow = wn * 64 + np * 16 + ((matB >> 1) << 3) + (lane & 7);
            int bseg = ks * 2 + (matB & 1);
            uint32_t boff = (uint32_t)(brow * 128 + ((bseg ^ (brow & 7)) << 4));
            LDSM4(bfh, sbase + 32768 + boff);
            LDSM4(bfl, sbase + 49152 + boff);
            #pragma unroll
            for (int t = 0; t < 2; t++)
                #pragma unroll
                for (int mt = 0; mt < 2; mt++)
                    mma16816(acc[mt][np * 2 + t], afh[mt], bfh + 2 * t);
            #pragma unroll
            for (int t = 0; t < 2; t++)
                #pragma unroll
                for (int mt = 0; mt < 2; mt++)
                    mma16816(acc[mt][np * 2 + t], afh[mt], bfl + 2 * t);
            #pragma unroll
            for (int t = 0; t < 2; t++)
                #pragma unroll
                for (int mt = 0; mt < 2; mt++)
                    mma16816(acc[mt][np * 2 + t], afl[mt], bfh + 2 * t);
        }
    }

    int r_l = lane >> 2, c_l = (lane & 3) * 2;
    #pragma unroll
    for (int mt = 0; mt < 2; mt++)
        #pragma unroll
        for (int h2 = 0; h2 < 2; h2++) {
            int rr = t0 + wm * 32 + mt * 16 + h2 * 8 + r_l;
            #pragma unroll
            for (int j = 0; j < 8; j++) {
                int col = s0 + wn * 64 + j * 8 + c_l;
                float2 v = make_float2(acc[mt][j][2 * h2] * SCALE_QK,
                                       acc[mt][j][2 * h2 + 1] * SCALE_QK);
                *(float2*)(S + ((size_t)z * TP + rr) * TP + col) = v;
            }
        }
}

// ---------------- masked softmax: S fp32 -> P hi/lo bf16 (cols padded 0) ----------------
__global__ void softmax_kernel(const float* __restrict__ S,
                               bf16* __restrict__ Ph, bf16* __restrict__ Pl)
{
    int t = blockIdx.x, z = blockIdx.y;
    const float* row = S + ((size_t)z * TP + t) * TP;
    bf16* ph = Ph + ((size_t)z * TP + t) * TP;
    bf16* pl = Pl + ((size_t)z * TP + t) * TP;
    __shared__ float red[256];
    int tid = threadIdx.x;
    float mx = -3.0e38f;
    #pragma unroll
    for (int i = 0; i < 3; i++) {
        int s = tid + i * 256;
        if (s < TP && keep_fn(t, s)) mx = fmaxf(mx, row[s]);
    }
    red[tid] = mx; __syncthreads();
    for (int off = 128; off; off >>= 1) {
        if (tid < off) red[tid] = fmaxf(red[tid], red[tid + off]);
        __syncthreads();
    }
    mx = red[0]; __syncthreads();
    float pv[3]; float sum = 0.f;
    #pragma unroll
    for (int i = 0; i < 3; i++) {
        int s = tid + i * 256;
        float p = 0.f;
        if (s < TP && keep_fn(t, s)) p = expf(row[s] - mx);
        pv[i] = p; sum += p;
    }
    red[tid] = sum; __syncthreads();
    for (int off = 128; off; off >>= 1) {
        if (tid < off) red[tid] += red[tid + off];
        __syncthreads();
    }
    float inv = 1.f / red[0];
    #pragma unroll
    for (int i = 0; i < 3; i++) {
        int s = tid + i * 256;
        if (s < TP) bf_split(pv[i] * inv, ph + s, pl + s);
    }
}

// ---------------- V repack: QKV v-part -> Vt[z][d][s] hi/lo (s padded 0) ----------------
__global__ void repack_v(const bf16* __restrict__ Qh, const bf16* __restrict__ Ql,
                         bf16* __restrict__ Vth, bf16* __restrict__ Vtl)
{
    __shared__ bf16 th[32][33], tl[32][33];
    int z = blockIdx.z, b = z / Hv, h = z % Hv;
    int s0 = blockIdx.x * 32, d0 = blockIdx.y * 32;
    int tx = threadIdx.x, ty = threadIdx.y;
    #pragma unroll
    for (int i = 0; i < 4; i++) {
        int s = s0 + ty + 8 * i;
        bf16 vh = __float2bfloat16(0.f), vl = vh;
        if (s < Tv) {
            size_t o = (size_t)(b * Tv + s) * QKVLD + 2 * Ev + h * HSv + d0 + tx;
            vh = Qh[o]; vl = Ql[o];
        }
        th[ty + 8 * i][tx] = vh;
        tl[ty + 8 * i][tx] = vl;
    }
    __syncthreads();
    #pragma unroll
    for (int i = 0; i < 4; i++) {
        size_t o = ((size_t)z * HSv + d0 + ty + 8 * i) * TP + s0 + tx;
        Vth[o] = th[tx][ty + 8 * i];
        Vtl[o] = tl[tx][ty + 8 * i];
    }
}

// =====================================================================
// pv_mma: O[z][t][d] = P @ V^T-layout ; tile 128x64, Kc=32, 20 chunks,
// 3-stage cp.async pipeline
// =====================================================================
__global__ void __launch_bounds__(256, 2)
pv_mma(const bf16* __restrict__ Ph, const bf16* __restrict__ Pl,
       const bf16* __restrict__ Vth, const bf16* __restrict__ Vtl,
       bf16* __restrict__ Ohi, bf16* __restrict__ Olo)
{
    extern __shared__ char sm[];
    uint32_t sbase = smem_u32(sm);
    // stage layout (24KB): +0 P_hi 8K, +8K P_lo 8K, +16K V_hi 4K, +20K V_lo 4K
    int tid = threadIdx.x, lane = tid & 31, wid = tid >> 5;
    int z = blockIdx.y, b = z / Hv, h = z % Hv;
    int t0 = blockIdx.x * 128;
    int wm = wid & 3, wn = wid >> 2;

    float acc[2][4][4];
    #pragma unroll
    for (int i = 0; i < 2; i++)
        #pragma unroll
        for (int j = 0; j < 4; j++)
            #pragma unroll
            for (int q = 0; q < 4; q++) acc[i][j][q] = 0.f;

    const int nc = TP / 32;

    auto ld_st = [&](int c, int st, bool active) {
        if (active) {
            uint32_t sb = sbase + st * 24576;
            int k0 = c * 32;
            {
                int u = tid;
                int row = u >> 1, seg0 = (u & 1) * 2;
                #pragma unroll
                for (int q = 0; q < 2; q++) {
                    int seg = seg0 + q;
                    uint32_t off = (uint32_t)(row * 64 + ((seg ^ ((row >> 1) & 3)) << 4));
                    size_t po = ((size_t)z * TP + t0 + row) * TP + k0 + seg * 8;
                    cp16(sb + off,        Ph + po, true);
                    cp16(sb + 8192 + off, Pl + po, true);
                }
            }
            {
                int row = tid >> 2, seg = tid & 3;
                uint32_t off = (uint32_t)(row * 64 + ((seg ^ ((row >> 1) & 3)) << 4));
                size_t vo = ((size_t)z * HSv + row) * TP + k0 + seg * 8;
                cp16(sb + 16384 + off, Vth + vo, true);
                cp16(sb + 20480 + off, Vtl + vo, true);
            }
        }
        CP_COMMIT();
    };

    ld_st(0, 0, true);
    ld_st(1, 1, true);

    for (int c = 0; c < nc; c++) {
        CP_WAIT1();
        __syncthreads();

        int st = c % 3;
        uint32_t sP_hi = sbase + st * 24576;
        uint32_t sP_lo = sP_hi + 8192;
        uint32_t sV_hi = sP_hi + 16384;
        uint32_t sV_lo = sP_hi + 20480;

        #pragma unroll
        for (int ks = 0; ks < 2; ks++) {
            uint32_t afh[2][4], afl[2][4];
            #pragma unroll
            for (int mt = 0; mt < 2; mt++) {
                int matA = lane >> 3;
                int arow = wm * 32 + mt * 16 + (lane & 7) + (matA & 1) * 8;
                int aseg = ks * 2 + (matA >> 1);
                uint32_t off = (uint32_t)(arow * 64 + ((aseg ^ ((arow >> 1) & 3)) << 4));
                LDSM4(afh[mt], sP_hi + off);
                LDSM4(afl[mt], sP_lo + off);
            }
            #pragma unroll
            for (int np = 0; np < 2; np++) {
                uint32_t bfh[4], bfl[4];
                int matB = lane >> 3;
                int brow = wn * 32 + np * 16 + ((matB >> 1) << 3) + (lane & 7);
                int bseg = ks * 2 + (matB & 1);
                uint32_t boff = (uint32_t)(brow * 64 + ((bseg ^ ((brow >> 1) & 3)) << 4));
                LDSM4(bfh, sV_hi + boff);
                LDSM4(bfl, sV_lo + boff);
                #pragma unroll
                for (int t = 0; t < 2; t++)
                    #pragma unroll
                    for (int mt = 0; mt < 2; mt++)
                        mma16816(acc[mt][np * 2 + t], afh[mt], bfh + 2 * t);
                #pragma unroll
                for (int t = 0; t < 2; t++)
                    #pragma unroll
                    for (int mt = 0; mt < 2; mt++)
                        mma16816(acc[mt][np * 2 + t], afh[mt], bfl + 2 * t);
                #pragma unroll
                for (int t = 0; t < 2; t++)
                    #pragma unroll
                    for (int mt = 0; mt < 2; mt++)
                        mma16816(acc[mt][np * 2 + t], afl[mt], bfh + 2 * t);
            }
        }
        ld_st(c + 2, (c + 2) % 3, c + 2 < nc);
    }

    int r_l = lane >> 2, c_l = (lane & 3) * 2;
    #pragma unroll
    for (int mt = 0; mt < 2; mt++)
        #pragma unroll
        for (int h2 = 0; h2 < 2; h2++) {
            int rr = t0 + wm * 32 + mt * 16 + h2 * 8 + r_l;
            if (rr >= Tv) continue;
            #pragma unroll
            for (int j = 0; j < 4; j++) {
                int col = wn * 32 + j * 8 + c_l;
                size_t o = ((size_t)(b * Tv + rr)) * Ev + h * HSv + col;
                bf_split(acc[mt][j][2 * h2],     Ohi + o,     Olo + o);
                bf_split(acc[mt][j][2 * h2 + 1], Ohi + o + 1, Olo + o + 1);
            }
        }
}

// ---------------- fp32 GEMM (head only) ----------------
__global__ void __launch_bounds__(256, 2)
sgemm128(int M, int N, int K,
         const float* __restrict__ A, int lda,
         const float* __restrict__ B, int ldb,
         float* __restrict__ C, int ldc,
         const float* __restrict__ bias, int reluflag)
{
    __shared__ __align__(16) float As[8][128];
    __shared__ __align__(16) float Bs[8][128];
    int n0 = blockIdx.x * 128, m0 = blockIdx.y * 128;
    int tid = threadIdx.x;
    int tx = tid & 15, ty = tid >> 4;
    int arow = tid >> 1,  akk  = (tid & 1) * 4;
    int bkk  = tid >> 5,  bcol = (tid & 31) * 4;
    bool aval = (m0 + arow) < M;
    bool bval = (n0 + bcol) < N;
    const float* Aptr = A + (size_t)(m0 + arow) * lda + akk;
    const float* Bptr = B + (size_t)bkk * ldb + n0 + bcol;
    float acc[8][8];
    #pragma unroll
    for (int i = 0; i < 8; i++)
        #pragma unroll
        for (int j = 0; j < 8; j++) acc[i][j] = 0.f;
    for (int k0 = 0; k0 < K; k0 += 8) {
        float4 av = make_float4(0.f,0.f,0.f,0.f), bv = make_float4(0.f,0.f,0.f,0.f);
        if (aval) av = *(const float4*)(Aptr + k0);
        if (bval) bv = *(const float4*)(Bptr + (size_t)k0 * ldb);
        __syncthreads();
        As[akk+0][arow] = av.x; As[akk+1][arow] = av.y;
        As[akk+2][arow] = av.z; As[akk+3][arow] = av.w;
        *(float4*)&Bs[bkk][bcol] = bv;
        __syncthreads();
        #pragma unroll
        for (int kk = 0; kk < 8; kk++) {
            float a[8], b2[8];
            *(float4*)(a)    = *(const float4*)&As[kk][ty*8];
            *(float4*)(a+4)  = *(const float4*)&As[kk][ty*8+4];
            *(float4*)(b2)   = *(const float4*)&Bs[kk][tx*8];
            *(float4*)(b2+4) = *(const float4*)&Bs[kk][tx*8+4];
            #pragma unroll
            for (int i = 0; i < 8; i++)
                #pragma unroll
                for (int j = 0; j < 8; j++)
                    acc[i][j] += a[i] * b2[j];
        }
    }
    #pragma unroll
    for (int i = 0; i < 8; i++) {
        int r = m0 + ty*8 + i;
        if (r >= M) continue;
        #pragma unroll
        for (int j = 0; j < 8; j++) {
            int c = n0 + tx*8 + j;
            if (c >= N) continue;
            float v = acc[i][j];
            if (bias) v += bias[c];
            if (reluflag) v = fmaxf(v, 0.f);
            C[(size_t)r * ldc + c] = v;
        }
    }
}

// ---------------- launch ----------------
extern "C" void kernel_launch(void* const* d_in, const int* in_sizes, int n_in,
                              void* d_out, int out_size) {
    const float* images     = (const float*)d_in[0];
    const int*   goals_txt  = (const int*)  d_in[1];
    const float* goal_imgs  = (const float*)d_in[2];
    const float* patch_w    = (const float*)d_in[3];
    const float* patch_b    = (const float*)d_in[4];
    const float* text_emb   = (const float*)d_in[5];
    const float* action_emb = (const float*)d_in[6];
    const float* wq         = (const float*)d_in[7];
    const float* wk         = (const float*)d_in[8];
    const float* wv         = (const float*)d_in[9];
    const float* proj_w     = (const float*)d_in[10];
    const float* proj_b     = (const float*)d_in[11];
    const float* ln1_s      = (const float*)d_in[12];
    const float* ln1_b      = (const float*)d_in[13];
    const float* ln2_s      = (const float*)d_in[14];
    const float* ln2_b      = (const float*)d_in[15];
    const float* ff_w1      = (const float*)d_in[16];
    const float* ff_b1      = (const float*)d_in[17];
    const float* ff_w2      = (const float*)d_in[18];
    const float* ff_b2      = (const float*)d_in[19];
    const float* hw1        = (const float*)d_in[20];
    const float* hb1        = (const float*)d_in[21];
    const float* hw2        = (const float*)d_in[22];
    const float* hb2        = (const float*)d_in[23];
    float* out = (float*)d_out;

    cudaFuncSetAttribute(tgemm,  cudaFuncAttributeMaxDynamicSharedMemorySize, TGSMEM);
    cudaFuncSetAttribute(qk_mma, cudaFuncAttributeMaxDynamicSharedMemorySize, QKSMEM);
    cudaFuncSetAttribute(pv_mma, cudaFuncAttributeMaxDynamicSharedMemorySize, PVSMEM);

    float *pPOS, *pX, *pS, *pZ;
    bf16 *pHh,*pHl,*pOh,*pOl,*pFh,*pFl,*pXPh,*pXPl,*pQh,*pQl,*pPh,*pPl,*pVth,*pVtl;
    bf16 *pWqh,*pWql,*pWph,*pWpl,*pW1h,*pW1l,*pW2h,*pW2l,*pWth,*pWtl;
    cudaGetSymbolAddress((void**)&pPOS, g_POS);
    cudaGetSymbolAddress((void**)&pX,   g_X);
    cudaGetSymbolAddress((void**)&pS,   g_S);
    cudaGetSymbolAddress((void**)&pZ,   g_Z);
    cudaGetSymbolAddress((void**)&pHh,  g_Hhi);  cudaGetSymbolAddress((void**)&pHl, g_Hlo);
    cudaGetSymbolAddress((void**)&pOh,  g_Ohi);  cudaGetSymbolAddress((void**)&pOl, g_Olo);
    cudaGetSymbolAddress((void**)&pFh,  g_Fhi);  cudaGetSymbolAddress((void**)&pFl, g_Flo);
    cudaGetSymbolAddress((void**)&pXPh, g_XPhi); cudaGetSymbolAddress((void**)&pXPl,g_XPlo);
    cudaGetSymbolAddress((void**)&pQh,  g_QKVh); cudaGetSymbolAddress((void**)&pQl, g_QKVl);
    cudaGetSymbolAddress((void**)&pPh,  g_Ph);   cudaGetSymbolAddress((void**)&pPl, g_Pl);
    cudaGetSymbolAddress((void**)&pVth, g_Vth);  cudaGetSymbolAddress((void**)&pVtl,g_Vtl);
    cudaGetSymbolAddress((void**)&pWqh, g_Wqkv_h); cudaGetSymbolAddress((void**)&pWql, g_Wqkv_l);
    cudaGetSymbolAddress((void**)&pWph, g_Wprj_h); cudaGetSymbolAddress((void**)&pWpl, g_Wprj_l);
    cudaGetSymbolAddress((void**)&pW1h, g_Wf1_h);  cudaGetSymbolAddress((void**)&pW1l, g_Wf1_l);
    cudaGetSymbolAddress((void**)&pW2h, g_Wf2_h);  cudaGetSymbolAddress((void**)&pW2l, g_Wf2_l);
    cudaGetSymbolAddress((void**)&pWth, g_Wpat_h); cudaGetSymbolAddress((void**)&pWtl, g_Wpat_l);

    // ---- prep (launch #4 = dummy QKV-shaped tgemm; ncu -s 5 -c 1 captures my 4th launch) ----
    pos_kernel    <<<CDIV(Tv*Ev, 256), 256>>>(pPOS);                                  // 1
    conv_wqkv     <<<dim3(2, 24, Lv*3*Hv), dim3(32,8)>>>(wq, wk, wv, pWqh, pWql);     // 2
    transpose_conv<<<dim3(24, 24, Lv), dim3(32,8)>>>(proj_w, pWph, pWpl, Ev, Ev);     // 3
    tgemm<<<dim3(QKVLD/128, 10), 256, TGSMEM>>>(                                       // 4 (profiling probe)
        2560, QKVLD, Ev, pXPh, pXPl, pWqh, pWql,
        nullptr, nullptr, 0, 0, pS, QKVLD, 0, 0, nullptr, nullptr);
    transpose_conv<<<dim3(96, 24, Lv), dim3(32,8)>>>(ff_w1, pW1h, pW1l, Ev, E4);      // 5
    transpose_conv<<<dim3(24, 96, Lv), dim3(32,8)>>>(ff_w2, pW2h, pW2l, E4, Ev);      // 6
    transpose_conv<<<dim3(24, 24, 1),  dim3(32,8)>>>(patch_w, pWth, pWtl, Ev, Ev);
    gather_patches<<<CDIV(MPATCH*Ev, 256), 256>>>(images, goal_imgs, pXPh, pXPl);
    embed_txt_act <<<CDIV(Bv*33*Ev, 256), 256>>>(goals_txt, text_emb, action_emb, pPOS, pX);

    // patch embed -> X rows 32..619 (+bias +POS)
    tgemm<<<dim3(Ev/128, CDIV(MPATCH,256)), 256, TGSMEM>>>(
        MPATCH, Ev, Ev, pXPh, pXPl, pWth, pWtl,
        patch_b, pPOS, Ev, 1,
        pX, Ev, 0, 0, nullptr, nullptr);

    for (int l = 0; l < Lv; l++) {
        ln_kernel<<<MTv, 256>>>(pX, pHh, pHl, ln1_s + l*Ev, ln1_b + l*Ev);

        tgemm<<<dim3(QKVLD/128, CDIV(MTv,256)), 256, TGSMEM>>>(   // QKV -> bf16 hi/lo
            MTv, QKVLD, Ev, pHh, pHl,
            pWqh + (size_t)l*QKVLD*Ev, pWql + (size_t)l*QKVLD*Ev,
            nullptr, nullptr, 0, 0,
            nullptr, 0, 0, 0, pQh, pQl);

        qk_mma        <<<dim3(TP/128, TP/128, ZH), 256, QKSMEM>>>(pQh, pQl, pS);
        softmax_kernel<<<dim3(Tv, ZH), 256>>>(pS, pPh, pPl);
        repack_v      <<<dim3(TP/32, HSv/32, ZH), dim3(32,8)>>>(pQh, pQl, pVth, pVtl);
        pv_mma        <<<dim3(TP/128, ZH), 256, PVSMEM>>>(pPh, pPl, pVth, pVtl, pOh, pOl);

        tgemm<<<dim3(Ev/128, CDIV(MTv,256)), 256, TGSMEM>>>(   // X += O @ proj + b
            MTv, Ev, Ev, pOh, pOl,
            pWph + (size_t)l*Ev*Ev, pWpl + (size_t)l*Ev*Ev,
            proj_b + l*Ev, nullptr, 0, 0,
            pX, Ev, 1, 0, nullptr, nullptr);

        ln_kernel<<<MTv, 256>>>(pX, pHh, pHl, ln2_s + l*Ev, ln2_b + l*Ev);

        tgemm<<<dim3(E4/128, CDIV(MTv,256)), 256, TGSMEM>>>(   // F = relu(h@W1+b1)
            MTv, E4, Ev, pHh, pHl,
            pW1h + (size_t)l*E4*Ev, pW1l + (size_t)l*E4*Ev,
            ff_b1 + l*E4, nullptr, 0, 0,
            nullptr, 0, 0, 1, pFh, pFl);

        tgemm<<<dim3(Ev/128, CDIV(MTv,256)), 256, TGSMEM>>>(   // X += F @ W2 + b2
            MTv, Ev, E4, pFh, pFl,
            pW2h + (size_t)l*Ev*E4, pW2l + (size_t)l*Ev*E4,
            ff_b2 + l*Ev, nullptr, 0, 0,
            pX, Ev, 1, 0, nullptr, nullptr);
    }

    // head
    sgemm128<<<dim3(Ev/128, 1), 256>>>(
        Bv, Ev, Ev, pX + (size_t)620*Ev, Tv*Ev, hw1, Ev, pZ, Ev, hb1, 1);
    sgemm128<<<dim3(1, 1), 256>>>(
        Bv, AOUTv, Ev, pZ, Ev, hw2, AOUTv, out, AOUTv, hb2, 0);

    (void)in_sizes; (void)n_in; (void)out_size;
}

// round 8
// speedup vs baseline: 1.0390x; 1.0071x over previous
#include <cuda_runtime.h>
#include <cuda_bf16.h>
#include <math.h>
#include <stdint.h>
#include <stddef.h>

// ---------------- problem constants ----------------
#define Bv      16
#define Kv      2
#define Ev      768
#define Hv      12
#define HSv     64
#define Lv      12
#define Tv      621
#define TP      640          // padded T for attention tiles
#define NPATCH  588
#define QKVLD   2304
#define E4      3072
#define AOUTv   64
#define MTv     (Bv*Tv)      // 9936
#define MPATCH  (Bv*NPATCH)  // 9408
#define ZH      (Bv*Hv)      // 192
#define SCALE_QK 0.036084391824351615f

#define CDIV(a,b) (((a)+(b)-1)/(b))
#define TGSMEM   147456      // 3 stages x 48KB
#define QKSMEM   65536
#define PVSMEM   73728       // 3 stages x 24KB

typedef __nv_bfloat16 bf16;

// ---------------- scratch ----------------
__device__ __align__(128) float g_POS[Tv*Ev];
__device__ __align__(128) float g_X  [(size_t)MTv*Ev];
__device__ __align__(128) float g_S  [(size_t)ZH*TP*TP];     // scores fp32 (also dummy-gemm dump)
__device__ __align__(128) float g_Z  [Bv*Ev];

__device__ __align__(128) bf16 g_Hhi [(size_t)MTv*Ev];
__device__ __align__(128) bf16 g_Hlo [(size_t)MTv*Ev];
__device__ __align__(128) bf16 g_Ohi [(size_t)MTv*Ev];
__device__ __align__(128) bf16 g_Olo [(size_t)MTv*Ev];
__device__ __align__(128) bf16 g_Fhi [(size_t)MTv*E4];
__device__ __align__(128) bf16 g_Flo [(size_t)MTv*E4];
__device__ __align__(128) bf16 g_XPhi[(size_t)MPATCH*Ev];
__device__ __align__(128) bf16 g_XPlo[(size_t)MPATCH*Ev];
__device__ __align__(128) bf16 g_QKVh[(size_t)MTv*QKVLD];
__device__ __align__(128) bf16 g_QKVl[(size_t)MTv*QKVLD];
__device__ __align__(128) bf16 g_Ph  [(size_t)ZH*TP*TP];     // probs hi (pad rows/cols stay 0)
__device__ __align__(128) bf16 g_Pl  [(size_t)ZH*TP*TP];
__device__ __align__(128) bf16 g_Vth [(size_t)ZH*HSv*TP];    // V transposed [z][d][s]
__device__ __align__(128) bf16 g_Vtl [(size_t)ZH*HSv*TP];

__device__ __align__(128) bf16 g_Wqkv_h[(size_t)Lv*QKVLD*Ev];
__device__ __align__(128) bf16 g_Wqkv_l[(size_t)Lv*QKVLD*Ev];
__device__ __align__(128) bf16 g_Wprj_h[(size_t)Lv*Ev*Ev];
__device__ __align__(128) bf16 g_Wprj_l[(size_t)Lv*Ev*Ev];
__device__ __align__(128) bf16 g_Wf1_h [(size_t)Lv*E4*Ev];
__device__ __align__(128) bf16 g_Wf1_l [(size_t)Lv*E4*Ev];
__device__ __align__(128) bf16 g_Wf2_h [(size_t)Lv*Ev*E4];
__device__ __align__(128) bf16 g_Wf2_l [(size_t)Lv*Ev*E4];
__device__ __align__(128) bf16 g_Wpat_h[(size_t)Ev*Ev];
__device__ __align__(128) bf16 g_Wpat_l[(size_t)Ev*Ev];

// ---------------- helpers ----------------
__device__ __forceinline__ uint32_t smem_u32(const void* p) {
    uint32_t a;
    asm("{ .reg .u64 t; cvta.to.shared.u64 t, %1; cvt.u32.u64 %0, t; }" : "=r"(a) : "l"(p));
    return a;
}
__device__ __forceinline__ void cp16(uint32_t sa, const void* ga, bool v) {
    int sz = v ? 16 : 0;
    asm volatile("cp.async.cg.shared.global [%0], [%1], 16, %2;" :: "r"(sa), "l"(ga), "r"(sz) : "memory");
}
#define CP_COMMIT() asm volatile("cp.async.commit_group;" ::: "memory")
#define CP_WAIT0()  asm volatile("cp.async.wait_group 0;" ::: "memory")
#define CP_WAIT1()  asm volatile("cp.async.wait_group 1;" ::: "memory")

#define LDSM4(r, a) \
    asm volatile("ldmatrix.sync.aligned.m8n8.x4.shared.b16 {%0,%1,%2,%3}, [%4];" \
        : "=r"((r)[0]),"=r"((r)[1]),"=r"((r)[2]),"=r"((r)[3]) : "r"(a))

__device__ __forceinline__ void mma16816(float* d, const uint32_t* a, const uint32_t* b) {
    asm volatile("mma.sync.aligned.m16n8k16.row.col.f32.bf16.bf16.f32 "
        "{%0,%1,%2,%3}, {%4,%5,%6,%7}, {%8,%9}, {%0,%1,%2,%3};"
        : "+f"(d[0]),"+f"(d[1]),"+f"(d[2]),"+f"(d[3])
        : "r"(a[0]),"r"(a[1]),"r"(a[2]),"r"(a[3]), "r"(b[0]),"r"(b[1]));
}

__device__ __forceinline__ void bf_split(float v, bf16* hi, bf16* lo) {
    bf16 h = __float2bfloat16(v);
    *hi = h;
    *lo = __float2bfloat16(v - __bfloat162float(h));
}

// ---------------- mask ----------------
__device__ __forceinline__ bool keep_fn(int t, int s) {
    bool v = (t == s);
    if (s < 32) v = !(t >= 32 && t < 228);
    if (t >= 228 && s >= 228 && s < 424) v = true;
    if (t >= 424 && s >= 424 && s < 620) v = true;
    return v;
}

// ---------------- positional embedding ----------------
__global__ void pos_kernel(float* POS) {
    int idx = blockIdx.x * 256 + threadIdx.x;
    if (idx >= Tv * Ev) return;
    int t = idx / Ev, j = idx % Ev;
    double expo = (double)(j & ~1) / (double)Ev;
    double ang  = (double)t / pow(10000.0, expo);
    POS[idx] = (float)((j & 1) ? cos(ang) : sin(ang));
}

// ---------------- transpose+convert weights ----------------
__global__ void transpose_conv(const float* __restrict__ src, bf16* __restrict__ dhi,
                               bf16* __restrict__ dlo, int R, int C) {
    __shared__ float t[32][33];
    int z = blockIdx.z;
    src += (size_t)z * R * C; dhi += (size_t)z * R * C; dlo += (size_t)z * R * C;
    int c0 = blockIdx.x * 32, r0 = blockIdx.y * 32;
    int tx = threadIdx.x, ty = threadIdx.y;
    #pragma unroll
    for (int i = 0; i < 4; i++)
        t[ty + 8*i][tx] = src[(size_t)(r0 + ty + 8*i) * C + c0 + tx];
    __syncthreads();
    #pragma unroll
    for (int i = 0; i < 4; i++) {
        float v = t[tx][ty + 8*i];
        size_t o = (size_t)(c0 + ty + 8*i) * R + r0 + tx;
        bf_split(v, dhi + o, dlo + o);
    }
}

__global__ void conv_wqkv(const float* __restrict__ wq, const float* __restrict__ wk,
                          const float* __restrict__ wv, bf16* __restrict__ dhi, bf16* __restrict__ dlo) {
    __shared__ float t[32][33];
    int z = blockIdx.z;
    int h = z % Hv, which = (z / Hv) % 3, l = z / (3 * Hv);
    const float* src = (which == 0) ? wq : (which == 1) ? wk : wv;
    src += ((size_t)l * Hv + h) * Ev * HSv;
    int d0 = blockIdx.x * 32, e0 = blockIdx.y * 32;
    int tx = threadIdx.x, ty = threadIdx.y;
    #pragma unroll
    for (int i = 0; i < 4; i++)
        t[ty + 8*i][tx] = src[(size_t)(e0 + ty + 8*i) * HSv + d0 + tx];
    __syncthreads();
    #pragma unroll
    for (int i = 0; i < 4; i++) {
        int d = d0 + ty + 8*i, e = e0 + tx;
        float v = t[tx][ty + 8*i];
        size_t o = ((size_t)l * QKVLD + which * Ev + h * HSv + d) * Ev + e;
        bf_split(v, dhi + o, dlo + o);
    }
}

// ---------------- gather patches ----------------
__global__ void gather_patches(const float* __restrict__ images, const float* __restrict__ goal_imgs,
                               bf16* __restrict__ Xhi, bf16* __restrict__ Xlo) {
    int idx = blockIdx.x * 256 + threadIdx.x;
    if (idx >= MPATCH * Ev) return;
    int f = idx % Ev;
    int r = idx / Ev;
    int p = r % NPATCH;
    int b = r / NPATCH;
    int py = f / 48, px = (f % 48) / 3, c = f % 3;
    float val;
    if (p < 196) {
        int pr = p / 14, pc = p % 14;
        int y = pr * 16 + py, x = pc * 16 + px;
        val = goal_imgs[(((size_t)b * 224 + y) * 224 + x) * 3 + c];
    } else {
        int q = p - 196;
        int k = q / 196, pp = q % 196;
        int pr = pp / 14, pc = pp % 14;
        int y = pr * 16 + py, x = pc * 16 + px;
        val = images[((((size_t)b * Kv + k) * 224 + y) * 224 + x) * 3 + c];
    }
    bf_split(val, Xhi + idx, Xlo + idx);
}

// ---------------- text + action embed (+POS) ----------------
__global__ void embed_txt_act(const int* __restrict__ goals_txt, const float* __restrict__ text_emb,
                              const float* __restrict__ action_emb, const float* __restrict__ POS,
                              float* __restrict__ X) {
    int idx = blockIdx.x * 256 + threadIdx.x;
    if (idx >= Bv * 33 * Ev) return;
    int e  = idx % Ev;
    int r  = idx / Ev;
    int tt = r % 33;
    int b  = r / 33;
    int t  = (tt < 32) ? tt : 620;
    float v = (tt < 32) ? text_emb[(size_t)goals_txt[b * 32 + tt] * Ev + e] : action_emb[e];
    X[((size_t)b * Tv + t) * Ev + e] = v + POS[(size_t)t * Ev + e];
}

// ---------------- layernorm -> hi/lo bf16 ----------------
__global__ void ln_kernel(const float* __restrict__ X, bf16* __restrict__ Ohi, bf16* __restrict__ Olo,
                          const float* __restrict__ sc, const float* __restrict__ bi) {
    int row = blockIdx.x;
    const float* x = X + (size_t)row * Ev;
    __shared__ float r1[256], r2[256];
    int tid = threadIdx.x;
    float s = 0.f, ss = 0.f;
    for (int e = tid; e < Ev; e += 256) { float v = x[e]; s += v; ss += v * v; }
    r1[tid] = s; r2[tid] = ss;
    __syncthreads();
    for (int off = 128; off; off >>= 1) {
        if (tid < off) { r1[tid] += r1[tid + off]; r2[tid] += r2[tid + off]; }
        __syncthreads();
    }
    float m   = r1[0] * (1.f / Ev);
    float var = r2[0] * (1.f / Ev) - m * m;
    float inv = 1.f / sqrtf(var + 1e-5f);
    for (int e = tid; e < Ev; e += 256) {
        float v = (x[e] - m) * inv * sc[e] + bi[e];
        size_t o = (size_t)row * Ev + e;
        bf_split(v, Ohi + o, Olo + o);
    }
}

// =====================================================================
// bf16x3 linear GEMM (mma.sync), 256x128 CTA tile, 512 threads (16 warps,
// warp tile 64x32), Kc=32, 3-stage cp.async pipeline, A-fragment double
// buffering inside the ks loop (LDSM latency hidden under MMA bursts).
// stage: Ahi 16K @0, Alo 16K @16K, Bhi 8K @32K, Blo 8K @40K  (48K/stage)
// =====================================================================
__global__ void __launch_bounds__(512, 1)
tgemm(int M, int N, int K,
      const bf16* __restrict__ Ahi, const bf16* __restrict__ Alo,
      const bf16* __restrict__ Bhi, const bf16* __restrict__ Blo,
      const float* __restrict__ bias,
      const float* __restrict__ rowmat, int ldrm, int rmode,
      float* outF, int ldo, int accf, int reluf,
      bf16* outHi, bf16* outLo)
{
    extern __shared__ char sm[];
    uint32_t sbase = smem_u32(sm);
    int tid = threadIdx.x, lane = tid & 31, wid = tid >> 5;
    int m0 = blockIdx.y * 256, n0 = blockIdx.x * 128;
    int wm = wid & 3, wn = wid >> 2;   // warp rows: wm*64 (4 bands), warp cols: wn*32 (4 bands)

    float acc[4][4][4];                // [mt][j(np*2+t)][quad]
    #pragma unroll
    for (int i = 0; i < 4; i++)
        #pragma unroll
        for (int j = 0; j < 4; j++)
            #pragma unroll
            for (int q = 0; q < 4; q++) acc[i][j][q] = 0.f;

    int nc = K >> 5;

    // always commits a group; loads only when active
    auto ld_st = [&](int c, int st, bool active) {
        if (active) {
            uint32_t sb = sbase + st * 49152;
            int k0 = c * 32;
            #pragma unroll
            for (int i = 0; i < 2; i++) {              // A: 256 rows x 4 segs = 1024 units
                int u = i * 512 + tid;
                int row = u >> 2, seg = u & 3;
                uint32_t off = (uint32_t)(row * 64 + ((seg ^ ((row >> 1) & 3)) << 4));
                bool av = (m0 + row) < M;
                size_t ao = (size_t)(av ? (m0 + row) : 0) * K + k0 + seg * 8;
                cp16(sb + off,         Ahi + ao, av);
                cp16(sb + 16384 + off, Alo + ao, av);
            }
            {                                          // B: 128 rows x 4 segs = 512 units
                int row = tid >> 2, seg = tid & 3;
                uint32_t off = (uint32_t)(row * 64 + ((seg ^ ((row >> 1) & 3)) << 4));
                size_t bo = (size_t)(n0 + row) * K + k0 + seg * 8;
                cp16(sb + 32768 + off, Bhi + bo, true);
                cp16(sb + 40960 + off, Blo + bo, true);
            }
        }
        CP_COMMIT();
    };

    ld_st(0, 0, true);
    ld_st(1, 1, 1 < nc);

    int matA = lane >> 3;   // 0..3
    int matB = lane >> 3;

    for (int c = 0; c < nc; c++) {
        CP_WAIT1();
        __syncthreads();

        int st = c % 3;
        uint32_t sA_hi = sbase + st * 49152;
        uint32_t sA_lo = sA_hi + 16384;
        uint32_t sB_hi = sA_hi + 32768;
        uint32_t sB_lo = sA_hi + 40960;

        #pragma unroll
        for (int ks = 0; ks < 2; ks++) {
            // ---- load all B fragments for this ks (2 np groups, hi+lo) ----
            uint32_t bfh[2][4], bfl[2][4];
            #pragma unroll
            for (int np = 0; np < 2; np++) {
                int brow = wn * 32 + np * 16 + ((matB >> 1) << 3) + (lane & 7);
                int bseg = ks * 2 + (matB & 1);
                uint32_t boff = (uint32_t)(brow * 64 + ((bseg ^ ((brow >> 1) & 3)) << 4));
                LDSM4(bfh[np], sB_hi + boff);
                LDSM4(bfl[np], sB_lo + boff);
            }
            // ---- A fragments: double-buffered over mt ----
            uint32_t afh[2][4], afl[2][4];
            {
                int arow = wm * 64 + 0 * 16 + (lane & 7) + (matA & 1) * 8;
                int aseg = ks * 2 + (matA >> 1);
                uint32_t aoff = (uint32_t)(arow * 64 + ((aseg ^ ((arow >> 1) & 3)) << 4));
                LDSM4(afh[0], sA_hi + aoff);
                LDSM4(afl[0], sA_lo + aoff);
            }
            #pragma unroll
            for (int mt = 0; mt < 4; mt++) {
                int cur = mt & 1, nxt = cur ^ 1;
                if (mt < 3) {
                    int arow = wm * 64 + (mt + 1) * 16 + (lane & 7) + (matA & 1) * 8;
                    int aseg = ks * 2 + (matA >> 1);
                    uint32_t aoff = (uint32_t)(arow * 64 + ((aseg ^ ((arow >> 1) & 3)) << 4));
                    LDSM4(afh[nxt], sA_hi + aoff);
                    LDSM4(afl[nxt], sA_lo + aoff);
                }
                // 12 MMAs, term-major (4 independent per term group)
                #pragma unroll
                for (int np = 0; np < 2; np++)
                    #pragma unroll
                    for (int t = 0; t < 2; t++)
                        mma16816(acc[mt][np * 2 + t], afh[cur], bfh[np] + 2 * t);
                #pragma unroll
                for (int np = 0; np < 2; np++)
                    #pragma unroll
                    for (int t = 0; t < 2; t++)
                        mma16816(acc[mt][np * 2 + t], afh[cur], bfl[np] + 2 * t);
                #pragma unroll
                for (int np = 0; np < 2; np++)
                    #pragma unroll
                    for (int t = 0; t < 2; t++)
                        mma16816(acc[mt][np * 2 + t], afl[cur], bfh[np] + 2 * t);
            }
        }
        ld_st(c + 2, (c + 2) % 3, c + 2 < nc);
    }

    int r_l = lane >> 2, c_l = (lane & 3) * 2;
    #pragma unroll
    for (int mt = 0; mt < 4; mt++) {
        #pragma unroll
        for (int h = 0; h < 2; h++) {
            int rr = m0 + wm * 64 + mt * 16 + h * 8 + r_l;
            if (rr >= M) continue;
            int orow = rr, prow = rr;
            if (rmode) {
                int b = rr / NPATCH, p = rr - b * NPATCH;
                orow = b * Tv + 32 + p;
                prow = 32 + p;
            }
            #pragma unroll
            for (int j = 0; j < 4; j++) {
                int col = n0 + wn * 32 + j * 8 + c_l;
                float v0 = acc[mt][j][2 * h];
                float v1 = acc[mt][j][2 * h + 1];
                if (bias)   { v0 += bias[col]; v1 += bias[col + 1]; }
                if (rowmat) { const float* rp = rowmat + (size_t)prow * ldrm + col; v0 += rp[0]; v1 += rp[1]; }
                if (accf)   { const float* op = outF + (size_t)orow * ldo + col;   v0 += op[0]; v1 += op[1]; }
                if (reluf)  { v0 = fmaxf(v0, 0.f); v1 = fmaxf(v1, 0.f); }
                if (outF)   *(float2*)(outF + (size_t)orow * ldo + col) = make_float2(v0, v1);
                if (outHi) {
                    size_t o = (size_t)rr * N + col;
                    bf_split(v0, outHi + o, outLo + o);
                    bf_split(v1, outHi + o + 1, outLo + o + 1);
                }
            }
        }
    }
}

// =====================================================================
// qk_mma: S[z][t][s] = (Q K^T)*scale ; 128x128 tile, K=64 one-shot
// =====================================================================
__global__ void __launch_bounds__(256, 2)
qk_mma(const bf16* __restrict__ Qh, const bf16* __restrict__ Ql, float* __restrict__ S)
{
    extern __shared__ char sm[];
    uint32_t sbase = smem_u32(sm);     // +0 Qhi, +16K Qlo, +32K Khi, +48K Klo (128 rows x 128B)
    int tid = threadIdx.x, lane = tid & 31, wid = tid >> 5;
    int z = blockIdx.z, b = z / Hv, h = z % Hv;
    int t0 = blockIdx.y * 128, s0 = blockIdx.x * 128;

    #pragma unroll
    for (int i = 0; i < 4; i++) {
        int u = i * 256 + tid;
        int row = u >> 3, seg = u & 7;
        uint32_t off = (uint32_t)(row * 128 + ((seg ^ (row & 7)) << 4));
        bool qv = (t0 + row) < Tv;
        bool kv = (s0 + row) < Tv;
        size_t qo = (size_t)(b * Tv + (qv ? t0 + row : 0)) * QKVLD + h * HSv + seg * 8;
        size_t ko = (size_t)(b * Tv + (kv ? s0 + row : 0)) * QKVLD + Ev + h * HSv + seg * 8;
        cp16(sbase + off,         Qh + qo, qv);
        cp16(sbase + 16384 + off, Ql + qo, qv);
        cp16(sbase + 32768 + off, Qh + ko, kv);
        cp16(sbase + 49152 + off, Ql + ko, kv);
    }
    CP_COMMIT();
    CP_WAIT0();
    __syncthreads();

    int wm = wid & 3, wn = wid >> 2;
    float acc[2][8][4];
    #pragma unroll
    for (int i = 0; i < 2; i++)
        #pragma unroll
        for (int j = 0; j < 8; j++)
            #pragma unroll
            for (int q = 0; q < 4; q++) acc[i][j][q] = 0.f;

    #pragma unroll
    for (int ks = 0; ks < 4; ks++) {
        uint32_t afh[2][4], afl[2][4];
        #pragma unroll
        for (int mt = 0; mt < 2; mt++) {
            int matA = lane >> 3;
            int arow = wm * 32 + mt * 16 + (lane & 7) + (matA & 1) * 8;
            int aseg = ks * 2 + (matA >> 1);
            uint32_t off = (uint32_t)(arow * 128 + ((aseg ^ (arow & 7)) << 4));
            LDSM4(afh[mt], sbase + off);
            LDSM4(afl[mt], sbase + 16384 + off);
        }
        #pragma unroll
        for (int np = 0; np < 4; np++) {
            uint32_t bfh[4], bfl[4];
            int matB = lane >> 3;
            int brow = wn * 64 + np * 16 + ((matB >> 1) << 3) + (lane & 7);
            int bseg = ks * 2 + (matB & 1);
            uint32_t boff = (uint32_t)(brow * 128 + ((bseg ^ (brow & 7)) << 4));
            LDSM4(bfh, sbase + 32768 + boff);
            LDSM4(bfl, sbase + 49152 + boff);
            #pragma unroll
            for (int t = 0; t < 2; t++)
                #pragma unroll
                for (int mt = 0; mt < 2; mt++)
                    mma16816(acc[mt][np * 2 + t], afh[mt], bfh + 2 * t);
            #pragma unroll
            for (int t = 0; t < 2; t++)
                #pragma unroll
                for (int mt = 0; mt < 2; mt++)
                    mma16816(acc[mt][np * 2 + t], afh[mt], bfl + 2 * t);
            #pragma unroll
            for (int t = 0; t < 2; t++)
                #pragma unroll
                for (int mt = 0; mt < 2; mt++)
                    mma16816(acc[mt][np * 2 + t], afl[mt], bfh + 2 * t);
        }
    }

    int r_l = lane >> 2, c_l = (lane & 3) * 2;
    #pragma unroll
    for (int mt = 0; mt < 2; mt++)
        #pragma unroll
        for (int h2 = 0; h2 < 2; h2++) {
            int rr = t0 + wm * 32 + mt * 16 + h2 * 8 + r_l;
            #pragma unroll
            for (int j = 0; j < 8; j++) {
                int col = s0 + wn * 64 + j * 8 + c_l;
                float2 v = make_float2(acc[mt][j][2 * h2] * SCALE_QK,
                                       acc[mt][j][2 * h2 + 1] * SCALE_QK);
                *(float2*)(S + ((size_t)z * TP + rr) * TP + col) = v;
            }
        }
}

// ---------------- masked softmax: S fp32 -> P hi/lo bf16 (cols padded 0) ----------------
__global__ void softmax_kernel(const float* __restrict__ S,
                               bf16* __restrict__ Ph, bf16* __restrict__ Pl)
{
    int t = blockIdx.x, z = blockIdx.y;
    const float* row = S + ((size_t)z * TP + t) * TP;
    bf16* ph = Ph + ((size_t)z * TP + t) * TP;
    bf16* pl = Pl + ((size_t)z * TP + t) * TP;
    __shared__ float red[256];
    int tid = threadIdx.x;
    float mx = -3.0e38f;
    #pragma unroll
    for (int i = 0; i < 3; i++) {
        int s = tid + i * 256;
        if (s < TP && keep_fn(t, s)) mx = fmaxf(mx, row[s]);
    }
    red[tid] = mx; __syncthreads();
    for (int off = 128; off; off >>= 1) {
        if (tid < off) red[tid] = fmaxf(red[tid], red[tid + off]);
        __syncthreads();
    }
    mx = red[0]; __syncthreads();
    float pv[3]; float sum = 0.f;
    #pragma unroll
    for (int i = 0; i < 3; i++) {
        int s = tid + i * 256;
        float p = 0.f;
        if (s < TP && keep_fn(t, s)) p = expf(row[s] - mx);
        pv[i] = p; sum += p;
    }
    red[tid] = sum; __syncthreads();
    for (int off = 128; off; off >>= 1) {
        if (tid < off) red[tid] += red[tid + off];
        __syncthreads();
    }
    float inv = 1.f / red[0];
    #pragma unroll
    for (int i = 0; i < 3; i++) {
        int s = tid + i * 256;
        if (s < TP) bf_split(pv[i] * inv, ph + s, pl + s);
    }
}

// ---------------- V repack: QKV v-part -> Vt[z][d][s] hi/lo (s padded 0) ----------------
__global__ void repack_v(const bf16* __restrict__ Qh, const bf16* __restrict__ Ql,
                         bf16* __restrict__ Vth, bf16* __restrict__ Vtl)
{
    __shared__ bf16 th[32][33], tl[32][33];
    int z = blockIdx.z, b = z / Hv, h = z % Hv;
    int s0 = blockIdx.x * 32, d0 = blockIdx.y * 32;
    int tx = threadIdx.x, ty = threadIdx.y;
    #pragma unroll
    for (int i = 0; i < 4; i++) {
        int s = s0 + ty + 8 * i;
        bf16 vh = __float2bfloat16(0.f), vl = vh;
        if (s < Tv) {
            size_t o = (size_t)(b * Tv + s) * QKVLD + 2 * Ev + h * HSv + d0 + tx;
            vh = Qh[o]; vl = Ql[o];
        }
        th[ty + 8 * i][tx] = vh;
        tl[ty + 8 * i][tx] = vl;
    }
    __syncthreads();
    #pragma unroll
    for (int i = 0; i < 4; i++) {
        size_t o = ((size_t)z * HSv + d0 + ty + 8 * i) * TP + s0 + tx;
        Vth[o] = th[tx][ty + 8 * i];
        Vtl[o] = tl[tx][ty + 8 * i];
    }
}

// =====================================================================
// pv_mma: O[z][t][d] = P @ V^T-layout ; tile 128x64, Kc=32, 20 chunks,
// 3-stage cp.async pipeline
// =====================================================================
__global__ void __launch_bounds__(256, 2)
pv_mma(const bf16* __restrict__ Ph, const bf16* __restrict__ Pl,
       const bf16* __restrict__ Vth, const bf16* __restrict__ Vtl,
       bf16* __restrict__ Ohi, bf16* __restrict__ Olo)
{
    extern __shared__ char sm[];
    uint32_t sbase = smem_u32(sm);
    // stage layout (24KB): +0 P_hi 8K, +8K P_lo 8K, +16K V_hi 4K, +20K V_lo 4K
    int tid = threadIdx.x, lane = tid & 31, wid = tid >> 5;
    int z = blockIdx.y, b = z / Hv, h = z % Hv;
    int t0 = blockIdx.x * 128;
    int wm = wid & 3, wn = wid >> 2;

    float acc[2][4][4];
    #pragma unroll
    for (int i = 0; i < 2; i++)
        #pragma unroll
        for (int j = 0; j < 4; j++)
            #pragma unroll
            for (int q = 0; q < 4; q++) acc[i][j][q] = 0.f;

    const int nc = TP / 32;

    auto ld_st = [&](int c, int st, bool active) {
        if (active) {
            uint32_t sb = sbase + st * 24576;
            int k0 = c * 32;
            {
                int u = tid;
                int row = u >> 1, seg0 = (u & 1) * 2;
                #pragma unroll
                for (int q = 0; q < 2; q++) {
                    int seg = seg0 + q;
                    uint32_t off = (uint32_t)(row * 64 + ((seg ^ ((row >> 1) & 3)) << 4));
                    size_t po = ((size_t)z * TP + t0 + row) * TP + k0 + seg * 8;
                    cp16(sb + off,        Ph + po, true);
                    cp16(sb + 8192 + off, Pl + po, true);
                }
            }
            {
                int row = tid >> 2, seg = tid & 3;
                uint32_t off = (uint32_t)(row * 64 + ((seg ^ ((row >> 1) & 3)) << 4));
                size_t vo = ((size_t)z * HSv + row) * TP + k0 + seg * 8;
                cp16(sb + 16384 + off, Vth + vo, true);
                cp16(sb + 20480 + off, Vtl + vo, true);
            }
        }
        CP_COMMIT();
    };

    ld_st(0, 0, true);
    ld_st(1, 1, true);

    for (int c = 0; c < nc; c++) {
        CP_WAIT1();
        __syncthreads();

        int st = c % 3;
        uint32_t sP_hi = sbase + st * 24576;
        uint32_t sP_lo = sP_hi + 8192;
        uint32_t sV_hi = sP_hi + 16384;
        uint32_t sV_lo = sP_hi + 20480;

        #pragma unroll
        for (int ks = 0; ks < 2; ks++) {
            uint32_t afh[2][4], afl[2][4];
            #pragma unroll
            for (int mt = 0; mt < 2; mt++) {
                int matA = lane >> 3;
                int arow = wm * 32 + mt * 16 + (lane & 7) + (matA & 1) * 8;
                int aseg = ks * 2 + (matA >> 1);
                uint32_t off = (uint32_t)(arow * 64 + ((aseg ^ ((arow >> 1) & 3)) << 4));
                LDSM4(afh[mt], sP_hi + off);
                LDSM4(afl[mt], sP_lo + off);
            }
            #pragma unroll
            for (int np = 0; np < 2; np++) {
                uint32_t bfh[4], bfl[4];
                int matB = lane >> 3;
                int brow = wn * 32 + np * 16 + ((matB >> 1) << 3) + (lane & 7);
                int bseg = ks * 2 + (matB & 1);
                uint32_t boff = (uint32_t)(brow * 64 + ((bseg ^ ((brow >> 1) & 3)) << 4));
                LDSM4(bfh, sV_hi + boff);
                LDSM4(bfl, sV_lo + boff);
                #pragma unroll
                for (int t = 0; t < 2; t++)
                    #pragma unroll
                    for (int mt = 0; mt < 2; mt++)
                        mma16816(acc[mt][np * 2 + t], afh[mt], bfh + 2 * t);
                #pragma unroll
                for (int t = 0; t < 2; t++)
                    #pragma unroll
                    for (int mt = 0; mt < 2; mt++)
                        mma16816(acc[mt][np * 2 + t], afh[mt], bfl + 2 * t);
                #pragma unroll
                for (int t = 0; t < 2; t++)
                    #pragma unroll
                    for (int mt = 0; mt < 2; mt++)
                        mma16816(acc[mt][np * 2 + t], afl[mt], bfh + 2 * t);
            }
        }
        ld_st(c + 2, (c + 2) % 3, c + 2 < nc);
    }

    int r_l = lane >> 2, c_l = (lane & 3) * 2;
    #pragma unroll
    for (int mt = 0; mt < 2; mt++)
        #pragma unroll
        for (int h2 = 0; h2 < 2; h2++) {
            int rr = t0 + wm * 32 + mt * 16 + h2 * 8 + r_l;
            if (rr >= Tv) continue;
            #pragma unroll
            for (int j = 0; j < 4; j++) {
                int col = wn * 32 + j * 8 + c_l;
                size_t o = ((size_t)(b * Tv + rr)) * Ev + h * HSv + col;
                bf_split(acc[mt][j][2 * h2],     Ohi + o,     Olo + o);
                bf_split(acc[mt][j][2 * h2 + 1], Ohi + o + 1, Olo + o + 1);
            }
        }
}

// ---------------- fp32 GEMM (head only) ----------------
__global__ void __launch_bounds__(256, 2)
sgemm128(int M, int N, int K,
         const float* __restrict__ A, int lda,
         const float* __restrict__ B, int ldb,
         float* __restrict__ C, int ldc,
         const float* __restrict__ bias, int reluflag)
{
    __shared__ __align__(16) float As[8][128];
    __shared__ __align__(16) float Bs[8][128];
    int n0 = blockIdx.x * 128, m0 = blockIdx.y * 128;
    int tid = threadIdx.x;
    int tx = tid & 15, ty = tid >> 4;
    int arow = tid >> 1,  akk  = (tid & 1) * 4;
    int bkk  = tid >> 5,  bcol = (tid & 31) * 4;
    bool aval = (m0 + arow) < M;
    bool bval = (n0 + bcol) < N;
    const float* Aptr = A + (size_t)(m0 + arow) * lda + akk;
    const float* Bptr = B + (size_t)bkk * ldb + n0 + bcol;
    float acc[8][8];
    #pragma unroll
    for (int i = 0; i < 8; i++)
        #pragma unroll
        for (int j = 0; j < 8; j++) acc[i][j] = 0.f;
    for (int k0 = 0; k0 < K; k0 += 8) {
        float4 av = make_float4(0.f,0.f,0.f,0.f), bv = make_float4(0.f,0.f,0.f,0.f);
        if (aval) av = *(const float4*)(Aptr + k0);
        if (bval) bv = *(const float4*)(Bptr + (size_t)k0 * ldb);
        __syncthreads();
        As[akk+0][arow] = av.x; As[akk+1][arow] = av.y;
        As[akk+2][arow] = av.z; As[akk+3][arow] = av.w;
        *(float4*)&Bs[bkk][bcol] = bv;
        __syncthreads();
        #pragma unroll
        for (int kk = 0; kk < 8; kk++) {
            float a[8], b2[8];
            *(float4*)(a)    = *(const float4*)&As[kk][ty*8];
            *(float4*)(a+4)  = *(const float4*)&As[kk][ty*8+4];
            *(float4*)(b2)   = *(const float4*)&Bs[kk][tx*8];
            *(float4*)(b2+4) = *(const float4*)&Bs[kk][tx*8+4];
            #pragma unroll
            for (int i = 0; i < 8; i++)
                #pragma unroll
                for (int j = 0; j < 8; j++)
                    acc[i][j] += a[i] * b2[j];
        }
    }
    #pragma unroll
    for (int i = 0; i < 8; i++) {
        int r = m0 + ty*8 + i;
        if (r >= M) continue;
        #pragma unroll
        for (int j = 0; j < 8; j++) {
            int c = n0 + tx*8 + j;
            if (c >= N) continue;
            float v = acc[i][j];
            if (bias) v += bias[c];
            if (reluflag) v = fmaxf(v, 0.f);
            C[(size_t)r * ldc + c] = v;
        }
    }
}

// ---------------- launch ----------------
extern "C" void kernel_launch(void* const* d_in, const int* in_sizes, int n_in,
                              void* d_out, int out_size) {
    const float* images     = (const float*)d_in[0];
    const int*   goals_txt  = (const int*)  d_in[1];
    const float* goal_imgs  = (const float*)d_in[2];
    const float* patch_w    = (const float*)d_in[3];
    const float* patch_b    = (const float*)d_in[4];
    const float* text_emb   = (const float*)d_in[5];
    const float* action_emb = (const float*)d_in[6];
    const float* wq         = (const float*)d_in[7];
    const float* wk         = (const float*)d_in[8];
    const float* wv         = (const float*)d_in[9];
    const float* proj_w     = (const float*)d_in[10];
    const float* proj_b     = (const float*)d_in[11];
    const float* ln1_s      = (const float*)d_in[12];
    const float* ln1_b      = (const float*)d_in[13];
    const float* ln2_s      = (const float*)d_in[14];
    const float* ln2_b      = (const float*)d_in[15];
    const float* ff_w1      = (const float*)d_in[16];
    const float* ff_b1      = (const float*)d_in[17];
    const float* ff_w2      = (const float*)d_in[18];
    const float* ff_b2      = (const float*)d_in[19];
    const float* hw1        = (const float*)d_in[20];
    const float* hb1        = (const float*)d_in[21];
    const float* hw2        = (const float*)d_in[22];
    const float* hb2        = (const float*)d_in[23];
    float* out = (float*)d_out;

    cudaFuncSetAttribute(tgemm,  cudaFuncAttributeMaxDynamicSharedMemorySize, TGSMEM);
    cudaFuncSetAttribute(qk_mma, cudaFuncAttributeMaxDynamicSharedMemorySize, QKSMEM);
    cudaFuncSetAttribute(pv_mma, cudaFuncAttributeMaxDynamicSharedMemorySize, PVSMEM);

    float *pPOS, *pX, *pS, *pZ;
    bf16 *pHh,*pHl,*pOh,*pOl,*pFh,*pFl,*pXPh,*pXPl,*pQh,*pQl,*pPh,*pPl,*pVth,*pVtl;
    bf16 *pWqh,*pWql,*pWph,*pWpl,*pW1h,*pW1l,*pW2h,*pW2l,*pWth,*pWtl;
    cudaGetSymbolAddress((void**)&pPOS, g_POS);
    cudaGetSymbolAddress((void**)&pX,   g_X);
    cudaGetSymbolAddress((void**)&pS,   g_S);
    cudaGetSymbolAddress((void**)&pZ,   g_Z);
    cudaGetSymbolAddress((void**)&pHh,  g_Hhi);  cudaGetSymbolAddress((void**)&pHl, g_Hlo);
    cudaGetSymbolAddress((void**)&pOh,  g_Ohi);  cudaGetSymbolAddress((void**)&pOl, g_Olo);
    cudaGetSymbolAddress((void**)&pFh,  g_Fhi);  cudaGetSymbolAddress((void**)&pFl, g_Flo);
    cudaGetSymbolAddress((void**)&pXPh, g_XPhi); cudaGetSymbolAddress((void**)&pXPl,g_XPlo);
    cudaGetSymbolAddress((void**)&pQh,  g_QKVh); cudaGetSymbolAddress((void**)&pQl, g_QKVl);
    cudaGetSymbolAddress((void**)&pPh,  g_Ph);   cudaGetSymbolAddress((void**)&pPl, g_Pl);
    cudaGetSymbolAddress((void**)&pVth, g_Vth);  cudaGetSymbolAddress((void**)&pVtl,g_Vtl);
    cudaGetSymbolAddress((void**)&pWqh, g_Wqkv_h); cudaGetSymbolAddress((void**)&pWql, g_Wqkv_l);
    cudaGetSymbolAddress((void**)&pWph, g_Wprj_h); cudaGetSymbolAddress((void**)&pWpl, g_Wprj_l);
    cudaGetSymbolAddress((void**)&pW1h, g_Wf1_h);  cudaGetSymbolAddress((void**)&pW1l, g_Wf1_l);
    cudaGetSymbolAddress((void**)&pW2h, g_Wf2_h);  cudaGetSymbolAddress((void**)&pW2l, g_Wf2_l);
    cudaGetSymbolAddress((void**)&pWth, g_Wpat_h); cudaGetSymbolAddress((void**)&pWtl, g_Wpat_l);

    // ---- prep (launch #4 = dummy QKV-shaped tgemm; ncu -s 5 -c 1 captures my 4th launch) ----
    pos_kernel    <<<CDIV(Tv*Ev, 256), 256>>>(pPOS);                                  // 1
    conv_wqkv     <<<dim3(2, 24, Lv*3*Hv), dim3(32,8)>>>(wq, wk, wv, pWqh, pWql);     // 2
    transpose_conv<<<dim3(24, 24, Lv), dim3(32,8)>>>(proj_w, pWph, pWpl, Ev, Ev);     // 3
    tgemm<<<dim3(QKVLD/128, 10), 512, TGSMEM>>>(                                       // 4 (profiling probe)
        2560, QKVLD, Ev, pXPh, pXPl, pWqh, pWql,
        nullptr, nullptr, 0, 0, pS, QKVLD, 0, 0, nullptr, nullptr);
    transpose_conv<<<dim3(96, 24, Lv), dim3(32,8)>>>(ff_w1, pW1h, pW1l, Ev, E4);      // 5
    transpose_conv<<<dim3(24, 96, Lv), dim3(32,8)>>>(ff_w2, pW2h, pW2l, E4, Ev);      // 6
    transpose_conv<<<dim3(24, 24, 1),  dim3(32,8)>>>(patch_w, pWth, pWtl, Ev, Ev);
    gather_patches<<<CDIV(MPATCH*Ev, 256), 256>>>(images, goal_imgs, pXPh, pXPl);
    embed_txt_act <<<CDIV(Bv*33*Ev, 256), 256>>>(goals_txt, text_emb, action_emb, pPOS, pX);

    // patch embed -> X rows 32..619 (+bias +POS)
    tgemm<<<dim3(Ev/128, CDIV(MPATCH,256)), 512, TGSMEM>>>(
        MPATCH, Ev, Ev, pXPh, pXPl, pWth, pWtl,
        patch_b, pPOS, Ev, 1,
        pX, Ev, 0, 0, nullptr, nullptr);

    for (int l = 0; l < Lv; l++) {
        ln_kernel<<<MTv, 256>>>(pX, pHh, pHl, ln1_s + l*Ev, ln1_b + l*Ev);

        tgemm<<<dim3(QKVLD/128, CDIV(MTv,256)), 512, TGSMEM>>>(   // QKV -> bf16 hi/lo
            MTv, QKVLD, Ev, pHh, pHl,
            pWqh + (size_t)l*QKVLD*Ev, pWql + (size_t)l*QKVLD*Ev,
            nullptr, nullptr, 0, 0,
            nullptr, 0, 0, 0, pQh, pQl);

        qk_mma        <<<dim3(TP/128, TP/128, ZH), 256, QKSMEM>>>(pQh, pQl, pS);
        softmax_kernel<<<dim3(Tv, ZH), 256>>>(pS, pPh, pPl);
        repack_v      <<<dim3(TP/32, HSv/32, ZH), dim3(32,8)>>>(pQh, pQl, pVth, pVtl);
        pv_mma        <<<dim3(TP/128, ZH), 256, PVSMEM>>>(pPh, pPl, pVth, pVtl, pOh, pOl);

        tgemm<<<dim3(Ev/128, CDIV(MTv,256)), 512, TGSMEM>>>(   // X += O @ proj + b
            MTv, Ev, Ev, pOh, pOl,
            pWph + (size_t)l*Ev*Ev, pWpl + (size_t)l*Ev*Ev,
            proj_b + l*Ev, nullptr, 0, 0,
            pX, Ev, 1, 0, nullptr, nullptr);

        ln_kernel<<<MTv, 256>>>(pX, pHh, pHl, ln2_s + l*Ev, ln2_b + l*Ev);

        tgemm<<<dim3(E4/128, CDIV(MTv,256)), 512, TGSMEM>>>(   // F = relu(h@W1+b1)
            MTv, E4, Ev, pHh, pHl,
            pW1h + (size_t)l*E4*Ev, pW1l + (size_t)l*E4*Ev,
            ff_b1 + l*E4, nullptr, 0, 0,
            nullptr, 0, 0, 1, pFh, pFl);

        tgemm<<<dim3(Ev/128, CDIV(MTv,256)), 512, TGSMEM>>>(   // X += F @ W2 + b2
            MTv, Ev, E4, pFh, pFl,
            pW2h + (size_t)l*Ev*E4, pW2l + (size_t)l*Ev*E4,
            ff_b2 + l*Ev, nullptr, 0, 0,
            pX, Ev, 1, 0, nullptr, nullptr);
    }

    // head
    sgemm128<<<dim3(Ev/128, 1), 256>>>(
        Bv, Ev, Ev, pX + (size_t)620*Ev, Tv*Ev, hw1, Ev, pZ, Ev, hb1, 1);
    sgemm128<<<dim3(1, 1), 256>>>(
        Bv, AOUTv, Ev, pZ, Ev, hw2, AOUTv, out, AOUTv, hb2, 0);

    (void)in_sizes; (void)n_in; (void)out_size;
}

// round 9
// speedup vs baseline: 1.9430x; 1.8701x over previous
#include <cuda_runtime.h>
#include <cuda_fp16.h>
#include <math.h>
#include <stdint.h>
#include <stddef.h>

// ---------------- problem constants ----------------
#define Bv      16
#define Kv      2
#define Ev      768
#define Hv      12
#define HSv     64
#define Lv      12
#define Tv      621
#define TP      640
#define NPATCH  588
#define QKVLD   2304
#define E4      3072
#define AOUTv   64
#define MTv     (Bv*Tv)      // 9936
#define MPATCH  (Bv*NPATCH)  // 9408
#define ZH      (Bv*Hv)      // 192
#define SCALE_QK 0.036084391824351615f

#define CDIV(a,b) (((a)+(b)-1)/(b))
#define TGSMEM   147456      // 3 stages x 48KB (A 32K + B 16K)
#define QKSMEM   32768
#define PVSMEM   36864       // 3 stages x 12KB

typedef __half h16;

// ---------------- scratch ----------------
__device__ __align__(128) float g_POS[Tv*Ev];
__device__ __align__(128) float g_X  [(size_t)MTv*Ev];
__device__ __align__(128) float g_S  [(size_t)ZH*TP*TP];
__device__ __align__(128) float g_Z  [Bv*Ev];

__device__ __align__(128) h16 g_H  [(size_t)MTv*Ev];
__device__ __align__(128) h16 g_O  [(size_t)MTv*Ev];
__device__ __align__(128) h16 g_F  [(size_t)MTv*E4];
__device__ __align__(128) h16 g_XP [(size_t)MPATCH*Ev];
__device__ __align__(128) h16 g_QKV[(size_t)MTv*QKVLD];
__device__ __align__(128) h16 g_P  [(size_t)ZH*TP*TP];
__device__ __align__(128) h16 g_Vt [(size_t)ZH*HSv*TP];

__device__ __align__(128) h16 g_Wqkv[(size_t)Lv*QKVLD*Ev];
__device__ __align__(128) h16 g_Wprj[(size_t)Lv*Ev*Ev];
__device__ __align__(128) h16 g_Wf1 [(size_t)Lv*E4*Ev];
__device__ __align__(128) h16 g_Wf2 [(size_t)Lv*Ev*E4];
__device__ __align__(128) h16 g_Wpat[(size_t)Ev*Ev];

// ---------------- helpers ----------------
__device__ __forceinline__ uint32_t smem_u32(const void* p) {
    uint32_t a;
    asm("{ .reg .u64 t; cvta.to.shared.u64 t, %1; cvt.u32.u64 %0, t; }" : "=r"(a) : "l"(p));
    return a;
}
__device__ __forceinline__ void cp16(uint32_t sa, const void* ga, bool v) {
    int sz = v ? 16 : 0;
    asm volatile("cp.async.cg.shared.global [%0], [%1], 16, %2;" :: "r"(sa), "l"(ga), "r"(sz) : "memory");
}
#define CP_COMMIT() asm volatile("cp.async.commit_group;" ::: "memory")
#define CP_WAIT0()  asm volatile("cp.async.wait_group 0;" ::: "memory")
#define CP_WAIT1()  asm volatile("cp.async.wait_group 1;" ::: "memory")

#define LDSM4(r, a) \
    asm volatile("ldmatrix.sync.aligned.m8n8.x4.shared.b16 {%0,%1,%2,%3}, [%4];" \
        : "=r"((r)[0]),"=r"((r)[1]),"=r"((r)[2]),"=r"((r)[3]) : "r"(a))

__device__ __forceinline__ void mma16816(float* d, const uint32_t* a, const uint32_t* b) {
    asm volatile("mma.sync.aligned.m16n8k16.row.col.f32.f16.f16.f32 "
        "{%0,%1,%2,%3}, {%4,%5,%6,%7}, {%8,%9}, {%0,%1,%2,%3};"
        : "+f"(d[0]),"+f"(d[1]),"+f"(d[2]),"+f"(d[3])
        : "r"(a[0]),"r"(a[1]),"r"(a[2]),"r"(a[3]), "r"(b[0]),"r"(b[1]));
}

// ---------------- mask ----------------
__device__ __forceinline__ bool keep_fn(int t, int s) {
    bool v = (t == s);
    if (s < 32) v = !(t >= 32 && t < 228);
    if (t >= 228 && s >= 228 && s < 424) v = true;
    if (t >= 424 && s >= 424 && s < 620) v = true;
    return v;
}

// ---------------- positional embedding ----------------
__global__ void pos_kernel(float* POS) {
    int idx = blockIdx.x * 256 + threadIdx.x;
    if (idx >= Tv * Ev) return;
    int t = idx / Ev, j = idx % Ev;
    double expo = (double)(j & ~1) / (double)Ev;
    double ang  = (double)t / pow(10000.0, expo);
    POS[idx] = (float)((j & 1) ? cos(ang) : sin(ang));
}

// ---------------- transpose+convert weights: src [z][R][C] f32 -> dst [z][C][R] fp16 ----------------
__global__ void transpose_conv(const float* __restrict__ src, h16* __restrict__ dst, int R, int C) {
    __shared__ float t[32][33];
    int z = blockIdx.z;
    src += (size_t)z * R * C; dst += (size_t)z * R * C;
    int c0 = blockIdx.x * 32, r0 = blockIdx.y * 32;
    int tx = threadIdx.x, ty = threadIdx.y;
    #pragma unroll
    for (int i = 0; i < 4; i++)
        t[ty + 8*i][tx] = src[(size_t)(r0 + ty + 8*i) * C + c0 + tx];
    __syncthreads();
    #pragma unroll
    for (int i = 0; i < 4; i++)
        dst[(size_t)(c0 + ty + 8*i) * R + r0 + tx] = __float2half(t[tx][ty + 8*i]);
}

__global__ void conv_wqkv(const float* __restrict__ wq, const float* __restrict__ wk,
                          const float* __restrict__ wv, h16* __restrict__ dst) {
    __shared__ float t[32][33];
    int z = blockIdx.z;
    int h = z % Hv, which = (z / Hv) % 3, l = z / (3 * Hv);
    const float* src = (which == 0) ? wq : (which == 1) ? wk : wv;
    src += ((size_t)l * Hv + h) * Ev * HSv;
    int d0 = blockIdx.x * 32, e0 = blockIdx.y * 32;
    int tx = threadIdx.x, ty = threadIdx.y;
    #pragma unroll
    for (int i = 0; i < 4; i++)
        t[ty + 8*i][tx] = src[(size_t)(e0 + ty + 8*i) * HSv + d0 + tx];
    __syncthreads();
    #pragma unroll
    for (int i = 0; i < 4; i++) {
        int d = d0 + ty + 8*i, e = e0 + tx;
        dst[((size_t)l * QKVLD + which * Ev + h * HSv + d) * Ev + e] = __float2half(t[tx][ty + 8*i]);
    }
}

// ---------------- gather patches -> fp16 ----------------
__global__ void gather_patches(const float* __restrict__ images, const float* __restrict__ goal_imgs,
                               h16* __restrict__ X) {
    int idx = blockIdx.x * 256 + threadIdx.x;
    if (idx >= MPATCH * Ev) return;
    int f = idx % Ev;
    int r = idx / Ev;
    int p = r % NPATCH;
    int b = r / NPATCH;
    int py = f / 48, px = (f % 48) / 3, c = f % 3;
    float val;
    if (p < 196) {
        int pr = p / 14, pc = p % 14;
        int y = pr * 16 + py, x = pc * 16 + px;
        val = goal_imgs[(((size_t)b * 224 + y) * 224 + x) * 3 + c];
    } else {
        int q = p - 196;
        int k = q / 196, pp = q % 196;
        int pr = pp / 14, pc = pp % 14;
        int y = pr * 16 + py, x = pc * 16 + px;
        val = images[((((size_t)b * Kv + k) * 224 + y) * 224 + x) * 3 + c];
    }
    X[idx] = __float2half(val);
}

// ---------------- text + action embed (+POS) ----------------
__global__ void embed_txt_act(const int* __restrict__ goals_txt, const float* __restrict__ text_emb,
                              const float* __restrict__ action_emb, const float* __restrict__ POS,
                              float* __restrict__ X) {
    int idx = blockIdx.x * 256 + threadIdx.x;
    if (idx >= Bv * 33 * Ev) return;
    int e  = idx % Ev;
    int r  = idx / Ev;
    int tt = r % 33;
    int b  = r / 33;
    int t  = (tt < 32) ? tt : 620;
    float v = (tt < 32) ? text_emb[(size_t)goals_txt[b * 32 + tt] * Ev + e] : action_emb[e];
    X[((size_t)b * Tv + t) * Ev + e] = v + POS[(size_t)t * Ev + e];
}

// ---------------- layernorm -> fp16 ----------------
__global__ void ln_kernel(const float* __restrict__ X, h16* __restrict__ Out,
                          const float* __restrict__ sc, const float* __restrict__ bi) {
    int row = blockIdx.x;
    const float* x = X + (size_t)row * Ev;
    __shared__ float r1[256], r2[256];
    int tid = threadIdx.x;
    float s = 0.f, ss = 0.f;
    for (int e = tid; e < Ev; e += 256) { float v = x[e]; s += v; ss += v * v; }
    r1[tid] = s; r2[tid] = ss;
    __syncthreads();
    for (int off = 128; off; off >>= 1) {
        if (tid < off) { r1[tid] += r1[tid + off]; r2[tid] += r2[tid + off]; }
        __syncthreads();
    }
    float m   = r1[0] * (1.f / Ev);
    float var = r2[0] * (1.f / Ev) - m * m;
    float inv = 1.f / sqrtf(var + 1e-5f);
    for (int e = tid; e < Ev; e += 256)
        Out[(size_t)row * Ev + e] = __float2half((x[e] - m) * inv * sc[e] + bi[e]);
}

// =====================================================================
// fp16 GEMM (mma.sync m16n8k16), 256x128 CTA tile, 256 threads (8 warps,
// warp tile 64x64), Kc=64, 3-stage cp.async pipeline.
// stage: A 32K @0 (256 rows x 128B swizzled), B 16K @32K (128 rows x 128B)
// =====================================================================
__global__ void __launch_bounds__(256, 1)
tgemm(int M, int N, int K,
      const h16* __restrict__ A, const h16* __restrict__ B,
      const float* __restrict__ bias,
      const float* __restrict__ rowmat, int ldrm, int rmode,
      float* outF, int ldo, int accf, int reluf,
      h16* outH)
{
    extern __shared__ char sm[];
    uint32_t sbase = smem_u32(sm);
    int tid = threadIdx.x, lane = tid & 31, wid = tid >> 5;
    int m0 = blockIdx.y * 256, n0 = blockIdx.x * 128;
    int wm = wid & 3, wn = wid >> 2;   // warp rows: wm*64, warp cols: wn*64

    float acc[4][8][4];
    #pragma unroll
    for (int i = 0; i < 4; i++)
        #pragma unroll
        for (int j = 0; j < 8; j++)
            #pragma unroll
            for (int q = 0; q < 4; q++) acc[i][j][q] = 0.f;

    int nc = K >> 6;

    auto ld_st = [&](int c, int st, bool active) {
        if (active) {
            uint32_t sb = sbase + st * 49152;
            int k0 = c * 64;
            #pragma unroll
            for (int i = 0; i < 8; i++) {              // A: 256 rows x 8 segs = 2048 units
                int u = i * 256 + tid;
                int row = u >> 3, seg = u & 7;
                uint32_t off = (uint32_t)(row * 128 + ((seg ^ (row & 7)) << 4));
                bool av = (m0 + row) < M;
                size_t ao = (size_t)(av ? (m0 + row) : 0) * K + k0 + seg * 8;
                cp16(sb + off, A + ao, av);
            }
            #pragma unroll
            for (int i = 0; i < 4; i++) {              // B: 128 rows x 8 segs = 1024 units
                int u = i * 256 + tid;
                int row = u >> 3, seg = u & 7;
                uint32_t off = (uint32_t)(row * 128 + ((seg ^ (row & 7)) << 4));
                size_t bo = (size_t)(n0 + row) * K + k0 + seg * 8;
                cp16(sb + 32768 + off, B + bo, true);
            }
        }
        CP_COMMIT();
    };

    ld_st(0, 0, true);
    ld_st(1, 1, 1 < nc);

    int matA = lane >> 3;
    int matB = lane >> 3;

    for (int c = 0; c < nc; c++) {
        CP_WAIT1();
        __syncthreads();

        int st = c % 3;
        uint32_t sA = sbase + st * 49152;
        uint32_t sB = sA + 32768;

        #pragma unroll
        for (int ks = 0; ks < 4; ks++) {
            // B fragments for this ks: 4 np groups (64 cols)
            uint32_t bf[4][4];
            #pragma unroll
            for (int np = 0; np < 4; np++) {
                int brow = wn * 64 + np * 16 + ((matB >> 1) << 3) + (lane & 7);
                int bseg = ks * 2 + (matB & 1);
                uint32_t boff = (uint32_t)(brow * 128 + ((bseg ^ (brow & 7)) << 4));
                LDSM4(bf[np], sB + boff);
            }
            // A fragments double-buffered over mt
            uint32_t af[2][4];
            {
                int arow = wm * 64 + (lane & 7) + (matA & 1) * 8;
                int aseg = ks * 2 + (matA >> 1);
                uint32_t aoff = (uint32_t)(arow * 128 + ((aseg ^ (arow & 7)) << 4));
                LDSM4(af[0], sA + aoff);
            }
            #pragma unroll
            for (int mt = 0; mt < 4; mt++) {
                int cur = mt & 1, nxt = cur ^ 1;
                if (mt < 3) {
                    int arow = wm * 64 + (mt + 1) * 16 + (lane & 7) + (matA & 1) * 8;
                    int aseg = ks * 2 + (matA >> 1);
                    uint32_t aoff = (uint32_t)(arow * 128 + ((aseg ^ (arow & 7)) << 4));
                    LDSM4(af[nxt], sA + aoff);
                }
                #pragma unroll
                for (int np = 0; np < 4; np++)
                    #pragma unroll
                    for (int t = 0; t < 2; t++)
                        mma16816(acc[mt][np * 2 + t], af[cur], bf[np] + 2 * t);
            }
        }
        ld_st(c + 2, (c + 2) % 3, c + 2 < nc);
    }

    int r_l = lane >> 2, c_l = (lane & 3) * 2;
    #pragma unroll
    for (int mt = 0; mt < 4; mt++) {
        #pragma unroll
        for (int h = 0; h < 2; h++) {
            int rr = m0 + wm * 64 + mt * 16 + h * 8 + r_l;
            if (rr >= M) continue;
            int orow = rr, prow = rr;
            if (rmode) {
                int b = rr / NPATCH, p = rr - b * NPATCH;
                orow = b * Tv + 32 + p;
                prow = 32 + p;
            }
            #pragma unroll
            for (int j = 0; j < 8; j++) {
                int col = n0 + wn * 64 + j * 8 + c_l;
                float v0 = acc[mt][j][2 * h];
                float v1 = acc[mt][j][2 * h + 1];
                if (bias)   { v0 += bias[col]; v1 += bias[col + 1]; }
                if (rowmat) { const float* rp = rowmat + (size_t)prow * ldrm + col; v0 += rp[0]; v1 += rp[1]; }
                if (accf)   { const float* op = outF + (size_t)orow * ldo + col;   v0 += op[0]; v1 += op[1]; }
                if (reluf)  { v0 = fmaxf(v0, 0.f); v1 = fmaxf(v1, 0.f); }
                if (outF)   *(float2*)(outF + (size_t)orow * ldo + col) = make_float2(v0, v1);
                if (outH) {
                    size_t o = (size_t)rr * N + col;
                    outH[o]     = __float2half(v0);
                    outH[o + 1] = __float2half(v1);
                }
            }
        }
    }
}

// =====================================================================
// qk_mma: S[z][t][s] = (Q K^T)*scale ; 128x128 tile, K=64 one-shot, fp16
// =====================================================================
__global__ void __launch_bounds__(256, 2)
qk_mma(const h16* __restrict__ Q, float* __restrict__ S)
{
    extern __shared__ char sm[];
    uint32_t sbase = smem_u32(sm);     // +0 Q (16K), +16K K (16K); 128 rows x 128B
    int tid = threadIdx.x, lane = tid & 31, wid = tid >> 5;
    int z = blockIdx.z, b = z / Hv, h = z % Hv;
    int t0 = blockIdx.y * 128, s0 = blockIdx.x * 128;

    #pragma unroll
    for (int i = 0; i < 4; i++) {
        int u = i * 256 + tid;
        int row = u >> 3, seg = u & 7;
        uint32_t off = (uint32_t)(row * 128 + ((seg ^ (row & 7)) << 4));
        bool qv = (t0 + row) < Tv;
        bool kv = (s0 + row) < Tv;
        size_t qo = (size_t)(b * Tv + (qv ? t0 + row : 0)) * QKVLD + h * HSv + seg * 8;
        size_t ko = (size_t)(b * Tv + (kv ? s0 + row : 0)) * QKVLD + Ev + h * HSv + seg * 8;
        cp16(sbase + off,         Q + qo, qv);
        cp16(sbase + 16384 + off, Q + ko, kv);
    }
    CP_COMMIT();
    CP_WAIT0();
    __syncthreads();

    int wm = wid & 3, wn = wid >> 2;
    float acc[2][8][4];
    #pragma unroll
    for (int i = 0; i < 2; i++)
        #pragma unroll
        for (int j = 0; j < 8; j++)
            #pragma unroll
            for (int q = 0; q < 4; q++) acc[i][j][q] = 0.f;

    #pragma unroll
    for (int ks = 0; ks < 4; ks++) {
        uint32_t af[2][4];
        #pragma unroll
        for (int mt = 0; mt < 2; mt++) {
            int matA = lane >> 3;
            int arow = wm * 32 + mt * 16 + (lane & 7) + (matA & 1) * 8;
            int aseg = ks * 2 + (matA >> 1);
            uint32_t off = (uint32_t)(arow * 128 + ((aseg ^ (arow & 7)) << 4));
            LDSM4(af[mt], sbase + off);
        }
        #pragma unroll
        for (int np = 0; np < 4; np++) {
            uint32_t bf[4];
            int matB = lane >> 3;
            int brow = wn * 64 + np * 16 + ((matB >> 1) << 3) + (lane & 7);
            int bseg = ks * 2 + (matB & 1);
            uint32_t boff = (uint32_t)(brow * 128 + ((bseg ^ (brow & 7)) << 4));
            LDSM4(bf, sbase + 16384 + boff);
            #pragma unroll
            for (int t = 0; t < 2; t++)
                #pragma unroll
                for (int mt = 0; mt < 2; mt++)
                    mma16816(acc[mt][np * 2 + t], af[mt], bf + 2 * t);
        }
    }

    int r_l = lane >> 2, c_l = (lane & 3) * 2;
    #pragma unroll
    for (int mt = 0; mt < 2; mt++)
        #pragma unroll
        for (int h2 = 0; h2 < 2; h2++) {
            int rr = t0 + wm * 32 + mt * 16 + h2 * 8 + r_l;
            #pragma unroll
            for (int j = 0; j < 8; j++) {
                int col = s0 + wn * 64 + j * 8 + c_l;
                float2 v = make_float2(acc[mt][j][2 * h2] * SCALE_QK,
                                       acc[mt][j][2 * h2 + 1] * SCALE_QK);
                *(float2*)(S + ((size_t)z * TP + rr) * TP + col) = v;
            }
        }
}

// ---------------- masked softmax: S fp32 -> P fp16 (cols padded 0) ----------------
__global__ void softmax_kernel(const float* __restrict__ S, h16* __restrict__ P)
{
    int t = blockIdx.x, z = blockIdx.y;
    const float* row = S + ((size_t)z * TP + t) * TP;
    h16* ph = P + ((size_t)z * TP + t) * TP;
    __shared__ float red[256];
    int tid = threadIdx.x;
    float mx = -3.0e38f;
    #pragma unroll
    for (int i = 0; i < 3; i++) {
        int s = tid + i * 256;
        if (s < TP && keep_fn(t, s)) mx = fmaxf(mx, row[s]);
    }
    red[tid] = mx; __syncthreads();
    for (int off = 128; off; off >>= 1) {
        if (tid < off) red[tid] = fmaxf(red[tid], red[tid + off]);
        __syncthreads();
    }
    mx = red[0]; __syncthreads();
    float pv[3]; float sum = 0.f;
    #pragma unroll
    for (int i = 0; i < 3; i++) {
        int s = tid + i * 256;
        float p = 0.f;
        if (s < TP && keep_fn(t, s)) p = expf(row[s] - mx);
        pv[i] = p; sum += p;
    }
    red[tid] = sum; __syncthreads();
    for (int off = 128; off; off >>= 1) {
        if (tid < off) red[tid] += red[tid + off];
        __syncthreads();
    }
    float inv = 1.f / red[0];
    #pragma unroll
    for (int i = 0; i < 3; i++) {
        int s = tid + i * 256;
        if (s < TP) ph[s] = __float2half(pv[i] * inv);
    }
}

// ---------------- V repack: QKV v-part -> Vt[z][d][s] fp16 (s padded 0) ----------------
__global__ void repack_v(const h16* __restrict__ Q, h16* __restrict__ Vt)
{
    __shared__ h16 th[32][33];
    int z = blockIdx.z, b = z / Hv, h = z % Hv;
    int s0 = blockIdx.x * 32, d0 = blockIdx.y * 32;
    int tx = threadIdx.x, ty = threadIdx.y;
    #pragma unroll
    for (int i = 0; i < 4; i++) {
        int s = s0 + ty + 8 * i;
        h16 vh = __float2half(0.f);
        if (s < Tv)
            vh = Q[(size_t)(b * Tv + s) * QKVLD + 2 * Ev + h * HSv + d0 + tx];
        th[ty + 8 * i][tx] = vh;
    }
    __syncthreads();
    #pragma unroll
    for (int i = 0; i < 4; i++)
        Vt[((size_t)z * HSv + d0 + ty + 8 * i) * TP + s0 + tx] = th[tx][ty + 8 * i];
}

// =====================================================================
// pv_mma: O[z][t][d] = P @ V^T-layout ; tile 128x64, Kc=32, 3-stage, fp16
// stage (12KB): P 8K @0 (128 rows x 64B), V 4K @8K (64 rows x 64B)
// =====================================================================
__global__ void __launch_bounds__(256, 2)
pv_mma(const h16* __restrict__ P, const h16* __restrict__ Vt, h16* __restrict__ O)
{
    extern __shared__ char sm[];
    uint32_t sbase = smem_u32(sm);
    int tid = threadIdx.x, lane = tid & 31, wid = tid >> 5;
    int z = blockIdx.y, b = z / Hv, h = z % Hv;
    int t0 = blockIdx.x * 128;
    int wm = wid & 3, wn = wid >> 2;

    float acc[2][4][4];
    #pragma unroll
    for (int i = 0; i < 2; i++)
        #pragma unroll
        for (int j = 0; j < 4; j++)
            #pragma unroll
            for (int q = 0; q < 4; q++) acc[i][j][q] = 0.f;

    const int nc = TP / 32;

    auto ld_st = [&](int c, int st, bool active) {
        if (active) {
            uint32_t sb = sbase + st * 12288;
            int k0 = c * 32;
            {   // P: 128 rows x 4 segs = 512 -> 2/thread
                int u = tid;
                int row = u >> 1, seg0 = (u & 1) * 2;
                #pragma unroll
                for (int q = 0; q < 2; q++) {
                    int seg = seg0 + q;
                    uint32_t off = (uint32_t)(row * 64 + ((seg ^ ((row >> 1) & 3)) << 4));
                    size_t po = ((size_t)z * TP + t0 + row) * TP + k0 + seg * 8;
                    cp16(sb + off, P + po, true);
                }
            }
            {   // V: 64 rows x 4 segs = 256 -> 1/thread
                int row = tid >> 2, seg = tid & 3;
                uint32_t off = (uint32_t)(row * 64 + ((seg ^ ((row >> 1) & 3)) << 4));
                size_t vo = ((size_t)z * HSv + row) * TP + k0 + seg * 8;
                cp16(sb + 8192 + off, Vt + vo, true);
            }
        }
        CP_COMMIT();
    };

    ld_st(0, 0, true);
    ld_st(1, 1, true);

    for (int c = 0; c < nc; c++) {
        CP_WAIT1();
        __syncthreads();

        int st = c % 3;
        uint32_t sP = sbase + st * 12288;
        uint32_t sV = sP + 8192;

        #pragma unroll
        for (int ks = 0; ks < 2; ks++) {
            uint32_t af[2][4];
            #pragma unroll
            for (int mt = 0; mt < 2; mt++) {
                int matA = lane >> 3;
                int arow = wm * 32 + mt * 16 + (lane & 7) + (matA & 1) * 8;
                int aseg = ks * 2 + (matA >> 1);
                uint32_t off = (uint32_t)(arow * 64 + ((aseg ^ ((arow >> 1) & 3)) << 4));
                LDSM4(af[mt], sP + off);
            }
            #pragma unroll
            for (int np = 0; np < 2; np++) {
                uint32_t bf[4];
                int matB = lane >> 3;
                int brow = wn * 32 + np * 16 + ((matB >> 1) << 3) + (lane & 7);
                int bseg = ks * 2 + (matB & 1);
                uint32_t boff = (uint32_t)(brow * 64 + ((bseg ^ ((brow >> 1) & 3)) << 4));
                LDSM4(bf, sV + boff);
                #pragma unroll
                for (int t = 0; t < 2; t++)
                    #pragma unroll
                    for (int mt = 0; mt < 2; mt++)
                        mma16816(acc[mt][np * 2 + t], af[mt], bf + 2 * t);
            }
        }
        ld_st(c + 2, (c + 2) % 3, c + 2 < nc);
    }

    int r_l = lane >> 2, c_l = (lane & 3) * 2;
    #pragma unroll
    for (int mt = 0; mt < 2; mt++)
        #pragma unroll
        for (int h2 = 0; h2 < 2; h2++) {
            int rr = t0 + wm * 32 + mt * 16 + h2 * 8 + r_l;
            if (rr >= Tv) continue;
            #pragma unroll
            for (int j = 0; j < 4; j++) {
                int col = wn * 32 + j * 8 + c_l;
                size_t o = ((size_t)(b * Tv + rr)) * Ev + h * HSv + col;
                O[o]     = __float2half(acc[mt][j][2 * h2]);
                O[o + 1] = __float2half(acc[mt][j][2 * h2 + 1]);
            }
        }
}

// ---------------- fp32 GEMM (head only) ----------------
__global__ void __launch_bounds__(256, 2)
sgemm128(int M, int N, int K,
         const float* __restrict__ A, int lda,
         const float* __restrict__ B, int ldb,
         float* __restrict__ C, int ldc,
         const float* __restrict__ bias, int reluflag)
{
    __shared__ __align__(16) float As[8][128];
    __shared__ __align__(16) float Bs[8][128];
    int n0 = blockIdx.x * 128, m0 = blockIdx.y * 128;
    int tid = threadIdx.x;
    int tx = tid & 15, ty = tid >> 4;
    int arow = tid >> 1,  akk  = (tid & 1) * 4;
    int bkk  = tid >> 5,  bcol = (tid & 31) * 4;
    bool aval = (m0 + arow) < M;
    bool bval = (n0 + bcol) < N;
    const float* Aptr = A + (size_t)(m0 + arow) * lda + akk;
    const float* Bptr = B + (size_t)bkk * ldb + n0 + bcol;
    float acc[8][8];
    #pragma unroll
    for (int i = 0; i < 8; i++)
        #pragma unroll
        for (int j = 0; j < 8; j++) acc[i][j] = 0.f;
    for (int k0 = 0; k0 < K; k0 += 8) {
        float4 av = make_float4(0.f,0.f,0.f,0.f), bv = make_float4(0.f,0.f,0.f,0.f);
        if (aval) av = *(const float4*)(Aptr + k0);
        if (bval) bv = *(const float4*)(Bptr + (size_t)k0 * ldb);
        __syncthreads();
        As[akk+0][arow] = av.x; As[akk+1][arow] = av.y;
        As[akk+2][arow] = av.z; As[akk+3][arow] = av.w;
        *(float4*)&Bs[bkk][bcol] = bv;
        __syncthreads();
        #pragma unroll
        for (int kk = 0; kk < 8; kk++) {
            float a[8], b2[8];
            *(float4*)(a)    = *(const float4*)&As[kk][ty*8];
            *(float4*)(a+4)  = *(const float4*)&As[kk][ty*8+4];
            *(float4*)(b2)   = *(const float4*)&Bs[kk][tx*8];
            *(float4*)(b2+4) = *(const float4*)&Bs[kk][tx*8+4];
            #pragma unroll
            for (int i = 0; i < 8; i++)
                #pragma unroll
                for (int j = 0; j < 8; j++)
                    acc[i][j] += a[i] * b2[j];
        }
    }
    #pragma unroll
    for (int i = 0; i < 8; i++) {
        int r = m0 + ty*8 + i;
        if (r >= M) continue;
        #pragma unroll
        for (int j = 0; j < 8; j++) {
            int c = n0 + tx*8 + j;
            if (c >= N) continue;
            float v = acc[i][j];
            if (bias) v += bias[c];
            if (reluflag) v = fmaxf(v, 0.f);
            C[(size_t)r * ldc + c] = v;
        }
    }
}

// ---------------- launch ----------------
extern "C" void kernel_launch(void* const* d_in, const int* in_sizes, int n_in,
                              void* d_out, int out_size) {
    const float* images     = (const float*)d_in[0];
    const int*   goals_txt  = (const int*)  d_in[1];
    const float* goal_imgs  = (const float*)d_in[2];
    const float* patch_w    = (const float*)d_in[3];
    const float* patch_b    = (const float*)d_in[4];
    const float* text_emb   = (const float*)d_in[5];
    const float* action_emb = (const float*)d_in[6];
    const float* wq         = (const float*)d_in[7];
    const float* wk         = (const float*)d_in[8];
    const float* wv         = (const float*)d_in[9];
    const float* proj_w     = (const float*)d_in[10];
    const float* proj_b     = (const float*)d_in[11];
    const float* ln1_s      = (const float*)d_in[12];
    const float* ln1_b      = (const float*)d_in[13];
    const float* ln2_s      = (const float*)d_in[14];
    const float* ln2_b      = (const float*)d_in[15];
    const float* ff_w1      = (const float*)d_in[16];
    const float* ff_b1      = (const float*)d_in[17];
    const float* ff_w2      = (const float*)d_in[18];
    const float* ff_b2      = (const float*)d_in[19];
    const float* hw1        = (const float*)d_in[20];
    const float* hb1        = (const float*)d_in[21];
    const float* hw2        = (const float*)d_in[22];
    const float* hb2        = (const float*)d_in[23];
    float* out = (float*)d_out;

    cudaFuncSetAttribute(tgemm,  cudaFuncAttributeMaxDynamicSharedMemorySize, TGSMEM);
    cudaFuncSetAttribute(qk_mma, cudaFuncAttributeMaxDynamicSharedMemorySize, QKSMEM);
    cudaFuncSetAttribute(pv_mma, cudaFuncAttributeMaxDynamicSharedMemorySize, PVSMEM);

    float *pPOS, *pX, *pS, *pZ;
    h16 *pH, *pO, *pF, *pXP, *pQ, *pP, *pVt;
    h16 *pWq, *pWp, *pW1, *pW2, *pWt;
    cudaGetSymbolAddress((void**)&pPOS, g_POS);
    cudaGetSymbolAddress((void**)&pX,   g_X);
    cudaGetSymbolAddress((void**)&pS,   g_S);
    cudaGetSymbolAddress((void**)&pZ,   g_Z);
    cudaGetSymbolAddress((void**)&pH,   g_H);
    cudaGetSymbolAddress((void**)&pO,   g_O);
    cudaGetSymbolAddress((void**)&pF,   g_F);
    cudaGetSymbolAddress((void**)&pXP,  g_XP);
    cudaGetSymbolAddress((void**)&pQ,   g_QKV);
    cudaGetSymbolAddress((void**)&pP,   g_P);
    cudaGetSymbolAddress((void**)&pVt,  g_Vt);
    cudaGetSymbolAddress((void**)&pWq,  g_Wqkv);
    cudaGetSymbolAddress((void**)&pWp,  g_Wprj);
    cudaGetSymbolAddress((void**)&pW1,  g_Wf1);
    cudaGetSymbolAddress((void**)&pW2,  g_Wf2);
    cudaGetSymbolAddress((void**)&pWt,  g_Wpat);

    // ---- prep (launch #4 = dummy QKV-shaped tgemm; ncu -s 5 -c 1 captures my 4th launch) ----
    pos_kernel    <<<CDIV(Tv*Ev, 256), 256>>>(pPOS);                                  // 1
    conv_wqkv     <<<dim3(2, 24, Lv*3*Hv), dim3(32,8)>>>(wq, wk, wv, pWq);            // 2
    transpose_conv<<<dim3(24, 24, Lv), dim3(32,8)>>>(proj_w, pWp, Ev, Ev);            // 3
    tgemm<<<dim3(QKVLD/128, 10), 256, TGSMEM>>>(                                       // 4 (profiling probe)
        2560, QKVLD, Ev, pXP, pWq,
        nullptr, nullptr, 0, 0, pS, QKVLD, 0, 0, nullptr);
    transpose_conv<<<dim3(96, 24, Lv), dim3(32,8)>>>(ff_w1, pW1, Ev, E4);             // 5
    transpose_conv<<<dim3(24, 96, Lv), dim3(32,8)>>>(ff_w2, pW2, E4, Ev);             // 6
    transpose_conv<<<dim3(24, 24, 1),  dim3(32,8)>>>(patch_w, pWt, Ev, Ev);
    gather_patches<<<CDIV(MPATCH*Ev, 256), 256>>>(images, goal_imgs, pXP);
    embed_txt_act <<<CDIV(Bv*33*Ev, 256), 256>>>(goals_txt, text_emb, action_emb, pPOS, pX);

    // patch embed -> X rows 32..619 (+bias +POS)
    tgemm<<<dim3(Ev/128, CDIV(MPATCH,256)), 256, TGSMEM>>>(
        MPATCH, Ev, Ev, pXP, pWt,
        patch_b, pPOS, Ev, 1,
        pX, Ev, 0, 0, nullptr);

    for (int l = 0; l < Lv; l++) {
        ln_kernel<<<MTv, 256>>>(pX, pH, ln1_s + l*Ev, ln1_b + l*Ev);

        tgemm<<<dim3(QKVLD/128, CDIV(MTv,256)), 256, TGSMEM>>>(   // QKV -> fp16
            MTv, QKVLD, Ev, pH, pWq + (size_t)l*QKVLD*Ev,
            nullptr, nullptr, 0, 0,
            nullptr, 0, 0, 0, pQ);

        qk_mma        <<<dim3(TP/128, TP/128, ZH), 256, QKSMEM>>>(pQ, pS);
        softmax_kernel<<<dim3(Tv, ZH), 256>>>(pS, pP);
        repack_v      <<<dim3(TP/32, HSv/32, ZH), dim3(32,8)>>>(pQ, pVt);
        pv_mma        <<<dim3(TP/128, ZH), 256, PVSMEM>>>(pP, pVt, pO);

        tgemm<<<dim3(Ev/128, CDIV(MTv,256)), 256, TGSMEM>>>(   // X += O @ proj + b
            MTv, Ev, Ev, pO, pWp + (size_t)l*Ev*Ev,
            proj_b + l*Ev, nullptr, 0, 0,
            pX, Ev, 1, 0, nullptr);

        ln_kernel<<<MTv, 256>>>(pX, pH, ln2_s + l*Ev, ln2_b + l*Ev);

        tgemm<<<dim3(E4/128, CDIV(MTv,256)), 256, TGSMEM>>>(   // F = relu(h@W1+b1) -> fp16
            MTv, E4, Ev, pH, pW1 + (size_t)l*E4*Ev,
            ff_b1 + l*E4, nullptr, 0, 0,
            nullptr, 0, 0, 1, pF);

        tgemm<<<dim3(Ev/128, CDIV(MTv,256)), 256, TGSMEM>>>(   // X += F @ W2 + b2
            MTv, Ev, E4, pF, pW2 + (size_t)l*Ev*E4,
            ff_b2 + l*Ev, nullptr, 0, 0,
            pX, Ev, 1, 0, nullptr);
    }

    // head
    sgemm128<<<dim3(Ev/128, 1), 256>>>(
        Bv, Ev, Ev, pX + (size_t)620*Ev, Tv*Ev, hw1, Ev, pZ, Ev, hb1, 1);
    sgemm128<<<dim3(1, 1), 256>>>(
        Bv, AOUTv, Ev, pZ, Ev, hw2, AOUTv, out, AOUTv, hb2, 0);

    (void)in_sizes; (void)n_in; (void)out_size;
}

// round 11
// speedup vs baseline: 3.0027x; 1.5454x over previous
#include <cuda_runtime.h>
#include <cuda_fp16.h>
#include <math.h>
#include <stdint.h>
#include <stddef.h>

// ---------------- problem constants ----------------
#define Bv      16
#define Kv      2
#define Ev      768
#define Hv      12
#define HSv     64
#define Lv      12
#define Tv      621
#define TP      640
#define NPATCH  588
#define QKVLD   2304
#define E4      3072
#define AOUTv   64
#define MTv     (Bv*Tv)      // 9936
#define MPATCH  (Bv*NPATCH)  // 9408
#define ZH      (Bv*Hv)      // 192
#define SCALE_QK 0.036084391824351615f

#define CDIV(a,b) (((a)+(b)-1)/(b))
#define TGSMEM   147456      // 3 stages x 48KB (A 32K + B 16K)
#define QKSMEM   32768
#define PVSMEM   36864       // 3 stages x 12KB

typedef __half h16;

// ---------------- scratch ----------------
__device__ __align__(128) float g_POS[Tv*Ev];
__device__ __align__(128) float g_X  [(size_t)MTv*Ev];
__device__ __align__(128) float g_Z  [Bv*Ev];

__device__ __align__(128) h16 g_S  [(size_t)ZH*TP*TP];   // fp16 scores (probe dumps floats here too)
__device__ __align__(128) h16 g_H  [(size_t)MTv*Ev];
__device__ __align__(128) h16 g_O  [(size_t)MTv*Ev];
__device__ __align__(128) h16 g_F  [(size_t)MTv*E4];
__device__ __align__(128) h16 g_XP [(size_t)MPATCH*Ev];
__device__ __align__(128) h16 g_QKV[(size_t)MTv*QKVLD];
__device__ __align__(128) h16 g_P  [(size_t)ZH*TP*TP];
__device__ __align__(128) h16 g_Vt [(size_t)ZH*HSv*TP];

__device__ __align__(128) h16 g_Wqkv[(size_t)Lv*QKVLD*Ev];
__device__ __align__(128) h16 g_Wprj[(size_t)Lv*Ev*Ev];
__device__ __align__(128) h16 g_Wf1 [(size_t)Lv*E4*Ev];
__device__ __align__(128) h16 g_Wf2 [(size_t)Lv*Ev*E4];
__device__ __align__(128) h16 g_Wpat[(size_t)Ev*Ev];

// ---------------- mask-derived tile lists ----------------
// qk: 19 live (t-tile, s-tile) pairs of 25
__constant__ int c_qkT[19] = {0, 1,1,1,1, 2,2,2,2, 3,3,3,3,3, 4,4,4,4,4};
__constant__ int c_qkS[19] = {0, 0,1,2,3, 0,1,2,3, 0,1,2,3,4, 0,1,2,3,4};
// pv: per t-tile, K-chunk ranges [lo1,hi1) + [lo2,hi2)  (P==0 outside)
__constant__ int c_pvLo1[5] = {0,0,0,0,0};
__constant__ int c_pvHi1[5] = {4,1,1,1,1};
__constant__ int c_pvLo2[5] = {4,4,7,7,7};
__constant__ int c_pvHi2[5] = {4,14,14,20,20};

// ---------------- helpers ----------------
__device__ __forceinline__ uint32_t smem_u32(const void* p) {
    uint32_t a;
    asm("{ .reg .u64 t; cvta.to.shared.u64 t, %1; cvt.u32.u64 %0, t; }" : "=r"(a) : "l"(p));
    return a;
}
__device__ __forceinline__ void cp16(uint32_t sa, const void* ga, bool v) {
    int sz = v ? 16 : 0;
    asm volatile("cp.async.cg.shared.global [%0], [%1], 16, %2;" :: "r"(sa), "l"(ga), "r"(sz) : "memory");
}
#define CP_COMMIT() asm volatile("cp.async.commit_group;" ::: "memory")
#define CP_WAIT0()  asm volatile("cp.async.wait_group 0;" ::: "memory")
#define CP_WAIT1()  asm volatile("cp.async.wait_group 1;" ::: "memory")

#define LDSM4(r, a) \
    asm volatile("ldmatrix.sync.aligned.m8n8.x4.shared.b16 {%0,%1,%2,%3}, [%4];" \
        : "=r"((r)[0]),"=r"((r)[1]),"=r"((r)[2]),"=r"((r)[3]) : "r"(a))

__device__ __forceinline__ void mma16816(float* d, const uint32_t* a, const uint32_t* b) {
    asm volatile("mma.sync.aligned.m16n8k16.row.col.f32.f16.f16.f32 "
        "{%0,%1,%2,%3}, {%4,%5,%6,%7}, {%8,%9}, {%0,%1,%2,%3};"
        : "+f"(d[0]),"+f"(d[1]),"+f"(d[2]),"+f"(d[3])
        : "r"(a[0]),"r"(a[1]),"r"(a[2]),"r"(a[3]), "r"(b[0]),"r"(b[1]));
}

// ---------------- mask ----------------
__device__ __forceinline__ bool keep_fn(int t, int s) {
    bool v = (t == s);
    if (s < 32) v = !(t >= 32 && t < 228);
    if (t >= 228 && s >= 228 && s < 424) v = true;
    if (t >= 424 && s >= 424 && s < 620) v = true;
    return v;
}

// ---------------- positional embedding ----------------
__global__ void pos_kernel(float* POS) {
    int idx = blockIdx.x * 256 + threadIdx.x;
    if (idx >= Tv * Ev) return;
    int t = idx / Ev, j = idx % Ev;
    double expo = (double)(j & ~1) / (double)Ev;
    double ang  = (double)t / pow(10000.0, expo);
    POS[idx] = (float)((j & 1) ? cos(ang) : sin(ang));
}

// ---------------- transpose+convert weights ----------------
__global__ void transpose_conv(const float* __restrict__ src, h16* __restrict__ dst, int R, int C) {
    __shared__ float t[32][33];
    int z = blockIdx.z;
    src += (size_t)z * R * C; dst += (size_t)z * R * C;
    int c0 = blockIdx.x * 32, r0 = blockIdx.y * 32;
    int tx = threadIdx.x, ty = threadIdx.y;
    #pragma unroll
    for (int i = 0; i < 4; i++)
        t[ty + 8*i][tx] = src[(size_t)(r0 + ty + 8*i) * C + c0 + tx];
    __syncthreads();
    #pragma unroll
    for (int i = 0; i < 4; i++)
        dst[(size_t)(c0 + ty + 8*i) * R + r0 + tx] = __float2half(t[tx][ty + 8*i]);
}

__global__ void conv_wqkv(const float* __restrict__ wq, const float* __restrict__ wk,
                          const float* __restrict__ wv, h16* __restrict__ dst) {
    __shared__ float t[32][33];
    int z = blockIdx.z;
    int h = z % Hv, which = (z / Hv) % 3, l = z / (3 * Hv);
    const float* src = (which == 0) ? wq : (which == 1) ? wk : wv;
    src += ((size_t)l * Hv + h) * Ev * HSv;
    int d0 = blockIdx.x * 32, e0 = blockIdx.y * 32;
    int tx = threadIdx.x, ty = threadIdx.y;
    #pragma unroll
    for (int i = 0; i < 4; i++)
        t[ty + 8*i][tx] = src[(size_t)(e0 + ty + 8*i) * HSv + d0 + tx];
    __syncthreads();
    #pragma unroll
    for (int i = 0; i < 4; i++) {
        int d = d0 + ty + 8*i, e = e0 + tx;
        dst[((size_t)l * QKVLD + which * Ev + h * HSv + d) * Ev + e] = __float2half(t[tx][ty + 8*i]);
    }
}

// ---------------- gather patches -> fp16 ----------------
__global__ void gather_patches(const float* __restrict__ images, const float* __restrict__ goal_imgs,
                               h16* __restrict__ X) {
    int idx = blockIdx.x * 256 + threadIdx.x;
    if (idx >= MPATCH * Ev) return;
    int f = idx % Ev;
    int r = idx / Ev;
    int p = r % NPATCH;
    int b = r / NPATCH;
    int py = f / 48, px = (f % 48) / 3, c = f % 3;
    float val;
    if (p < 196) {
        int pr = p / 14, pc = p % 14;
        int y = pr * 16 + py, x = pc * 16 + px;
        val = goal_imgs[(((size_t)b * 224 + y) * 224 + x) * 3 + c];
    } else {
        int q = p - 196;
        int k = q / 196, pp = q % 196;
        int pr = pp / 14, pc = pp % 14;
        int y = pr * 16 + py, x = pc * 16 + px;
        val = images[((((size_t)b * Kv + k) * 224 + y) * 224 + x) * 3 + c];
    }
    X[idx] = __float2half(val);
}

// ---------------- text + action embed (+POS) ----------------
__global__ void embed_txt_act(const int* __restrict__ goals_txt, const float* __restrict__ text_emb,
                              const float* __restrict__ action_emb, const float* __restrict__ POS,
                              float* __restrict__ X) {
    int idx = blockIdx.x * 256 + threadIdx.x;
    if (idx >= Bv * 33 * Ev) return;
    int e  = idx % Ev;
    int r  = idx / Ev;
    int tt = r % 33;
    int b  = r / 33;
    int t  = (tt < 32) ? tt : 620;
    float v = (tt < 32) ? text_emb[(size_t)goals_txt[b * 32 + tt] * Ev + e] : action_emb[e];
    X[((size_t)b * Tv + t) * Ev + e] = v + POS[(size_t)t * Ev + e];
}

// ---------------- layernorm: warp per row, shuffle reduce -> fp16 ----------------
__global__ void ln_kernel(const float* __restrict__ X, h16* __restrict__ Out,
                          const float* __restrict__ sc, const float* __restrict__ bi) {
    int w = threadIdx.x >> 5, lane = threadIdx.x & 31;
    int row = blockIdx.x * 8 + w;
    if (row >= MTv) return;
    const float* x = X + (size_t)row * Ev;
    float4 v[6];
    float s = 0.f, ss = 0.f;
    #pragma unroll
    for (int i = 0; i < 6; i++) {
        v[i] = *(const float4*)(x + i * 128 + lane * 4);
        s  += v[i].x + v[i].y + v[i].z + v[i].w;
        ss += v[i].x*v[i].x + v[i].y*v[i].y + v[i].z*v[i].z + v[i].w*v[i].w;
    }
    #pragma unroll
    for (int off = 16; off; off >>= 1) {
        s  += __shfl_xor_sync(0xffffffff, s,  off);
        ss += __shfl_xor_sync(0xffffffff, ss, off);
    }
    float m   = s * (1.f / Ev);
    float var = ss * (1.f / Ev) - m * m;
    float inv = rsqrtf(var + 1e-5f);
    #pragma unroll
    for (int i = 0; i < 6; i++) {
        int col = i * 128 + lane * 4;
        float o0 = (v[i].x - m) * inv * sc[col]   + bi[col];
        float o1 = (v[i].y - m) * inv * sc[col+1] + bi[col+1];
        float o2 = (v[i].z - m) * inv * sc[col+2] + bi[col+2];
        float o3 = (v[i].w - m) * inv * sc[col+3] + bi[col+3];
        __half2 h0 = __floats2half2_rn(o0, o1);
        __half2 h1 = __floats2half2_rn(o2, o3);
        uint2 u = make_uint2(*(uint32_t*)&h0, *(uint32_t*)&h1);
        *(uint2*)(Out + (size_t)row * Ev + col) = u;
    }
}

// =====================================================================
// fp16 GEMM (mma.sync m16n8k16), 256x128 CTA tile, 256 threads,
// warp tile 64x64, Kc=64, 3-stage cp.async pipeline.
// =====================================================================
__global__ void __launch_bounds__(256, 1)
tgemm(int M, int N, int K,
      const h16* __restrict__ A, const h16* __restrict__ B,
      const float* __restrict__ bias,
      const float* __restrict__ rowmat, int ldrm, int rmode,
      float* outF, int ldo, int accf, int reluf,
      h16* outH)
{
    extern __shared__ char sm[];
    uint32_t sbase = smem_u32(sm);
    int tid = threadIdx.x, lane = tid & 31, wid = tid >> 5;
    int m0 = blockIdx.y * 256, n0 = blockIdx.x * 128;
    int wm = wid & 3, wn = wid >> 2;

    float acc[4][8][4];
    #pragma unroll
    for (int i = 0; i < 4; i++)
        #pragma unroll
        for (int j = 0; j < 8; j++)
            #pragma unroll
            for (int q = 0; q < 4; q++) acc[i][j][q] = 0.f;

    int nc = K >> 6;

    auto ld_st = [&](int c, int st, bool active) {
        if (active) {
            uint32_t sb = sbase + st * 49152;
            int k0 = c * 64;
            #pragma unroll
            for (int i = 0; i < 8; i++) {
                int u = i * 256 + tid;
                int row = u >> 3, seg = u & 7;
                uint32_t off = (uint32_t)(row * 128 + ((seg ^ (row & 7)) << 4));
                bool av = (m0 + row) < M;
                size_t ao = (size_t)(av ? (m0 + row) : 0) * K + k0 + seg * 8;
                cp16(sb + off, A + ao, av);
            }
            #pragma unroll
            for (int i = 0; i < 4; i++) {
                int u = i * 256 + tid;
                int row = u >> 3, seg = u & 7;
                uint32_t off = (uint32_t)(row * 128 + ((seg ^ (row & 7)) << 4));
                size_t bo = (size_t)(n0 + row) * K + k0 + seg * 8;
                cp16(sb + 32768 + off, B + bo, true);
            }
        }
        CP_COMMIT();
    };

    ld_st(0, 0, true);
    ld_st(1, 1, 1 < nc);

    int matA = lane >> 3;
    int matB = lane >> 3;

    for (int c = 0; c < nc; c++) {
        CP_WAIT1();
        __syncthreads();

        int st = c % 3;
        uint32_t sA = sbase + st * 49152;
        uint32_t sB = sA + 32768;

        #pragma unroll
        for (int ks = 0; ks < 4; ks++) {
            uint32_t bf[4][4];
            #pragma unroll
            for (int np = 0; np < 4; np++) {
                int brow = wn * 64 + np * 16 + ((matB >> 1) << 3) + (lane & 7);
                int bseg = ks * 2 + (matB & 1);
                uint32_t boff = (uint32_t)(brow * 128 + ((bseg ^ (brow & 7)) << 4));
                LDSM4(bf[np], sB + boff);
            }
            uint32_t af[2][4];
            {
                int arow = wm * 64 + (lane & 7) + (matA & 1) * 8;
                int aseg = ks * 2 + (matA >> 1);
                uint32_t aoff = (uint32_t)(arow * 128 + ((aseg ^ (arow & 7)) << 4));
                LDSM4(af[0], sA + aoff);
            }
            #pragma unroll
            for (int mt = 0; mt < 4; mt++) {
                int cur = mt & 1, nxt = cur ^ 1;
                if (mt < 3) {
                    int arow = wm * 64 + (mt + 1) * 16 + (lane & 7) + (matA & 1) * 8;
                    int aseg = ks * 2 + (matA >> 1);
                    uint32_t aoff = (uint32_t)(arow * 128 + ((aseg ^ (arow & 7)) << 4));
                    LDSM4(af[nxt], sA + aoff);
                }
                #pragma unroll
                for (int np = 0; np < 4; np++)
                    #pragma unroll
                    for (int t = 0; t < 2; t++)
                        mma16816(acc[mt][np * 2 + t], af[cur], bf[np] + 2 * t);
            }
        }
        ld_st(c + 2, (c + 2) % 3, c + 2 < nc);
    }

    int r_l = lane >> 2, c_l = (lane & 3) * 2;
    #pragma unroll
    for (int mt = 0; mt < 4; mt++) {
        #pragma unroll
        for (int h = 0; h < 2; h++) {
            int rr = m0 + wm * 64 + mt * 16 + h * 8 + r_l;
            if (rr >= M) continue;
            int orow = rr, prow = rr;
            if (rmode) {
                int b = rr / NPATCH, p = rr - b * NPATCH;
                orow = b * Tv + 32 + p;
                prow = 32 + p;
            }
            #pragma unroll
            for (int j = 0; j < 8; j++) {
                int col = n0 + wn * 64 + j * 8 + c_l;
                float v0 = acc[mt][j][2 * h];
                float v1 = acc[mt][j][2 * h + 1];
                if (bias)   { v0 += bias[col]; v1 += bias[col + 1]; }
                if (rowmat) { const float* rp = rowmat + (size_t)prow * ldrm + col; v0 += rp[0]; v1 += rp[1]; }
                if (accf)   { const float* op = outF + (size_t)orow * ldo + col;   v0 += op[0]; v1 += op[1]; }
                if (reluf)  { v0 = fmaxf(v0, 0.f); v1 = fmaxf(v1, 0.f); }
                if (outF)   *(float2*)(outF + (size_t)orow * ldo + col) = make_float2(v0, v1);
                if (outH) {
                    size_t o = (size_t)rr * N + col;
                    __half2 hv = __floats2half2_rn(v0, v1);
                    *(__half2*)(outH + o) = hv;
                }
            }
        }
    }
}

// =====================================================================
// qk_mma: S[z][t][s] = (Q K^T)*scale ; live 128x128 tiles only, fp16 out
// =====================================================================
__global__ void __launch_bounds__(256, 2)
qk_mma(const h16* __restrict__ Q, h16* __restrict__ S)
{
    extern __shared__ char sm[];
    uint32_t sbase = smem_u32(sm);     // +0 Q (16K), +16K K (16K)
    int tid = threadIdx.x, lane = tid & 31, wid = tid >> 5;
    int z = blockIdx.y, b = z / Hv, h = z % Hv;
    int t0 = c_qkT[blockIdx.x] * 128, s0 = c_qkS[blockIdx.x] * 128;

    #pragma unroll
    for (int i = 0; i < 4; i++) {
        int u = i * 256 + tid;
        int row = u >> 3, seg = u & 7;
        uint32_t off = (uint32_t)(row * 128 + ((seg ^ (row & 7)) << 4));
        bool qv = (t0 + row) < Tv;
        bool kv = (s0 + row) < Tv;
        size_t qo = (size_t)(b * Tv + (qv ? t0 + row : 0)) * QKVLD + h * HSv + seg * 8;
        size_t ko = (size_t)(b * Tv + (kv ? s0 + row : 0)) * QKVLD + Ev + h * HSv + seg * 8;
        cp16(sbase + off,         Q + qo, qv);
        cp16(sbase + 16384 + off, Q + ko, kv);
    }
    CP_COMMIT();
    CP_WAIT0();
    __syncthreads();

    int wm = wid & 3, wn = wid >> 2;
    float acc[2][8][4];
    #pragma unroll
    for (int i = 0; i < 2; i++)
        #pragma unroll
        for (int j = 0; j < 8; j++)
            #pragma unroll
            for (int q = 0; q < 4; q++) acc[i][j][q] = 0.f;

    #pragma unroll
    for (int ks = 0; ks < 4; ks++) {
        uint32_t af[2][4];
        #pragma unroll
        for (int mt = 0; mt < 2; mt++) {
            int matA = lane >> 3;
            int arow = wm * 32 + mt * 16 + (lane & 7) + (matA & 1) * 8;
            int aseg = ks * 2 + (matA >> 1);
            uint32_t off = (uint32_t)(arow * 128 + ((aseg ^ (arow & 7)) << 4));
            LDSM4(af[mt], sbase + off);
        }
        #pragma unroll
        for (int np = 0; np < 4; np++) {
            uint32_t bf[4];
            int matB = lane >> 3;
            int brow = wn * 64 + np * 16 + ((matB >> 1) << 3) + (lane & 7);
            int bseg = ks * 2 + (matB & 1);
            uint32_t boff = (uint32_t)(brow * 128 + ((bseg ^ (brow & 7)) << 4));
            LDSM4(bf, sbase + 16384 + boff);
            #pragma unroll
            for (int t = 0; t < 2; t++)
                #pragma unroll
                for (int mt = 0; mt < 2; mt++)
                    mma16816(acc[mt][np * 2 + t], af[mt], bf + 2 * t);
        }
    }

    int r_l = lane >> 2, c_l = (lane & 3) * 2;
    #pragma unroll
    for (int mt = 0; mt < 2; mt++)
        #pragma unroll
        for (int h2 = 0; h2 < 2; h2++) {
            int rr = t0 + wm * 32 + mt * 16 + h2 * 8 + r_l;
            #pragma unroll
            for (int j = 0; j < 8; j++) {
                int col = s0 + wn * 64 + j * 8 + c_l;
                __half2 hv = __floats2half2_rn(acc[mt][j][2 * h2] * SCALE_QK,
                                               acc[mt][j][2 * h2 + 1] * SCALE_QK);
                *(__half2*)(S + ((size_t)z * TP + rr) * TP + col) = hv;
            }
        }
}

// ---------------- masked softmax: warp per row, fp16 in/out ----------------
__global__ void softmax_kernel(const h16* __restrict__ S, h16* __restrict__ P)
{
    int gid = blockIdx.x * 8 + (threadIdx.x >> 5);
    if (gid >= Tv * ZH) return;
    int z = gid / Tv, t = gid - z * Tv;
    const h16* row = S + ((size_t)z * TP + t) * TP;
    h16* ph = P + ((size_t)z * TP + t) * TP;
    int lane = threadIdx.x & 31;
    float v[20];
    float mx = -3.0e38f;
    #pragma unroll
    for (int i = 0; i < 20; i++) {
        int s = lane + i * 32;
        float val = __half2float(row[s]);
        v[i] = keep_fn(t, s) ? val : -3.0e38f;
        mx = fmaxf(mx, v[i]);
    }
    #pragma unroll
    for (int off = 16; off; off >>= 1)
        mx = fmaxf(mx, __shfl_xor_sync(0xffffffff, mx, off));
    float sum = 0.f;
    #pragma unroll
    for (int i = 0; i < 20; i++) {
        v[i] = (v[i] > -1.0e38f) ? expf(v[i] - mx) : 0.f;
        sum += v[i];
    }
    #pragma unroll
    for (int off = 16; off; off >>= 1)
        sum += __shfl_xor_sync(0xffffffff, sum, off);
    float inv = 1.f / sum;
    #pragma unroll
    for (int i = 0; i < 20; i++)
        ph[lane + i * 32] = __float2half(v[i] * inv);
}

// ---------------- V repack: QKV v-part -> Vt[z][d][s] fp16 (s padded 0) ----------------
__global__ void repack_v(const h16* __restrict__ Q, h16* __restrict__ Vt)
{
    __shared__ h16 th[32][33];
    int z = blockIdx.z, b = z / Hv, h = z % Hv;
    int s0 = blockIdx.x * 32, d0 = blockIdx.y * 32;
    int tx = threadIdx.x, ty = threadIdx.y;
    #pragma unroll
    for (int i = 0; i < 4; i++) {
        int s = s0 + ty + 8 * i;
        h16 vh = __float2half(0.f);
        if (s < Tv)
            vh = Q[(size_t)(b * Tv + s) * QKVLD + 2 * Ev + h * HSv + d0 + tx];
        th[ty + 8 * i][tx] = vh;
    }
    __syncthreads();
    #pragma unroll
    for (int i = 0; i < 4; i++)
        Vt[((size_t)z * HSv + d0 + ty + 8 * i) * TP + s0 + tx] = th[tx][ty + 8 * i];
}

// =====================================================================
// pv_mma: O[z][t][d] = P @ V^T-layout ; tile 128x64, Kc=32, mask-pruned
// chunk list per t-tile, 3-stage pipeline, fp16
// =====================================================================
__global__ void __launch_bounds__(256, 2)
pv_mma(const h16* __restrict__ P, const h16* __restrict__ Vt, h16* __restrict__ O)
{
    extern __shared__ char sm[];
    uint32_t sbase = smem_u32(sm);
    int tid = threadIdx.x, lane = tid & 31, wid = tid >> 5;
    int z = blockIdx.y, b = z / Hv, h = z % Hv;
    int tt = blockIdx.x;
    int t0 = tt * 128;
    int wm = wid & 3, wn = wid >> 2;

    int n1 = c_pvHi1[tt] - c_pvLo1[tt];
    int nch = n1 + (c_pvHi2[tt] - c_pvLo2[tt]);
    int lo1 = c_pvLo1[tt], lo2 = c_pvLo2[tt];
    auto chunk_of = [&](int i) { return (i < n1) ? lo1 + i : lo2 + (i - n1); };

    float acc[2][4][4];
    #pragma unroll
    for (int i = 0; i < 2; i++)
        #pragma unroll
        for (int j = 0; j < 4; j++)
            #pragma unroll
            for (int q = 0; q < 4; q++) acc[i][j][q] = 0.f;

    auto ld_st = [&](int c, int st, bool active) {
        if (active) {
            uint32_t sb = sbase + st * 12288;
            int k0 = c * 32;
            {
                int u = tid;
                int row = u >> 1, seg0 = (u & 1) * 2;
                #pragma unroll
                for (int q = 0; q < 2; q++) {
                    int seg = seg0 + q;
                    uint32_t off = (uint32_t)(row * 64 + ((seg ^ ((row >> 1) & 3)) << 4));
                    size_t po = ((size_t)z * TP + t0 + row) * TP + k0 + seg * 8;
                    cp16(sb + off, P + po, true);
                }
            }
            {
                int row = tid >> 2, seg = tid & 3;
                uint32_t off = (uint32_t)(row * 64 + ((seg ^ ((row >> 1) & 3)) << 4));
                size_t vo = ((size_t)z * HSv + row) * TP + k0 + seg * 8;
                cp16(sb + 8192 + off, Vt + vo, true);
            }
        }
        CP_COMMIT();
    };

    ld_st(chunk_of(0), 0, true);
    ld_st(1 < nch ? chunk_of(1) : 0, 1, 1 < nch);

    for (int i = 0; i < nch; i++) {
        CP_WAIT1();
        __syncthreads();

        int st = i % 3;
        uint32_t sP = sbase + st * 12288;
        uint32_t sV = sP + 8192;

        #pragma unroll
        for (int ks = 0; ks < 2; ks++) {
            uint32_t af[2][4];
            #pragma unroll
            for (int mt = 0; mt < 2; mt++) {
                int matA = lane >> 3;
                int arow = wm * 32 + mt * 16 + (lane & 7) + (matA & 1) * 8;
                int aseg = ks * 2 + (matA >> 1);
                uint32_t off = (uint32_t)(arow * 64 + ((aseg ^ ((arow >> 1) & 3)) << 4));
                LDSM4(af[mt], sP + off);
            }
            #pragma unroll
            for (int np = 0; np < 2; np++) {
                uint32_t bf[4];
                int matB = lane >> 3;
                int brow = wn * 32 + np * 16 + ((matB >> 1) << 3) + (lane & 7);
                int bseg = ks * 2 + (matB & 1);
                uint32_t boff = (uint32_t)(brow * 64 + ((bseg ^ ((brow >> 1) & 3)) << 4));
                LDSM4(bf, sV + boff);
                #pragma unroll
                for (int t = 0; t < 2; t++)
                    #pragma unroll
                    for (int mt = 0; mt < 2; mt++)
                        mma16816(acc[mt][np * 2 + t], af[mt], bf + 2 * t);
            }
        }
        ld_st(i + 2 < nch ? chunk_of(i + 2) : 0, (i + 2) % 3, i + 2 < nch);
    }

    int r_l = lane >> 2, c_l = (lane & 3) * 2;
    #pragma unroll
    for (int mt = 0; mt < 2; mt++)
        #pragma unroll
        for (int h2 = 0; h2 < 2; h2++) {
            int rr = t0 + wm * 32 + mt * 16 + h2 * 8 + r_l;
            if (rr >= Tv) continue;
            #pragma unroll
            for (int j = 0; j < 4; j++) {
                int col = wn * 32 + j * 8 + c_l;
                size_t o = ((size_t)(b * Tv + rr)) * Ev + h * HSv + col;
                __half2 hv = __floats2half2_rn(acc[mt][j][2 * h2], acc[mt][j][2 * h2 + 1]);
                *(__half2*)(O + o) = hv;
            }
        }
}

// ---------------- fp32 GEMM (head only) ----------------
__global__ void __launch_bounds__(256, 2)
sgemm128(int M, int N, int K,
         const float* __restrict__ A, int lda,
         const float* __restrict__ B, int ldb,
         float* __restrict__ C, int ldc,
         const float* __restrict__ bias, int reluflag)
{
    __shared__ __align__(16) float As[8][128];
    __shared__ __align__(16) float Bs[8][128];
    int n0 = blockIdx.x * 128, m0 = blockIdx.y * 128;
    int tid = threadIdx.x;
    int tx = tid & 15, ty = tid >> 4;
    int arow = tid >> 1,  akk  = (tid & 1) * 4;
    int bkk  = tid >> 5,  bcol = (tid & 31) * 4;
    bool aval = (m0 + arow) < M;
    bool bval = (n0 + bcol) < N;
    const float* Aptr = A + (size_t)(m0 + arow) * lda + akk;
    const float* Bptr = B + (size_t)bkk * ldb + n0 + bcol;
    float acc[8][8];
    #pragma unroll
    for (int i = 0; i < 8; i++)
        #pragma unroll
        for (int j = 0; j < 8; j++) acc[i][j] = 0.f;
    for (int k0 = 0; k0 < K; k0 += 8) {
        float4 av = make_float4(0.f,0.f,0.f,0.f), bv = make_float4(0.f,0.f,0.f,0.f);
        if (aval) av = *(const float4*)(Aptr + k0);
        if (bval) bv = *(const float4*)(Bptr + (size_t)k0 * ldb);
        __syncthreads();
        As[akk+0][arow] = av.x; As[akk+1][arow] = av.y;
        As[akk+2][arow] = av.z; As[akk+3][arow] = av.w;
        *(float4*)&Bs[bkk][bcol] = bv;
        __syncthreads();
        #pragma unroll
        for (int kk = 0; kk < 8; kk++) {
            float a[8], b2[8];
            *(float4*)(a)    = *(const float4*)&As[kk][ty*8];
            *(float4*)(a+4)  = *(const float4*)&As[kk][ty*8+4];
            *(float4*)(b2)   = *(const float4*)&Bs[kk][tx*8];
            *(float4*)(b2+4) = *(const float4*)&Bs[kk][tx*8+4];
            #pragma unroll
            for (int i = 0; i < 8; i++)
                #pragma unroll
                for (int j = 0; j < 8; j++)
                    acc[i][j] += a[i] * b2[j];
        }
    }
    #pragma unroll
    for (int i = 0; i < 8; i++) {
        int r = m0 + ty*8 + i;
        if (r >= M) continue;
        #pragma unroll
        for (int j = 0; j < 8; j++) {
            int c = n0 + tx*8 + j;
            if (c >= N) continue;
            float v = acc[i][j];
            if (bias) v += bias[c];
            if (reluflag) v = fmaxf(v, 0.f);
            C[(size_t)r * ldc + c] = v;
        }
    }
}

// ---------------- launch ----------------
extern "C" void kernel_launch(void* const* d_in, const int* in_sizes, int n_in,
                              void* d_out, int out_size) {
    const float* images     = (const float*)d_in[0];
    const int*   goals_txt  = (const int*)  d_in[1];
    const float* goal_imgs  = (const float*)d_in[2];
    const float* patch_w    = (const float*)d_in[3];
    const float* patch_b    = (const float*)d_in[4];
    const float* text_emb   = (const float*)d_in[5];
    const float* action_emb = (const float*)d_in[6];
    const float* wq         = (const float*)d_in[7];
    const float* wk         = (const float*)d_in[8];
    const float* wv         = (const float*)d_in[9];
    const float* proj_w     = (const float*)d_in[10];
    const float* proj_b     = (const float*)d_in[11];
    const float* ln1_s      = (const float*)d_in[12];
    const float* ln1_b      = (const float*)d_in[13];
    const float* ln2_s      = (const float*)d_in[14];
    const float* ln2_b      = (const float*)d_in[15];
    const float* ff_w1      = (const float*)d_in[16];
    const float* ff_b1      = (const float*)d_in[17];
    const float* ff_w2      = (const float*)d_in[18];
    const float* ff_b2      = (const float*)d_in[19];
    const float* hw1        = (const float*)d_in[20];
    const float* hb1        = (const float*)d_in[21];
    const float* hw2        = (const float*)d_in[22];
    const float* hb2        = (const float*)d_in[23];
    float* out = (float*)d_out;

    cudaFuncSetAttribute(tgemm,  cudaFuncAttributeMaxDynamicSharedMemorySize, TGSMEM);
    cudaFuncSetAttribute(qk_mma, cudaFuncAttributeMaxDynamicSharedMemorySize, QKSMEM);
    cudaFuncSetAttribute(pv_mma, cudaFuncAttributeMaxDynamicSharedMemorySize, PVSMEM);

    float *pPOS, *pX, *pZ;
    h16 *pS, *pH, *pO, *pF, *pXP, *pQ, *pP, *pVt;
    h16 *pWq, *pWp, *pW1, *pW2, *pWt;
    cudaGetSymbolAddress((void**)&pPOS, g_POS);
    cudaGetSymbolAddress((void**)&pX,   g_X);
    cudaGetSymbolAddress((void**)&pZ,   g_Z);
    cudaGetSymbolAddress((void**)&pS,   g_S);
    cudaGetSymbolAddress((void**)&pH,   g_H);
    cudaGetSymbolAddress((void**)&pO,   g_O);
    cudaGetSymbolAddress((void**)&pF,   g_F);
    cudaGetSymbolAddress((void**)&pXP,  g_XP);
    cudaGetSymbolAddress((void**)&pQ,   g_QKV);
    cudaGetSymbolAddress((void**)&pP,   g_P);
    cudaGetSymbolAddress((void**)&pVt,  g_Vt);
    cudaGetSymbolAddress((void**)&pWq,  g_Wqkv);
    cudaGetSymbolAddress((void**)&pWp,  g_Wprj);
    cudaGetSymbolAddress((void**)&pW1,  g_Wf1);
    cudaGetSymbolAddress((void**)&pW2,  g_Wf2);
    cudaGetSymbolAddress((void**)&pWt,  g_Wpat);

    // ---- prep (launch #4 = dummy QKV-shaped tgemm probe for ncu -s 5 -c 1) ----
    pos_kernel    <<<CDIV(Tv*Ev, 256), 256>>>(pPOS);                                  // 1
    conv_wqkv     <<<dim3(2, 24, Lv*3*Hv), dim3(32,8)>>>(wq, wk, wv, pWq);            // 2
    transpose_conv<<<dim3(24, 24, Lv), dim3(32,8)>>>(proj_w, pWp, Ev, Ev);            // 3
    tgemm<<<dim3(QKVLD/128, 10), 256, TGSMEM>>>(                                       // 4 (probe)
        2560, QKVLD, Ev, pXP, pWq,
        nullptr, nullptr, 0, 0, (float*)pS, QKVLD, 0, 0, nullptr);
    transpose_conv<<<dim3(96, 24, Lv), dim3(32,8)>>>(ff_w1, pW1, Ev, E4);             // 5
    transpose_conv<<<dim3(24, 96, Lv), dim3(32,8)>>>(ff_w2, pW2, E4, Ev);             // 6
    transpose_conv<<<dim3(24, 24, 1),  dim3(32,8)>>>(patch_w, pWt, Ev, Ev);
    gather_patches<<<CDIV(MPATCH*Ev, 256), 256>>>(images, goal_imgs, pXP);
    embed_txt_act <<<CDIV(Bv*33*Ev, 256), 256>>>(goals_txt, text_emb, action_emb, pPOS, pX);

    // patch embed -> X rows 32..619 (+bias +POS)
    tgemm<<<dim3(Ev/128, CDIV(MPATCH,256)), 256, TGSMEM>>>(
        MPATCH, Ev, Ev, pXP, pWt,
        patch_b, pPOS, Ev, 1,
        pX, Ev, 0, 0, nullptr);

    for (int l = 0; l < Lv; l++) {
        ln_kernel<<<CDIV(MTv,8), 256>>>(pX, pH, ln1_s + l*Ev, ln1_b + l*Ev);

        tgemm<<<dim3(QKVLD/128, CDIV(MTv,256)), 256, TGSMEM>>>(   // QKV -> fp16
            MTv, QKVLD, Ev, pH, pWq + (size_t)l*QKVLD*Ev,
            nullptr, nullptr, 0, 0,
            nullptr, 0, 0, 0, pQ);

        qk_mma        <<<dim3(19, ZH), 256, QKSMEM>>>(pQ, pS);
        softmax_kernel<<<CDIV(Tv*ZH,8), 256>>>(pS, pP);
        repack_v      <<<dim3(TP/32, HSv/32, ZH), dim3(32,8)>>>(pQ, pVt);
        pv_mma        <<<dim3(TP/128, ZH), 256, PVSMEM>>>(pP, pVt, pO);

        tgemm<<<dim3(Ev/128, CDIV(MTv,256)), 256, TGSMEM>>>(   // X += O @ proj + b
            MTv, Ev, Ev, pO, pWp + (size_t)l*Ev*Ev,
            proj_b + l*Ev, nullptr, 0, 0,
            pX, Ev, 1, 0, nullptr);

        ln_kernel<<<CDIV(MTv,8), 256>>>(pX, pH, ln2_s + l*Ev, ln2_b + l*Ev);

        tgemm<<<dim3(E4/128, CDIV(MTv,256)), 256, TGSMEM>>>(   // F = relu(h@W1+b1) -> fp16
            MTv, E4, Ev, pH, pW1 + (size_t)l*E4*Ev,
            ff_b1 + l*E4, nullptr, 0, 0,
            nullptr, 0, 0, 1, pF);

        tgemm<<<dim3(Ev/128, CDIV(MTv,256)), 256, TGSMEM>>>(   // X += F @ W2 + b2
            MTv, Ev, E4, pF, pW2 + (size_t)l*Ev*E4,
            ff_b2 + l*Ev, nullptr, 0, 0,
            pX, Ev, 1, 0, nullptr);
    }

    // head
    sgemm128<<<dim3(Ev/128, 1), 256>>>(
        Bv, Ev, Ev, pX + (size_t)620*Ev, Tv*Ev, hw1, Ev, pZ, Ev, hb1, 1);
    sgemm128<<<dim3(1, 1), 256>>>(
        Bv, AOUTv, Ev, pZ, Ev, hw2, AOUTv, out, AOUTv, hb2, 0);

    (void)in_sizes; (void)n_in; (void)out_size;
}

// round 12
// speedup vs baseline: 3.0284x; 1.0086x over previous
#include <cuda_runtime.h>
#include <cuda_fp16.h>
#include <math.h>
#include <stdint.h>
#include <stddef.h>

// ---------------- problem constants ----------------
#define Bv      16
#define Kv      2
#define Ev      768
#define Hv      12
#define HSv     64
#define Lv      12
#define Tv      621
#define TP      640
#define NPATCH  588
#define QKVLD   2304
#define E4      3072
#define AOUTv   64
#define MTv     (Bv*Tv)      // 9936
#define MPATCH  (Bv*NPATCH)  // 9408
#define ZH      (Bv*Hv)      // 192
#define SCALE_QK 0.036084391824351615f

#define CDIV(a,b) (((a)+(b)-1)/(b))
#define TGSMEM   196608      // 2 stages x 96KB (A 64K + B 32K)
#define QKSMEM   32768
#define PVSMEM   36864       // 3 stages x 12KB

typedef __half h16;

// ---------------- scratch ----------------
__device__ __align__(128) float g_POS[Tv*Ev];
__device__ __align__(128) float g_X  [(size_t)MTv*Ev];
__device__ __align__(128) float g_Z  [Bv*Ev];

__device__ __align__(128) h16 g_S  [(size_t)ZH*TP*TP];   // fp16 scores (probe dumps floats here too)
__device__ __align__(128) h16 g_H  [(size_t)MTv*Ev];
__device__ __align__(128) h16 g_O  [(size_t)MTv*Ev];
__device__ __align__(128) h16 g_F  [(size_t)MTv*E4];
__device__ __align__(128) h16 g_XP [(size_t)MPATCH*Ev];
__device__ __align__(128) h16 g_QKV[(size_t)MTv*QKVLD];
__device__ __align__(128) h16 g_P  [(size_t)ZH*TP*TP];
__device__ __align__(128) h16 g_Vt [(size_t)ZH*HSv*TP];

__device__ __align__(128) h16 g_Wqkv[(size_t)Lv*QKVLD*Ev];
__device__ __align__(128) h16 g_Wprj[(size_t)Lv*Ev*Ev];
__device__ __align__(128) h16 g_Wf1 [(size_t)Lv*E4*Ev];
__device__ __align__(128) h16 g_Wf2 [(size_t)Lv*Ev*E4];
__device__ __align__(128) h16 g_Wpat[(size_t)Ev*Ev];

// ---------------- mask-derived tile lists ----------------
__constant__ int c_qkT[19] = {0, 1,1,1,1, 2,2,2,2, 3,3,3,3,3, 4,4,4,4,4};
__constant__ int c_qkS[19] = {0, 0,1,2,3, 0,1,2,3, 0,1,2,3,4, 0,1,2,3,4};
__constant__ int c_pvLo1[5] = {0,0,0,0,0};
__constant__ int c_pvHi1[5] = {4,1,1,1,1};
__constant__ int c_pvLo2[5] = {4,4,7,7,7};
__constant__ int c_pvHi2[5] = {4,14,14,20,20};

// ---------------- helpers ----------------
__device__ __forceinline__ uint32_t smem_u32(const void* p) {
    uint32_t a;
    asm("{ .reg .u64 t; cvta.to.shared.u64 t, %1; cvt.u32.u64 %0, t; }" : "=r"(a) : "l"(p));
    return a;
}
__device__ __forceinline__ void cp16(uint32_t sa, const void* ga, bool v) {
    int sz = v ? 16 : 0;
    asm volatile("cp.async.cg.shared.global [%0], [%1], 16, %2;" :: "r"(sa), "l"(ga), "r"(sz) : "memory");
}
#define CP_COMMIT() asm volatile("cp.async.commit_group;" ::: "memory")
#define CP_WAIT0()  asm volatile("cp.async.wait_group 0;" ::: "memory")
#define CP_WAIT1()  asm volatile("cp.async.wait_group 1;" ::: "memory")

#define LDSM4(r, a) \
    asm volatile("ldmatrix.sync.aligned.m8n8.x4.shared.b16 {%0,%1,%2,%3}, [%4];" \
        : "=r"((r)[0]),"=r"((r)[1]),"=r"((r)[2]),"=r"((r)[3]) : "r"(a))

__device__ __forceinline__ void mma16816(float* d, const uint32_t* a, const uint32_t* b) {
    asm volatile("mma.sync.aligned.m16n8k16.row.col.f32.f16.f16.f32 "
        "{%0,%1,%2,%3}, {%4,%5,%6,%7}, {%8,%9}, {%0,%1,%2,%3};"
        : "+f"(d[0]),"+f"(d[1]),"+f"(d[2]),"+f"(d[3])
        : "r"(a[0]),"r"(a[1]),"r"(a[2]),"r"(a[3]), "r"(b[0]),"r"(b[1]));
}

// 256B-row swizzled offset (two 128B atoms per row); seg = 16B unit index 0..15
__device__ __forceinline__ uint32_t swz256(int row, int seg) {
    return (uint32_t)(row * 256 + ((seg & 8) << 4) + (((seg & 7) ^ (row & 7)) << 4));
}

// ---------------- mask ----------------
__device__ __forceinline__ bool keep_fn(int t, int s) {
    bool v = (t == s);
    if (s < 32) v = !(t >= 32 && t < 228);
    if (t >= 228 && s >= 228 && s < 424) v = true;
    if (t >= 424 && s >= 424 && s < 620) v = true;
    return v;
}

// ---------------- positional embedding ----------------
__global__ void pos_kernel(float* POS) {
    int idx = blockIdx.x * 256 + threadIdx.x;
    if (idx >= Tv * Ev) return;
    int t = idx / Ev, j = idx % Ev;
    double expo = (double)(j & ~1) / (double)Ev;
    double ang  = (double)t / pow(10000.0, expo);
    POS[idx] = (float)((j & 1) ? cos(ang) : sin(ang));
}

// ---------------- transpose+convert weights ----------------
__global__ void transpose_conv(const float* __restrict__ src, h16* __restrict__ dst, int R, int C) {
    __shared__ float t[32][33];
    int z = blockIdx.z;
    src += (size_t)z * R * C; dst += (size_t)z * R * C;
    int c0 = blockIdx.x * 32, r0 = blockIdx.y * 32;
    int tx = threadIdx.x, ty = threadIdx.y;
    #pragma unroll
    for (int i = 0; i < 4; i++)
        t[ty + 8*i][tx] = src[(size_t)(r0 + ty + 8*i) * C + c0 + tx];
    __syncthreads();
    #pragma unroll
    for (int i = 0; i < 4; i++)
        dst[(size_t)(c0 + ty + 8*i) * R + r0 + tx] = __float2half(t[tx][ty + 8*i]);
}

__global__ void conv_wqkv(const float* __restrict__ wq, const float* __restrict__ wk,
                          const float* __restrict__ wv, h16* __restrict__ dst) {
    __shared__ float t[32][33];
    int z = blockIdx.z;
    int h = z % Hv, which = (z / Hv) % 3, l = z / (3 * Hv);
    const float* src = (which == 0) ? wq : (which == 1) ? wk : wv;
    src += ((size_t)l * Hv + h) * Ev * HSv;
    int d0 = blockIdx.x * 32, e0 = blockIdx.y * 32;
    int tx = threadIdx.x, ty = threadIdx.y;
    #pragma unroll
    for (int i = 0; i < 4; i++)
        t[ty + 8*i][tx] = src[(size_t)(e0 + ty + 8*i) * HSv + d0 + tx];
    __syncthreads();
    #pragma unroll
    for (int i = 0; i < 4; i++) {
        int d = d0 + ty + 8*i, e = e0 + tx;
        dst[((size_t)l * QKVLD + which * Ev + h * HSv + d) * Ev + e] = __float2half(t[tx][ty + 8*i]);
    }
}

// ---------------- gather patches -> fp16 ----------------
__global__ void gather_patches(const float* __restrict__ images, const float* __restrict__ goal_imgs,
                               h16* __restrict__ X) {
    int idx = blockIdx.x * 256 + threadIdx.x;
    if (idx >= MPATCH * Ev) return;
    int f = idx % Ev;
    int r = idx / Ev;
    int p = r % NPATCH;
    int b = r / NPATCH;
    int py = f / 48, px = (f % 48) / 3, c = f % 3;
    float val;
    if (p < 196) {
        int pr = p / 14, pc = p % 14;
        int y = pr * 16 + py, x = pc * 16 + px;
        val = goal_imgs[(((size_t)b * 224 + y) * 224 + x) * 3 + c];
    } else {
        int q = p - 196;
        int k = q / 196, pp = q % 196;
        int pr = pp / 14, pc = pp % 14;
        int y = pr * 16 + py, x = pc * 16 + px;
        val = images[((((size_t)b * Kv + k) * 224 + y) * 224 + x) * 3 + c];
    }
    X[idx] = __float2half(val);
}

// ---------------- text + action embed (+POS) ----------------
__global__ void embed_txt_act(const int* __restrict__ goals_txt, const float* __restrict__ text_emb,
                              const float* __restrict__ action_emb, const float* __restrict__ POS,
                              float* __restrict__ X) {
    int idx = blockIdx.x * 256 + threadIdx.x;
    if (idx >= Bv * 33 * Ev) return;
    int e  = idx % Ev;
    int r  = idx / Ev;
    int tt = r % 33;
    int b  = r / 33;
    int t  = (tt < 32) ? tt : 620;
    float v = (tt < 32) ? text_emb[(size_t)goals_txt[b * 32 + tt] * Ev + e] : action_emb[e];
    X[((size_t)b * Tv + t) * Ev + e] = v + POS[(size_t)t * Ev + e];
}

// ---------------- layernorm: warp per row, shuffle reduce -> fp16 ----------------
__global__ void ln_kernel(const float* __restrict__ X, h16* __restrict__ Out,
                          const float* __restrict__ sc, const float* __restrict__ bi) {
    int w = threadIdx.x >> 5, lane = threadIdx.x & 31;
    int row = blockIdx.x * 8 + w;
    if (row >= MTv) return;
    const float* x = X + (size_t)row * Ev;
    float4 v[6];
    float s = 0.f, ss = 0.f;
    #pragma unroll
    for (int i = 0; i < 6; i++) {
        v[i] = *(const float4*)(x + i * 128 + lane * 4);
        s  += v[i].x + v[i].y + v[i].z + v[i].w;
        ss += v[i].x*v[i].x + v[i].y*v[i].y + v[i].z*v[i].z + v[i].w*v[i].w;
    }
    #pragma unroll
    for (int off = 16; off; off >>= 1) {
        s  += __shfl_xor_sync(0xffffffff, s,  off);
        ss += __shfl_xor_sync(0xffffffff, ss, off);
    }
    float m   = s * (1.f / Ev);
    float var = ss * (1.f / Ev) - m * m;
    float inv = rsqrtf(var + 1e-5f);
    #pragma unroll
    for (int i = 0; i < 6; i++) {
        int col = i * 128 + lane * 4;
        float o0 = (v[i].x - m) * inv * sc[col]   + bi[col];
        float o1 = (v[i].y - m) * inv * sc[col+1] + bi[col+1];
        float o2 = (v[i].z - m) * inv * sc[col+2] + bi[col+2];
        float o3 = (v[i].w - m) * inv * sc[col+3] + bi[col+3];
        __half2 h0 = __floats2half2_rn(o0, o1);
        __half2 h1 = __floats2half2_rn(o2, o3);
        uint2 u = make_uint2(*(uint32_t*)&h0, *(uint32_t*)&h1);
        *(uint2*)(Out + (size_t)row * Ev + col) = u;
    }
}

// =====================================================================
// fp16 GEMM (mma.sync m16n8k16), 256x128 CTA tile, 256 threads,
// warp tile 64x64, Kc=128, 2-stage cp.async pipeline (wait0+sync then
// issue next load so it overlaps the full chunk compute).
// stage: A 64K @0 (256 rows x 256B), B 32K @64K (128 rows x 256B)
// =====================================================================
__global__ void __launch_bounds__(256, 1)
tgemm(int M, int N, int K,
      const h16* __restrict__ A, const h16* __restrict__ B,
      const float* __restrict__ bias,
      const float* __restrict__ rowmat, int ldrm, int rmode,
      float* outF, int ldo, int accf, int reluf,
      h16* outH)
{
    extern __shared__ char sm[];
    uint32_t sbase = smem_u32(sm);
    int tid = threadIdx.x, lane = tid & 31, wid = tid >> 5;
    int m0 = blockIdx.y * 256, n0 = blockIdx.x * 128;
    int wm = wid & 3, wn = wid >> 2;

    float acc[4][8][4];
    #pragma unroll
    for (int i = 0; i < 4; i++)
        #pragma unroll
        for (int j = 0; j < 8; j++)
            #pragma unroll
            for (int q = 0; q < 4; q++) acc[i][j][q] = 0.f;

    int nc = K >> 7;

    auto ld_st = [&](int c, int st, bool active) {
        if (active) {
            uint32_t sb = sbase + st * 98304;
            int k0 = c * 128;
            #pragma unroll
            for (int i = 0; i < 16; i++) {             // A: 256 rows x 16 segs
                int u = i * 256 + tid;
                int row = u >> 4, seg = u & 15;
                uint32_t off = swz256(row, seg);
                bool av = (m0 + row) < M;
                size_t ao = (size_t)(av ? (m0 + row) : 0) * K + k0 + seg * 8;
                cp16(sb + off, A + ao, av);
            }
            #pragma unroll
            for (int i = 0; i < 8; i++) {              // B: 128 rows x 16 segs
                int u = i * 256 + tid;
                int row = u >> 4, seg = u & 15;
                uint32_t off = swz256(row, seg);
                size_t bo = (size_t)(n0 + row) * K + k0 + seg * 8;
                cp16(sb + 65536 + off, B + bo, true);
            }
        }
        CP_COMMIT();
    };

    ld_st(0, 0, true);

    int matA = lane >> 3;
    int matB = lane >> 3;

    for (int c = 0; c < nc; c++) {
        CP_WAIT0();
        __syncthreads();
        ld_st(c + 1, (c + 1) & 1, c + 1 < nc);   // overlaps compute(c); stage (c+1)&1 != c&1

        uint32_t sA = sbase + (c & 1) * 98304;
        uint32_t sB = sA + 65536;

        #pragma unroll
        for (int ks = 0; ks < 8; ks++) {
            uint32_t bf[4][4];
            #pragma unroll
            for (int np = 0; np < 4; np++) {
                int brow = wn * 64 + np * 16 + ((matB >> 1) << 3) + (lane & 7);
                int bseg = ks * 2 + (matB & 1);
                LDSM4(bf[np], sB + swz256(brow, bseg));
            }
            uint32_t af[2][4];
            {
                int arow = wm * 64 + (lane & 7) + (matA & 1) * 8;
                int aseg = ks * 2 + (matA >> 1);
                LDSM4(af[0], sA + swz256(arow, aseg));
            }
            #pragma unroll
            for (int mt = 0; mt < 4; mt++) {
                int cur = mt & 1, nxt = cur ^ 1;
                if (mt < 3) {
                    int arow = wm * 64 + (mt + 1) * 16 + (lane & 7) + (matA & 1) * 8;
                    int aseg = ks * 2 + (matA >> 1);
                    LDSM4(af[nxt], sA + swz256(arow, aseg));
                }
                #pragma unroll
                for (int np = 0; np < 4; np++)
                    #pragma unroll
                    for (int t = 0; t < 2; t++)
                        mma16816(acc[mt][np * 2 + t], af[cur], bf[np] + 2 * t);
            }
        }
    }

    int r_l = lane >> 2, c_l = (lane & 3) * 2;
    #pragma unroll
    for (int mt = 0; mt < 4; mt++) {
        #pragma unroll
        for (int h = 0; h < 2; h++) {
            int rr = m0 + wm * 64 + mt * 16 + h * 8 + r_l;
            if (rr >= M) continue;
            int orow = rr, prow = rr;
            if (rmode) {
                int b = rr / NPATCH, p = rr - b * NPATCH;
                orow = b * Tv + 32 + p;
                prow = 32 + p;
            }
            #pragma unroll
            for (int j = 0; j < 8; j++) {
                int col = n0 + wn * 64 + j * 8 + c_l;
                float v0 = acc[mt][j][2 * h];
                float v1 = acc[mt][j][2 * h + 1];
                if (bias)   { v0 += bias[col]; v1 += bias[col + 1]; }
                if (rowmat) { const float* rp = rowmat + (size_t)prow * ldrm + col; v0 += rp[0]; v1 += rp[1]; }
                if (accf)   { const float* op = outF + (size_t)orow * ldo + col;   v0 += op[0]; v1 += op[1]; }
                if (reluf)  { v0 = fmaxf(v0, 0.f); v1 = fmaxf(v1, 0.f); }
                if (outF)   *(float2*)(outF + (size_t)orow * ldo + col) = make_float2(v0, v1);
                if (outH) {
                    size_t o = (size_t)rr * N + col;
                    __half2 hv = __floats2half2_rn(v0, v1);
                    *(__half2*)(outH + o) = hv;
                }
            }
        }
    }
}

// =====================================================================
// qk_mma: S[z][t][s] = (Q K^T)*scale ; live 128x128 tiles only, fp16 out
// =====================================================================
__global__ void __launch_bounds__(256, 2)
qk_mma(const h16* __restrict__ Q, h16* __restrict__ S)
{
    extern __shared__ char sm[];
    uint32_t sbase = smem_u32(sm);     // +0 Q (16K), +16K K (16K)
    int tid = threadIdx.x, lane = tid & 31, wid = tid >> 5;
    int z = blockIdx.y, b = z / Hv, h = z % Hv;
    int t0 = c_qkT[blockIdx.x] * 128, s0 = c_qkS[blockIdx.x] * 128;

    #pragma unroll
    for (int i = 0; i < 4; i++) {
        int u = i * 256 + tid;
        int row = u >> 3, seg = u & 7;
        uint32_t off = (uint32_t)(row * 128 + ((seg ^ (row & 7)) << 4));
        bool qv = (t0 + row) < Tv;
        bool kv = (s0 + row) < Tv;
        size_t qo = (size_t)(b * Tv + (qv ? t0 + row : 0)) * QKVLD + h * HSv + seg * 8;
        size_t ko = (size_t)(b * Tv + (kv ? s0 + row : 0)) * QKVLD + Ev + h * HSv + seg * 8;
        cp16(sbase + off,         Q + qo, qv);
        cp16(sbase + 16384 + off, Q + ko, kv);
    }
    CP_COMMIT();
    CP_WAIT0();
    __syncthreads();

    int wm = wid & 3, wn = wid >> 2;
    float acc[2][8][4];
    #pragma unroll
    for (int i = 0; i < 2; i++)
        #pragma unroll
        for (int j = 0; j < 8; j++)
            #pragma unroll
            for (int q = 0; q < 4; q++) acc[i][j][q] = 0.f;

    #pragma unroll
    for (int ks = 0; ks < 4; ks++) {
        uint32_t af[2][4];
        #pragma unroll
        for (int mt = 0; mt < 2; mt++) {
            int matA = lane >> 3;
            int arow = wm * 32 + mt * 16 + (lane & 7) + (matA & 1) * 8;
            int aseg = ks * 2 + (matA >> 1);
            uint32_t off = (uint32_t)(arow * 128 + ((aseg ^ (arow & 7)) << 4));
            LDSM4(af[mt], sbase + off);
        }
        #pragma unroll
        for (int np = 0; np < 4; np++) {
            uint32_t bf[4];
            int matB = lane >> 3;
            int brow = wn * 64 + np * 16 + ((matB >> 1) << 3) + (lane & 7);
            int bseg = ks * 2 + (matB & 1);
            uint32_t boff = (uint32_t)(brow * 128 + ((bseg ^ (brow & 7)) << 4));
            LDSM4(bf, sbase + 16384 + boff);
            #pragma unroll
            for (int t = 0; t < 2; t++)
                #pragma unroll
                for (int mt = 0; mt < 2; mt++)
                    mma16816(acc[mt][np * 2 + t], af[mt], bf + 2 * t);
        }
    }

    int r_l = lane >> 2, c_l = (lane & 3) * 2;
    #pragma unroll
    for (int mt = 0; mt < 2; mt++)
        #pragma unroll
        for (int h2 = 0; h2 < 2; h2++) {
            int rr = t0 + wm * 32 + mt * 16 + h2 * 8 + r_l;
            #pragma unroll
            for (int j = 0; j < 8; j++) {
                int col = s0 + wn * 64 + j * 8 + c_l;
                __half2 hv = __floats2half2_rn(acc[mt][j][2 * h2] * SCALE_QK,
                                               acc[mt][j][2 * h2 + 1] * SCALE_QK);
                *(__half2*)(S + ((size_t)z * TP + rr) * TP + col) = hv;
            }
        }
}

// ---------------- masked softmax: warp per row, fp16 in/out ----------------
__global__ void softmax_kernel(const h16* __restrict__ S, h16* __restrict__ P)
{
    int gid = blockIdx.x * 8 + (threadIdx.x >> 5);
    if (gid >= Tv * ZH) return;
    int z = gid / Tv, t = gid - z * Tv;
    const h16* row = S + ((size_t)z * TP + t) * TP;
    h16* ph = P + ((size_t)z * TP + t) * TP;
    int lane = threadIdx.x & 31;
    float v[20];
    float mx = -3.0e38f;
    #pragma unroll
    for (int i = 0; i < 20; i++) {
        int s = lane + i * 32;
        float val = __half2float(row[s]);
        v[i] = keep_fn(t, s) ? val : -3.0e38f;
        mx = fmaxf(mx, v[i]);
    }
    #pragma unroll
    for (int off = 16; off; off >>= 1)
        mx = fmaxf(mx, __shfl_xor_sync(0xffffffff, mx, off));
    float sum = 0.f;
    #pragma unroll
    for (int i = 0; i < 20; i++) {
        v[i] = (v[i] > -1.0e38f) ? expf(v[i] - mx) : 0.f;
        sum += v[i];
    }
    #pragma unroll
    for (int off = 16; off; off >>= 1)
        sum += __shfl_xor_sync(0xffffffff, sum, off);
    float inv = 1.f / sum;
    #pragma unroll
    for (int i = 0; i < 20; i++)
        ph[lane + i * 32] = __float2half(v[i] * inv);
}

// ---------------- V repack: QKV v-part -> Vt[z][d][s] fp16 (s padded 0) ----------------
__global__ void repack_v(const h16* __restrict__ Q, h16* __restrict__ Vt)
{
    __shared__ h16 th[32][33];
    int z = blockIdx.z, b = z / Hv, h = z % Hv;
    int s0 = blockIdx.x * 32, d0 = blockIdx.y * 32;
    int tx = threadIdx.x, ty = threadIdx.y;
    #pragma unroll
    for (int i = 0; i < 4; i++) {
        int s = s0 + ty + 8 * i;
        h16 vh = __float2half(0.f);
        if (s < Tv)
            vh = Q[(size_t)(b * Tv + s) * QKVLD + 2 * Ev + h * HSv + d0 + tx];
        th[ty + 8 * i][tx] = vh;
    }
    __syncthreads();
    #pragma unroll
    for (int i = 0; i < 4; i++)
        Vt[((size_t)z * HSv + d0 + ty + 8 * i) * TP + s0 + tx] = th[tx][ty + 8 * i];
}

// =====================================================================
// pv_mma: O[z][t][d] = P @ V^T-layout ; tile 128x64, Kc=32, mask-pruned
// chunk list per t-tile, 3-stage pipeline, fp16
// =====================================================================
__global__ void __launch_bounds__(256, 2)
pv_mma(const h16* __restrict__ P, const h16* __restrict__ Vt, h16* __restrict__ O)
{
    extern __shared__ char sm[];
    uint32_t sbase = smem_u32(sm);
    int tid = threadIdx.x, lane = tid & 31, wid = tid >> 5;
    int z = blockIdx.y, b = z / Hv, h = z % Hv;
    int tt = blockIdx.x;
    int t0 = tt * 128;
    int wm = wid & 3, wn = wid >> 2;

    int n1 = c_pvHi1[tt] - c_pvLo1[tt];
    int nch = n1 + (c_pvHi2[tt] - c_pvLo2[tt]);
    int lo1 = c_pvLo1[tt], lo2 = c_pvLo2[tt];
    auto chunk_of = [&](int i) { return (i < n1) ? lo1 + i : lo2 + (i - n1); };

    float acc[2][4][4];
    #pragma unroll
    for (int i = 0; i < 2; i++)
        #pragma unroll
        for (int j = 0; j < 4; j++)
            #pragma unroll
            for (int q = 0; q < 4; q++) acc[i][j][q] = 0.f;

    auto ld_st = [&](int c, int st, bool active) {
        if (active) {
            uint32_t sb = sbase + st * 12288;
            int k0 = c * 32;
            {
                int u = tid;
                int row = u >> 1, seg0 = (u & 1) * 2;
                #pragma unroll
                for (int q = 0; q < 2; q++) {
                    int seg = seg0 + q;
                    uint32_t off = (uint32_t)(row * 64 + ((seg ^ ((row >> 1) & 3)) << 4));
                    size_t po = ((size_t)z * TP + t0 + row) * TP + k0 + seg * 8;
                    cp16(sb + off, P + po, true);
                }
            }
            {
                int row = tid >> 2, seg = tid & 3;
                uint32_t off = (uint32_t)(row * 64 + ((seg ^ ((row >> 1) & 3)) << 4));
                size_t vo = ((size_t)z * HSv + row) * TP + k0 + seg * 8;
                cp16(sb + 8192 + off, Vt + vo, true);
            }
        }
        CP_COMMIT();
    };

    ld_st(chunk_of(0), 0, true);
    ld_st(1 < nch ? chunk_of(1) : 0, 1, 1 < nch);

    for (int i = 0; i < nch; i++) {
        CP_WAIT1();
        __syncthreads();

        int st = i % 3;
        uint32_t sP = sbase + st * 12288;
        uint32_t sV = sP + 8192;

        #pragma unroll
        for (int ks = 0; ks < 2; ks++) {
            uint32_t af[2][4];
            #pragma unroll
            for (int mt = 0; mt < 2; mt++) {
                int matA = lane >> 3;
                int arow = wm * 32 + mt * 16 + (lane & 7) + (matA & 1) * 8;
                int aseg = ks * 2 + (matA >> 1);
                uint32_t off = (uint32_t)(arow * 64 + ((aseg ^ ((arow >> 1) & 3)) << 4));
                LDSM4(af[mt], sP + off);
            }
            #pragma unroll
            for (int np = 0; np < 2; np++) {
                uint32_t bf[4];
                int matB = lane >> 3;
                int brow = wn * 32 + np * 16 + ((matB >> 1) << 3) + (lane & 7);
                int bseg = ks * 2 + (matB & 1);
                uint32_t boff = (uint32_t)(brow * 64 + ((bseg ^ ((brow >> 1) & 3)) << 4));
                LDSM4(bf, sV + boff);
                #pragma unroll
                for (int t = 0; t < 2; t++)
                    #pragma unroll
                    for (int mt = 0; mt < 2; mt++)
                        mma16816(acc[mt][np * 2 + t], af[mt], bf + 2 * t);
            }
        }
        ld_st(i + 2 < nch ? chunk_of(i + 2) : 0, (i + 2) % 3, i + 2 < nch);
    }

    int r_l = lane >> 2, c_l = (lane & 3) * 2;
    #pragma unroll
    for (int mt = 0; mt < 2; mt++)
        #pragma unroll
        for (int h2 = 0; h2 < 2; h2++) {
            int rr = t0 + wm * 32 + mt * 16 + h2 * 8 + r_l;
            if (rr >= Tv) continue;
            #pragma unroll
            for (int j = 0; j < 4; j++) {
                int col = wn * 32 + j * 8 + c_l;
                size_t o = ((size_t)(b * Tv + rr)) * Ev + h * HSv + col;
                __half2 hv = __floats2half2_rn(acc[mt][j][2 * h2], acc[mt][j][2 * h2 + 1]);
                *(__half2*)(O + o) = hv;
            }
        }
}

// ---------------- fp32 GEMM (head only) ----------------
__global__ void __launch_bounds__(256, 2)
sgemm128(int M, int N, int K,
         const float* __restrict__ A, int lda,
         const float* __restrict__ B, int ldb,
         float* __restrict__ C, int ldc,
         const float* __restrict__ bias, int reluflag)
{
    __shared__ __align__(16) float As[8][128];
    __shared__ __align__(16) float Bs[8][128];
    int n0 = blockIdx.x * 128, m0 = blockIdx.y * 128;
    int tid = threadIdx.x;
    int tx = tid & 15, ty = tid >> 4;
    int arow = tid >> 1,  akk  = (tid & 1) * 4;
    int bkk  = tid >> 5,  bcol = (tid & 31) * 4;
    bool aval = (m0 + arow) < M;
    bool bval = (n0 + bcol) < N;
    const float* Aptr = A + (size_t)(m0 + arow) * lda + akk;
    const float* Bptr = B + (size_t)bkk * ldb + n0 + bcol;
    float acc[8][8];
    #pragma unroll
    for (int i = 0; i < 8; i++)
        #pragma unroll
        for (int j = 0; j < 8; j++) acc[i][j] = 0.f;
    for (int k0 = 0; k0 < K; k0 += 8) {
        float4 av = make_float4(0.f,0.f,0.f,0.f), bv = make_float4(0.f,0.f,0.f,0.f);
        if (aval) av = *(const float4*)(Aptr + k0);
        if (bval) bv = *(const float4*)(Bptr + (size_t)k0 * ldb);
        __syncthreads();
        As[akk+0][arow] = av.x; As[akk+1][arow] = av.y;
        As[akk+2][arow] = av.z; As[akk+3][arow] = av.w;
        *(float4*)&Bs[bkk][bcol] = bv;
        __syncthreads();
        #pragma unroll
        for (int kk = 0; kk < 8; kk++) {
            float a[8], b2[8];
            *(float4*)(a)    = *(const float4*)&As[kk][ty*8];
            *(float4*)(a+4)  = *(const float4*)&As[kk][ty*8+4];
            *(float4*)(b2)   = *(const float4*)&Bs[kk][tx*8];
            *(float4*)(b2+4) = *(const float4*)&Bs[kk][tx*8+4];
            #pragma unroll
            for (int i = 0; i < 8; i++)
                #pragma unroll
                for (int j = 0; j < 8; j++)
                    acc[i][j] += a[i] * b2[j];
        }
    }
    #pragma unroll
    for (int i = 0; i < 8; i++) {
        int r = m0 + ty*8 + i;
        if (r >= M) continue;
        #pragma unroll
        for (int j = 0; j < 8; j++) {
            int c = n0 + tx*8 + j;
            if (c >= N) continue;
            float v = acc[i][j];
            if (bias) v += bias[c];
            if (reluflag) v = fmaxf(v, 0.f);
            C[(size_t)r * ldc + c] = v;
        }
    }
}

// ---------------- launch ----------------
extern "C" void kernel_launch(void* const* d_in, const int* in_sizes, int n_in,
                              void* d_out, int out_size) {
    const float* images     = (const float*)d_in[0];
    const int*   goals_txt  = (const int*)  d_in[1];
    const float* goal_imgs  = (const float*)d_in[2];
    const float* patch_w    = (const float*)d_in[3];
    const float* patch_b    = (const float*)d_in[4];
    const float* text_emb   = (const float*)d_in[5];
    const float* action_emb = (const float*)d_in[6];
    const float* wq         = (const float*)d_in[7];
    const float* wk         = (const float*)d_in[8];
    const float* wv         = (const float*)d_in[9];
    const float* proj_w     = (const float*)d_in[10];
    const float* proj_b     = (const float*)d_in[11];
    const float* ln1_s      = (const float*)d_in[12];
    const float* ln1_b      = (const float*)d_in[13];
    const float* ln2_s      = (const float*)d_in[14];
    const float* ln2_b      = (const float*)d_in[15];
    const float* ff_w1      = (const float*)d_in[16];
    const float* ff_b1      = (const float*)d_in[17];
    const float* ff_w2      = (const float*)d_in[18];
    const float* ff_b2      = (const float*)d_in[19];
    const float* hw1        = (const float*)d_in[20];
    const float* hb1        = (const float*)d_in[21];
    const float* hw2        = (const float*)d_in[22];
    const float* hb2        = (const float*)d_in[23];
    float* out = (float*)d_out;

    cudaFuncSetAttribute(tgemm,  cudaFuncAttributeMaxDynamicSharedMemorySize, TGSMEM);
    cudaFuncSetAttribute(qk_mma, cudaFuncAttributeMaxDynamicSharedMemorySize, QKSMEM);
    cudaFuncSetAttribute(pv_mma, cudaFuncAttributeMaxDynamicSharedMemorySize, PVSMEM);

    float *pPOS, *pX, *pZ;
    h16 *pS, *pH, *pO, *pF, *pXP, *pQ, *pP, *pVt;
    h16 *pWq, *pWp, *pW1, *pW2, *pWt;
    cudaGetSymbolAddress((void**)&pPOS, g_POS);
    cudaGetSymbolAddress((void**)&pX,   g_X);
    cudaGetSymbolAddress((void**)&pZ,   g_Z);
    cudaGetSymbolAddress((void**)&pS,   g_S);
    cudaGetSymbolAddress((void**)&pH,   g_H);
    cudaGetSymbolAddress((void**)&pO,   g_O);
    cudaGetSymbolAddress((void**)&pF,   g_F);
    cudaGetSymbolAddress((void**)&pXP,  g_XP);
    cudaGetSymbolAddress((void**)&pQ,   g_QKV);
    cudaGetSymbolAddress((void**)&pP,   g_P);
    cudaGetSymbolAddress((void**)&pVt,  g_Vt);
    cudaGetSymbolAddress((void**)&pWq,  g_Wqkv);
    cudaGetSymbolAddress((void**)&pWp,  g_Wprj);
    cudaGetSymbolAddress((void**)&pW1,  g_Wf1);
    cudaGetSymbolAddress((void**)&pW2,  g_Wf2);
    cudaGetSymbolAddress((void**)&pWt,  g_Wpat);

    // ---- prep (launch #4 = dummy QKV-shaped tgemm probe for ncu -s 5 -c 1) ----
    pos_kernel    <<<CDIV(Tv*Ev, 256), 256>>>(pPOS);                                  // 1
    conv_wqkv     <<<dim3(2, 24, Lv*3*Hv), dim3(32,8)>>>(wq, wk, wv, pWq);            // 2
    transpose_conv<<<dim3(24, 24, Lv), dim3(32,8)>>>(proj_w, pWp, Ev, Ev);            // 3
    tgemm<<<dim3(QKVLD/128, 10), 256, TGSMEM>>>(                                       // 4 (probe)
        2560, QKVLD, Ev, pXP, pWq,
        nullptr, nullptr, 0, 0, (float*)pS, QKVLD, 0, 0, nullptr);
    transpose_conv<<<dim3(96, 24, Lv), dim3(32,8)>>>(ff_w1, pW1, Ev, E4);             // 5
    transpose_conv<<<dim3(24, 96, Lv), dim3(32,8)>>>(ff_w2, pW2, E4, Ev);             // 6
    transpose_conv<<<dim3(24, 24, 1),  dim3(32,8)>>>(patch_w, pWt, Ev, Ev);
    gather_patches<<<CDIV(MPATCH*Ev, 256), 256>>>(images, goal_imgs, pXP);
    embed_txt_act <<<CDIV(Bv*33*Ev, 256), 256>>>(goals_txt, text_emb, action_emb, pPOS, pX);

    // patch embed -> X rows 32..619 (+bias +POS)
    tgemm<<<dim3(Ev/128, CDIV(MPATCH,256)), 256, TGSMEM>>>(
        MPATCH, Ev, Ev, pXP, pWt,
        patch_b, pPOS, Ev, 1,
        pX, Ev, 0, 0, nullptr);

    for (int l = 0; l < Lv; l++) {
        ln_kernel<<<CDIV(MTv,8), 256>>>(pX, pH, ln1_s + l*Ev, ln1_b + l*Ev);

        tgemm<<<dim3(QKVLD/128, CDIV(MTv,256)), 256, TGSMEM>>>(   // QKV -> fp16
            MTv, QKVLD, Ev, pH, pWq + (size_t)l*QKVLD*Ev,
            nullptr, nullptr, 0, 0,
            nullptr, 0, 0, 0, pQ);

        qk_mma        <<<dim3(19, ZH), 256, QKSMEM>>>(pQ, pS);
        softmax_kernel<<<CDIV(Tv*ZH,8), 256>>>(pS, pP);
        repack_v      <<<dim3(TP/32, HSv/32, ZH), dim3(32,8)>>>(pQ, pVt);
        pv_mma        <<<dim3(TP/128, ZH), 256, PVSMEM>>>(pP, pVt, pO);

        tgemm<<<dim3(Ev/128, CDIV(MTv,256)), 256, TGSMEM>>>(   // X += O @ proj + b
            MTv, Ev, Ev, pO, pWp + (size_t)l*Ev*Ev,
            proj_b + l*Ev, nullptr, 0, 0,
            pX, Ev, 1, 0, nullptr);

        ln_kernel<<<CDIV(MTv,8), 256>>>(pX, pH, ln2_s + l*Ev, ln2_b + l*Ev);

        tgemm<<<dim3(E4/128, CDIV(MTv,256)), 256, TGSMEM>>>(   // F = relu(h@W1+b1) -> fp16
            MTv, E4, Ev, pH, pW1 + (size_t)l*E4*Ev,
            ff_b1 + l*E4, nullptr, 0, 0,
            nullptr, 0, 0, 1, pF);

        tgemm<<<dim3(Ev/128, CDIV(MTv,256)), 256, TGSMEM>>>(   // X += F @ W2 + b2
            MTv, Ev, E4, pF, pW2 + (size_t)l*Ev*E4,
            ff_b2 + l*Ev, nullptr, 0, 0,
            pX, Ev, 1, 0, nullptr);
    }

    // head
    sgemm128<<<dim3(Ev/128, 1), 256>>>(
        Bv, Ev, Ev, pX + (size_t)620*Ev, Tv*Ev, hw1, Ev, pZ, Ev, hb1, 1);
    sgemm128<<<dim3(1, 1), 256>>>(
        Bv, AOUTv, Ev, pZ, Ev, hw2, AOUTv, out, AOUTv, hb2, 0);

    (void)in_sizes; (void)n_in; (void)out_size;
}

// round 14
// speedup vs baseline: 3.1612x; 1.0438x over previous
#include <cuda_runtime.h>
#include <cuda_fp16.h>
#include <math.h>
#include <stdint.h>
#include <stddef.h>

// ---------------- problem constants ----------------
#define Bv      16
#define Kv      2
#define Ev      768
#define Hv      12
#define HSv     64
#define Lv      12
#define Tv      621
#define TP      640
#define NPATCH  588
#define QKVLD   2304
#define E4      3072
#define AOUTv   64
#define MTv     (Bv*Tv)      // 9936
#define MPATCH  (Bv*NPATCH)  // 9408
#define ZH      (Bv*Hv)      // 192
#define SCALE_QK 0.036084391824351615f

#define CDIV(a,b) (((a)+(b)-1)/(b))
#define TGSMEM   196608      // 2 stages x 96KB (A 64K + B 32K)
#define FASMEM   83968       // Q 16K + 2x(K16K+V16K) + stats 2K

typedef __half h16;

// ---------------- scratch ----------------
__device__ __align__(128) float g_POS[Tv*Ev];
__device__ __align__(128) float g_X  [(size_t)MTv*Ev];
__device__ __align__(128) float g_Z  [Bv*Ev];

__device__ __align__(128) h16 g_H  [(size_t)MTv*Ev];
__device__ __align__(128) h16 g_O  [(size_t)MTv*Ev];
__device__ __align__(128) h16 g_F  [(size_t)MTv*E4];
__device__ __align__(128) h16 g_XP [(size_t)MPATCH*Ev];
__device__ __align__(128) h16 g_QKV[(size_t)MTv*QKVLD];
__device__ __align__(128) h16 g_Vt [(size_t)ZH*HSv*TP];

__device__ __align__(128) h16 g_Wqkv[(size_t)Lv*QKVLD*Ev];
__device__ __align__(128) h16 g_Wprj[(size_t)Lv*Ev*Ev];
__device__ __align__(128) h16 g_Wf1 [(size_t)Lv*E4*Ev];
__device__ __align__(128) h16 g_Wf2 [(size_t)Lv*Ev*E4];
__device__ __align__(128) h16 g_Wpat[(size_t)Ev*Ev];

// ---------------- mask-derived live s-block lists per t-tile ----------------
__constant__ int c_fN[5] = {1, 4, 4, 5, 5};
__constant__ int c_fB[5][5] = {
    {0, 0, 0, 0, 0},
    {0, 1, 2, 3, 0},
    {0, 1, 2, 3, 0},
    {0, 1, 2, 3, 4},
    {0, 1, 2, 3, 4}
};

// ---------------- helpers ----------------
__device__ __forceinline__ uint32_t smem_u32(const void* p) {
    uint32_t a;
    asm("{ .reg .u64 t; cvta.to.shared.u64 t, %1; cvt.u32.u64 %0, t; }" : "=r"(a) : "l"(p));
    return a;
}
__device__ __forceinline__ void cp16(uint32_t sa, const void* ga, bool v) {
    int sz = v ? 16 : 0;
    asm volatile("cp.async.cg.shared.global [%0], [%1], 16, %2;" :: "r"(sa), "l"(ga), "r"(sz) : "memory");
}
#define CP_COMMIT() asm volatile("cp.async.commit_group;" ::: "memory")
#define CP_WAIT0()  asm volatile("cp.async.wait_group 0;" ::: "memory")

#define LDSM4(r, a) \
    asm volatile("ldmatrix.sync.aligned.m8n8.x4.shared.b16 {%0,%1,%2,%3}, [%4];" \
        : "=r"((r)[0]),"=r"((r)[1]),"=r"((r)[2]),"=r"((r)[3]) : "r"(a))

__device__ __forceinline__ void mma16816(float* d, const uint32_t* a, const uint32_t* b) {
    asm volatile("mma.sync.aligned.m16n8k16.row.col.f32.f16.f16.f32 "
        "{%0,%1,%2,%3}, {%4,%5,%6,%7}, {%8,%9}, {%0,%1,%2,%3};"
        : "+f"(d[0]),"+f"(d[1]),"+f"(d[2]),"+f"(d[3])
        : "r"(a[0]),"r"(a[1]),"r"(a[2]),"r"(a[3]), "r"(b[0]),"r"(b[1]));
}

// 256B-row swizzled offset; seg = 16B unit index 0..15
__device__ __forceinline__ uint32_t swz256(int row, int seg) {
    return (uint32_t)(row * 256 + ((seg & 8) << 4) + (((seg & 7) ^ (row & 7)) << 4));
}

// ---------------- mask ----------------
__device__ __forceinline__ bool keep_fn(int t, int s) {
    bool v = (t == s);
    if (s < 32) v = !(t >= 32 && t < 228);
    if (t >= 228 && s >= 228 && s < 424) v = true;
    if (t >= 424 && s >= 424 && s < 620) v = true;
    return v;
}

// ---------------- positional embedding ----------------
__global__ void pos_kernel(float* POS) {
    int idx = blockIdx.x * 256 + threadIdx.x;
    if (idx >= Tv * Ev) return;
    int t = idx / Ev, j = idx % Ev;
    double expo = (double)(j & ~1) / (double)Ev;
    double ang  = (double)t / pow(10000.0, expo);
    POS[idx] = (float)((j & 1) ? cos(ang) : sin(ang));
}

// ---------------- transpose+convert weights ----------------
__global__ void transpose_conv(const float* __restrict__ src, h16* __restrict__ dst, int R, int C) {
    __shared__ float t[32][33];
    int z = blockIdx.z;
    src += (size_t)z * R * C; dst += (size_t)z * R * C;
    int c0 = blockIdx.x * 32, r0 = blockIdx.y * 32;
    int tx = threadIdx.x, ty = threadIdx.y;
    #pragma unroll
    for (int i = 0; i < 4; i++)
        t[ty + 8*i][tx] = src[(size_t)(r0 + ty + 8*i) * C + c0 + tx];
    __syncthreads();
    #pragma unroll
    for (int i = 0; i < 4; i++)
        dst[(size_t)(c0 + ty + 8*i) * R + r0 + tx] = __float2half(t[tx][ty + 8*i]);
}

__global__ void conv_wqkv(const float* __restrict__ wq, const float* __restrict__ wk,
                          const float* __restrict__ wv, h16* __restrict__ dst) {
    __shared__ float t[32][33];
    int z = blockIdx.z;
    int h = z % Hv, which = (z / Hv) % 3, l = z / (3 * Hv);
    const float* src = (which == 0) ? wq : (which == 1) ? wk : wv;
    src += ((size_t)l * Hv + h) * Ev * HSv;
    int d0 = blockIdx.x * 32, e0 = blockIdx.y * 32;
    int tx = threadIdx.x, ty = threadIdx.y;
    #pragma unroll
    for (int i = 0; i < 4; i++)
        t[ty + 8*i][tx] = src[(size_t)(e0 + ty + 8*i) * HSv + d0 + tx];
    __syncthreads();
    #pragma unroll
    for (int i = 0; i < 4; i++) {
        int d = d0 + ty + 8*i, e = e0 + tx;
        dst[((size_t)l * QKVLD + which * Ev + h * HSv + d) * Ev + e] = __float2half(t[tx][ty + 8*i]);
    }
}

// ---------------- gather patches -> fp16 ----------------
__global__ void gather_patches(const float* __restrict__ images, const float* __restrict__ goal_imgs,
                               h16* __restrict__ X) {
    int idx = blockIdx.x * 256 + threadIdx.x;
    if (idx >= MPATCH * Ev) return;
    int f = idx % Ev;
    int r = idx / Ev;
    int p = r % NPATCH;
    int b = r / NPATCH;
    int py = f / 48, px = (f % 48) / 3, c = f % 3;
    float val;
    if (p < 196) {
        int pr = p / 14, pc = p % 14;
        int y = pr * 16 + py, x = pc * 16 + px;
        val = goal_imgs[(((size_t)b * 224 + y) * 224 + x) * 3 + c];
    } else {
        int q = p - 196;
        int k = q / 196, pp = q % 196;
        int pr = pp / 14, pc = pp % 14;
        int y = pr * 16 + py, x = pc * 16 + px;
        val = images[((((size_t)b * Kv + k) * 224 + y) * 224 + x) * 3 + c];
    }
    X[idx] = __float2half(val);
}

// ---------------- text + action embed (+POS) ----------------
__global__ void embed_txt_act(const int* __restrict__ goals_txt, const float* __restrict__ text_emb,
                              const float* __restrict__ action_emb, const float* __restrict__ POS,
                              float* __restrict__ X) {
    int idx = blockIdx.x * 256 + threadIdx.x;
    if (idx >= Bv * 33 * Ev) return;
    int e  = idx % Ev;
    int r  = idx / Ev;
    int tt = r % 33;
    int b  = r / 33;
    int t  = (tt < 32) ? tt : 620;
    float v = (tt < 32) ? text_emb[(size_t)goals_txt[b * 32 + tt] * Ev + e] : action_emb[e];
    X[((size_t)b * Tv + t) * Ev + e] = v + POS[(size_t)t * Ev + e];
}

// ---------------- layernorm: warp per row, shuffle reduce -> fp16 ----------------
__global__ void ln_kernel(const float* __restrict__ X, h16* __restrict__ Out,
                          const float* __restrict__ sc, const float* __restrict__ bi) {
    int w = threadIdx.x >> 5, lane = threadIdx.x & 31;
    int row = blockIdx.x * 8 + w;
    if (row >= MTv) return;
    const float* x = X + (size_t)row * Ev;
    float4 v[6];
    float s = 0.f, ss = 0.f;
    #pragma unroll
    for (int i = 0; i < 6; i++) {
        v[i] = *(const float4*)(x + i * 128 + lane * 4);
        s  += v[i].x + v[i].y + v[i].z + v[i].w;
        ss += v[i].x*v[i].x + v[i].y*v[i].y + v[i].z*v[i].z + v[i].w*v[i].w;
    }
    #pragma unroll
    for (int off = 16; off; off >>= 1) {
        s  += __shfl_xor_sync(0xffffffff, s,  off);
        ss += __shfl_xor_sync(0xffffffff, ss, off);
    }
    float m   = s * (1.f / Ev);
    float var = ss * (1.f / Ev) - m * m;
    float inv = rsqrtf(var + 1e-5f);
    #pragma unroll
    for (int i = 0; i < 6; i++) {
        int col = i * 128 + lane * 4;
        float o0 = (v[i].x - m) * inv * sc[col]   + bi[col];
        float o1 = (v[i].y - m) * inv * sc[col+1] + bi[col+1];
        float o2 = (v[i].z - m) * inv * sc[col+2] + bi[col+2];
        float o3 = (v[i].w - m) * inv * sc[col+3] + bi[col+3];
        __half2 h0 = __floats2half2_rn(o0, o1);
        __half2 h1 = __floats2half2_rn(o2, o3);
        uint2 u = make_uint2(*(uint32_t*)&h0, *(uint32_t*)&h1);
        *(uint2*)(Out + (size_t)row * Ev + col) = u;
    }
}

// =====================================================================
// fp16 GEMM (mma.sync m16n8k16), 256x128 CTA tile, 256 threads,
// warp tile 64x64, Kc=128, 2-stage cp.async pipeline.
// =====================================================================
__global__ void __launch_bounds__(256, 1)
tgemm(int M, int N, int K,
      const h16* __restrict__ A, const h16* __restrict__ B,
      const float* __restrict__ bias,
      const float* __restrict__ rowmat, int ldrm, int rmode,
      float* outF, int ldo, int accf, int reluf,
      h16* outH)
{
    extern __shared__ char sm[];
    uint32_t sbase = smem_u32(sm);
    int tid = threadIdx.x, lane = tid & 31, wid = tid >> 5;
    int m0 = blockIdx.y * 256, n0 = blockIdx.x * 128;
    int wm = wid & 3, wn = wid >> 2;

    float acc[4][8][4];
    #pragma unroll
    for (int i = 0; i < 4; i++)
        #pragma unroll
        for (int j = 0; j < 8; j++)
            #pragma unroll
            for (int q = 0; q < 4; q++) acc[i][j][q] = 0.f;

    int nc = K >> 7;

    auto ld_st = [&](int c, int st, bool active) {
        if (active) {
            uint32_t sb = sbase + st * 98304;
            int k0 = c * 128;
            #pragma unroll
            for (int i = 0; i < 16; i++) {
                int u = i * 256 + tid;
                int row = u >> 4, seg = u & 15;
                uint32_t off = swz256(row, seg);
                bool av = (m0 + row) < M;
                size_t ao = (size_t)(av ? (m0 + row) : 0) * K + k0 + seg * 8;
                cp16(sb + off, A + ao, av);
            }
            #pragma unroll
            for (int i = 0; i < 8; i++) {
                int u = i * 256 + tid;
                int row = u >> 4, seg = u & 15;
                uint32_t off = swz256(row, seg);
                size_t bo = (size_t)(n0 + row) * K + k0 + seg * 8;
                cp16(sb + 65536 + off, B + bo, true);
            }
        }
        CP_COMMIT();
    };

    ld_st(0, 0, true);

    int matA = lane >> 3;
    int matB = lane >> 3;

    for (int c = 0; c < nc; c++) {
        CP_WAIT0();
        __syncthreads();
        ld_st(c + 1, (c + 1) & 1, c + 1 < nc);

        uint32_t sA = sbase + (c & 1) * 98304;
        uint32_t sB = sA + 65536;

        #pragma unroll
        for (int ks = 0; ks < 8; ks++) {
            uint32_t bf[4][4];
            #pragma unroll
            for (int np = 0; np < 4; np++) {
                int brow = wn * 64 + np * 16 + ((matB >> 1) << 3) + (lane & 7);
                int bseg = ks * 2 + (matB & 1);
                LDSM4(bf[np], sB + swz256(brow, bseg));
            }
            uint32_t af[2][4];
            {
                int arow = wm * 64 + (lane & 7) + (matA & 1) * 8;
                int aseg = ks * 2 + (matA >> 1);
                LDSM4(af[0], sA + swz256(arow, aseg));
            }
            #pragma unroll
            for (int mt = 0; mt < 4; mt++) {
                int cur = mt & 1, nxt = cur ^ 1;
                if (mt < 3) {
                    int arow = wm * 64 + (mt + 1) * 16 + (lane & 7) + (matA & 1) * 8;
                    int aseg = ks * 2 + (matA >> 1);
                    LDSM4(af[nxt], sA + swz256(arow, aseg));
                }
                #pragma unroll
                for (int np = 0; np < 4; np++)
                    #pragma unroll
                    for (int t = 0; t < 2; t++)
                        mma16816(acc[mt][np * 2 + t], af[cur], bf[np] + 2 * t);
            }
        }
    }

    int r_l = lane >> 2, c_l = (lane & 3) * 2;
    #pragma unroll
    for (int mt = 0; mt < 4; mt++) {
        #pragma unroll
        for (int h = 0; h < 2; h++) {
            int rr = m0 + wm * 64 + mt * 16 + h * 8 + r_l;
            if (rr >= M) continue;
            int orow = rr, prow = rr;
            if (rmode) {
                int b = rr / NPATCH, p = rr - b * NPATCH;
                orow = b * Tv + 32 + p;
                prow = 32 + p;
            }
            #pragma unroll
            for (int j = 0; j < 8; j++) {
                int col = n0 + wn * 64 + j * 8 + c_l;
                float v0 = acc[mt][j][2 * h];
                float v1 = acc[mt][j][2 * h + 1];
                if (bias)   { v0 += bias[col]; v1 += bias[col + 1]; }
                if (rowmat) { const float* rp = rowmat + (size_t)prow * ldrm + col; v0 += rp[0]; v1 += rp[1]; }
                if (accf)   { const float* op = outF + (size_t)orow * ldo + col;   v0 += op[0]; v1 += op[1]; }
                if (reluf)  { v0 = fmaxf(v0, 0.f); v1 = fmaxf(v1, 0.f); }
                if (outF)   *(float2*)(outF + (size_t)orow * ldo + col) = make_float2(v0, v1);
                if (outH) {
                    size_t o = (size_t)rr * N + col;
                    __half2 hv = __floats2half2_rn(v0, v1);
                    *(__half2*)(outH + o) = hv;
                }
            }
        }
    }
}

// ---------------- V repack: QKV v-part -> Vt[z][d][s] fp16 (s padded 0) ----------------
__global__ void repack_v(const h16* __restrict__ Q, h16* __restrict__ Vt)
{
    __shared__ h16 th[32][33];
    int z = blockIdx.z, b = z / Hv, h = z % Hv;
    int s0 = blockIdx.x * 32, d0 = blockIdx.y * 32;
    int tx = threadIdx.x, ty = threadIdx.y;
    #pragma unroll
    for (int i = 0; i < 4; i++) {
        int s = s0 + ty + 8 * i;
        h16 vh = __float2half(0.f);
        if (s < Tv)
            vh = Q[(size_t)(b * Tv + s) * QKVLD + 2 * Ev + h * HSv + d0 + tx];
        th[ty + 8 * i][tx] = vh;
    }
    __syncthreads();
    #pragma unroll
    for (int i = 0; i < 4; i++)
        Vt[((size_t)z * HSv + d0 + ty + 8 * i) * TP + s0 + tx] = th[tx][ty + 8 * i];
}

// =====================================================================
// fattn: fused flash attention. One CTA per (t-tile, z).
// 8 warps: wm=wid>>1 (m32 rows), wn=wid&1 (s-half 64 of each s-block).
// S in fp32 regs; online softmax; P->A-frag in-register; O partial per
// warp summed across the wn pair at the end.
// smem: Q @0 (16K), stage{0,1}: K @16K/48K (16K), V @32K/64K (16K),
//       mx @80K (1K), ls @81K (1K). obuf (32KB fp32) reuses @16K.
// =====================================================================
__global__ void __launch_bounds__(256, 1)
fattn(const h16* __restrict__ QKV, const h16* __restrict__ Vt, h16* __restrict__ O)
{
    extern __shared__ char sm[];
    uint32_t sbase = smem_u32(sm);
    float* mxbuf = (float*)(sm + 81920);   // [2][128]
    float* lsbuf = (float*)(sm + 82944);   // [2][128]
    float* obuf  = (float*)(sm + 16384);   // [4][32][64] fp32 (reuse stages)

    int tid = threadIdx.x, lane = tid & 31, wid = tid >> 5;
    int wm = wid >> 1, wn = wid & 1;
    int tt = blockIdx.x, z = blockIdx.y, b = z / Hv, h = z % Hv;
    int t0 = tt * 128;
    int nblk = c_fN[tt];
    int matX = lane >> 3;
    int r_l = lane >> 2, c_l = (lane & 3) * 2;

    // ---- loaders ----
    auto ldQ = [&]() {
        #pragma unroll
        for (int i = 0; i < 4; i++) {
            int u = i * 256 + tid;
            int row = u >> 3, seg = u & 7;
            uint32_t off = (uint32_t)(row * 128 + ((seg ^ (row & 7)) << 4));
            bool v = (t0 + row) < Tv;
            size_t qo = (size_t)(b * Tv + (v ? t0 + row : 0)) * QKVLD + h * HSv + seg * 8;
            cp16(sbase + off, QKV + qo, v);
        }
    };
    auto ldKV = [&](int blk_i, int st, bool active) {
        if (active) {
            int s0 = c_fB[tt][blk_i] * 128;
            uint32_t kb = sbase + 16384 + st * 32768;
            uint32_t vb = kb + 16384;
            #pragma unroll
            for (int i = 0; i < 4; i++) {   // K: 128 rows x 8 segs (128B rows)
                int u = i * 256 + tid;
                int row = u >> 3, seg = u & 7;
                uint32_t off = (uint32_t)(row * 128 + ((seg ^ (row & 7)) << 4));
                bool v = (s0 + row) < Tv;
                size_t ko = (size_t)(b * Tv + (v ? s0 + row : 0)) * QKVLD + Ev + h * HSv + seg * 8;
                cp16(kb + off, QKV + ko, v);
            }
            #pragma unroll
            for (int i = 0; i < 4; i++) {   // V: 64 rows x 16 segs (256B rows)
                int u = i * 256 + tid;
                int row = u >> 4, seg = u & 15;
                size_t vo = ((size_t)z * HSv + row) * TP + s0 + seg * 8;
                cp16(vb + swz256(row, seg), Vt + vo, true);
            }
        }
        CP_COMMIT();
    };

    // ---- state ----
    float oacc[2][8][4];
    #pragma unroll
    for (int m = 0; m < 2; m++)
        #pragma unroll
        for (int j = 0; j < 8; j++)
            #pragma unroll
            for (int q = 0; q < 4; q++) oacc[m][j][q] = 0.f;
    float mrow[2][2], lrow[2][2];
    #pragma unroll
    for (int m = 0; m < 2; m++) { mrow[m][0] = mrow[m][1] = -3.0e38f; lrow[m][0] = lrow[m][1] = 0.f; }

    uint32_t qf[2][4][4];
    bool qloaded = false;

    ldQ(); ldKV(0, 0, true);

    for (int i = 0; i < nblk; i++) {
        CP_WAIT0();
        __syncthreads();
        ldKV(i + 1, (i + 1) & 1, i + 1 < nblk);

        if (!qloaded) {
            qloaded = true;
            #pragma unroll
            for (int m = 0; m < 2; m++)
                #pragma unroll
                for (int ks = 0; ks < 4; ks++) {
                    int arow = wm * 32 + m * 16 + (lane & 7) + (matX & 1) * 8;
                    int aseg = ks * 2 + (matX >> 1);
                    uint32_t off = (uint32_t)(arow * 128 + ((aseg ^ (arow & 7)) << 4));
                    LDSM4(qf[m][ks], sbase + off);
                }
        }

        int s0 = c_fB[tt][i] * 128;
        uint32_t kb = sbase + 16384 + (i & 1) * 32768;
        uint32_t vb = kb + 16384;

        // ---- S = Q K^T (my m32 x n64 part) ----
        float sacc[2][8][4];
        #pragma unroll
        for (int m = 0; m < 2; m++)
            #pragma unroll
            for (int j = 0; j < 8; j++)
                #pragma unroll
                for (int q = 0; q < 4; q++) sacc[m][j][q] = 0.f;

        #pragma unroll
        for (int ks = 0; ks < 4; ks++) {
            #pragma unroll
            for (int np = 0; np < 4; np++) {
                uint32_t bf[4];
                int brow = wn * 64 + np * 16 + ((matX >> 1) << 3) + (lane & 7);
                int bseg = ks * 2 + (matX & 1);
                uint32_t boff = (uint32_t)(brow * 128 + ((bseg ^ (brow & 7)) << 4));
                LDSM4(bf, kb + boff);
                #pragma unroll
                for (int m = 0; m < 2; m++)
                    #pragma unroll
                    for (int t2 = 0; t2 < 2; t2++)
                        mma16816(sacc[m][np * 2 + t2], qf[m][ks], bf + 2 * t2);
            }
        }

        // ---- scale + mask + local row max ----
        float lmax[2][2];
        #pragma unroll
        for (int m = 0; m < 2; m++) { lmax[m][0] = -3.0e38f; lmax[m][1] = -3.0e38f; }
        #pragma unroll
        for (int m = 0; m < 2; m++)
            #pragma unroll
            for (int hh = 0; hh < 2; hh++) {
                int r = t0 + wm * 32 + m * 16 + hh * 8 + r_l;
                #pragma unroll
                for (int j = 0; j < 8; j++) {
                    int cc = s0 + wn * 64 + j * 8 + c_l;
                    float v0 = keep_fn(r, cc)     ? sacc[m][j][2*hh]   * SCALE_QK : -3.0e38f;
                    float v1 = keep_fn(r, cc + 1) ? sacc[m][j][2*hh+1] * SCALE_QK : -3.0e38f;
                    sacc[m][j][2*hh]   = v0;
                    sacc[m][j][2*hh+1] = v1;
                    lmax[m][hh] = fmaxf(lmax[m][hh], fmaxf(v0, v1));
                }
            }
        // quad reduce
        #pragma unroll
        for (int m = 0; m < 2; m++)
            #pragma unroll
            for (int hh = 0; hh < 2; hh++) {
                float mx = lmax[m][hh];
                mx = fmaxf(mx, __shfl_xor_sync(0xffffffff, mx, 1));
                mx = fmaxf(mx, __shfl_xor_sync(0xffffffff, mx, 2));
                lmax[m][hh] = mx;
            }
        // cross-wn exchange (max)
        if ((lane & 3) == 0) {
            #pragma unroll
            for (int m = 0; m < 2; m++)
                #pragma unroll
                for (int hh = 0; hh < 2; hh++)
                    mxbuf[wn * 128 + wm * 32 + m * 16 + hh * 8 + r_l] = lmax[m][hh];
        }
        __syncthreads();
        float mnew[2][2], alpha[2][2];
        #pragma unroll
        for (int m = 0; m < 2; m++)
            #pragma unroll
            for (int hh = 0; hh < 2; hh++) {
                int rl = wm * 32 + m * 16 + hh * 8 + r_l;
                float mb = fmaxf(mxbuf[rl], mxbuf[128 + rl]);
                float mn = fmaxf(mrow[m][hh], mb);
                mnew[m][hh] = mn;
                alpha[m][hh] = __expf(mrow[m][hh] - mn);
            }
        // ---- P = exp(S - mnew), local row sum ----
        float lsum[2][2] = {{0.f, 0.f}, {0.f, 0.f}};
        #pragma unroll
        for (int m = 0; m < 2; m++)
            #pragma unroll
            for (int hh = 0; hh < 2; hh++) {
                float mn = mnew[m][hh];
                #pragma unroll
                for (int j = 0; j < 8; j++) {
                    float v0 = sacc[m][j][2*hh];
                    float v1 = sacc[m][j][2*hh+1];
                    v0 = (v0 > -1.0e38f) ? __expf(v0 - mn) : 0.f;
                    v1 = (v1 > -1.0e38f) ? __expf(v1 - mn) : 0.f;
                    sacc[m][j][2*hh]   = v0;
                    sacc[m][j][2*hh+1] = v1;
                    lsum[m][hh] += v0 + v1;
                }
            }
        #pragma unroll
        for (int m = 0; m < 2; m++)
            #pragma unroll
            for (int hh = 0; hh < 2; hh++) {
                float s = lsum[m][hh];
                s += __shfl_xor_sync(0xffffffff, s, 1);
                s += __shfl_xor_sync(0xffffffff, s, 2);
                lsum[m][hh] = s;
            }
        if ((lane & 3) == 0) {
            #pragma unroll
            for (int m = 0; m < 2; m++)
                #pragma unroll
                for (int hh = 0; hh < 2; hh++)
                    lsbuf[wn * 128 + wm * 32 + m * 16 + hh * 8 + r_l] = lsum[m][hh];
        }
        __syncthreads();
        #pragma unroll
        for (int m = 0; m < 2; m++)
            #pragma unroll
            for (int hh = 0; hh < 2; hh++) {
                int rl = wm * 32 + m * 16 + hh * 8 + r_l;
                float lb = lsbuf[rl] + lsbuf[128 + rl];
                lrow[m][hh] = lrow[m][hh] * alpha[m][hh] + lb;
                mrow[m][hh] = mnew[m][hh];
                // rescale O
                #pragma unroll
                for (int j = 0; j < 8; j++) {
                    oacc[m][j][2*hh]   *= alpha[m][hh];
                    oacc[m][j][2*hh+1] *= alpha[m][hh];
                }
            }
        // ---- O += P * V (contraction over my s-half 64) ----
        #pragma unroll
        for (int kf = 0; kf < 4; kf++) {
            uint32_t vf[4][4];
            #pragma unroll
            for (int nf = 0; nf < 4; nf++) {
                int vrow = nf * 16 + ((matX >> 1) << 3) + (lane & 7);
                int vseg = wn * 8 + kf * 2 + (matX & 1);
                LDSM4(vf[nf], vb + swz256(vrow, vseg));
            }
            #pragma unroll
            for (int m = 0; m < 2; m++) {
                uint32_t pf[4];
                __half2 p0 = __floats2half2_rn(sacc[m][2*kf][0],   sacc[m][2*kf][1]);
                __half2 p1 = __floats2half2_rn(sacc[m][2*kf][2],   sacc[m][2*kf][3]);
                __half2 p2 = __floats2half2_rn(sacc[m][2*kf+1][0], sacc[m][2*kf+1][1]);
                __half2 p3 = __floats2half2_rn(sacc[m][2*kf+1][2], sacc[m][2*kf+1][3]);
                pf[0] = *(uint32_t*)&p0; pf[1] = *(uint32_t*)&p1;
                pf[2] = *(uint32_t*)&p2; pf[3] = *(uint32_t*)&p3;
                #pragma unroll
                for (int nf = 0; nf < 4; nf++)
                    #pragma unroll
                    for (int t2 = 0; t2 < 2; t2++)
                        mma16816(oacc[m][nf * 2 + t2], pf, vf[nf] + 2 * t2);
            }
        }
    }

    // ---- combine wn partials, divide by l, store ----
    __syncthreads();
    if (wn == 1) {
        #pragma unroll
        for (int m = 0; m < 2; m++)
            #pragma unroll
            for (int hh = 0; hh < 2; hh++) {
                int rl = wm * 32 + m * 16 + hh * 8 + r_l;
                #pragma unroll
                for (int j = 0; j < 8; j++) {
                    obuf[rl * 64 + j * 8 + c_l]     = oacc[m][j][2*hh];
                    obuf[rl * 64 + j * 8 + c_l + 1] = oacc[m][j][2*hh+1];
                }
            }
    }
    __syncthreads();
    if (wn == 0) {
        #pragma unroll
        for (int m = 0; m < 2; m++)
            #pragma unroll
            for (int hh = 0; hh < 2; hh++) {
                int rl = wm * 32 + m * 16 + hh * 8 + r_l;
                int rr = t0 + rl;
                if (rr >= Tv) continue;
                float linv = 1.f / lrow[m][hh];
                #pragma unroll
                for (int j = 0; j < 8; j++) {
                    float v0 = (oacc[m][j][2*hh]   + obuf[rl * 64 + j * 8 + c_l])     * linv;
                    float v1 = (oacc[m][j][2*hh+1] + obuf[rl * 64 + j * 8 + c_l + 1]) * linv;
                    __half2 hv = __floats2half2_rn(v0, v1);
                    *(__half2*)(O + ((size_t)(b * Tv + rr)) * Ev + h * HSv + j * 8 + c_l) = hv;
                }
            }
    }
}

// ---------------- fp32 GEMM (head only) ----------------
__global__ void __launch_bounds__(256, 2)
sgemm128(int M, int N, int K,
         const float* __restrict__ A, int lda,
         const float* __restrict__ B, int ldb,
         float* __restrict__ C, int ldc,
         const float* __restrict__ bias, int reluflag)
{
    __shared__ __align__(16) float As[8][128];
    __shared__ __align__(16) float Bs[8][128];
    int n0 = blockIdx.x * 128, m0 = blockIdx.y * 128;
    int tid = threadIdx.x;
    int tx = tid & 15, ty = tid >> 4;
    int arow = tid >> 1,  akk  = (tid & 1) * 4;
    int bkk  = tid >> 5,  bcol = (tid & 31) * 4;
    bool aval = (m0 + arow) < M;
    bool bval = (n0 + bcol) < N;
    const float* Aptr = A + (size_t)(m0 + arow) * lda + akk;
    const float* Bptr = B + (size_t)bkk * ldb + n0 + bcol;
    float acc[8][8];
    #pragma unroll
    for (int i = 0; i < 8; i++)
        #pragma unroll
        for (int j = 0; j < 8; j++) acc[i][j] = 0.f;
    for (int k0 = 0; k0 < K; k0 += 8) {
        float4 av = make_float4(0.f,0.f,0.f,0.f), bv = make_float4(0.f,0.f,0.f,0.f);
        if (aval) av = *(const float4*)(Aptr + k0);
        if (bval) bv = *(const float4*)(Bptr + (size_t)k0 * ldb);
        __syncthreads();
        As[akk+0][arow] = av.x; As[akk+1][arow] = av.y;
        As[akk+2][arow] = av.z; As[akk+3][arow] = av.w;
        *(float4*)&Bs[bkk][bcol] = bv;
        __syncthreads();
        #pragma unroll
        for (int kk = 0; kk < 8; kk++) {
            float a[8], b2[8];
            *(float4*)(a)    = *(const float4*)&As[kk][ty*8];
            *(float4*)(a+4)  = *(const float4*)&As[kk][ty*8+4];
            *(float4*)(b2)   = *(const float4*)&Bs[kk][tx*8];
            *(float4*)(b2+4) = *(const float4*)&Bs[kk][tx*8+4];
            #pragma unroll
            for (int i = 0; i < 8; i++)
                #pragma unroll
                for (int j = 0; j < 8; j++)
                    acc[i][j] += a[i] * b2[j];
        }
    }
    #pragma unroll
    for (int i = 0; i < 8; i++) {
        int r = m0 + ty*8 + i;
        if (r >= M) continue;
        #pragma unroll
        for (int j = 0; j < 8; j++) {
            int c = n0 + tx*8 + j;
            if (c >= N) continue;
            float v = acc[i][j];
            if (bias) v += bias[c];
            if (reluflag) v = fmaxf(v, 0.f);
            C[(size_t)r * ldc + c] = v;
        }
    }
}

// ---------------- launch ----------------
extern "C" void kernel_launch(void* const* d_in, const int* in_sizes, int n_in,
                              void* d_out, int out_size) {
    const float* images     = (const float*)d_in[0];
    const int*   goals_txt  = (const int*)  d_in[1];
    const float* goal_imgs  = (const float*)d_in[2];
    const float* patch_w    = (const float*)d_in[3];
    const float* patch_b    = (const float*)d_in[4];
    const float* text_emb   = (const float*)d_in[5];
    const float* action_emb = (const float*)d_in[6];
    const float* wq         = (const float*)d_in[7];
    const float* wk         = (const float*)d_in[8];
    const float* wv         = (const float*)d_in[9];
    const float* proj_w     = (const float*)d_in[10];
    const float* proj_b     = (const float*)d_in[11];
    const float* ln1_s      = (const float*)d_in[12];
    const float* ln1_b      = (const float*)d_in[13];
    const float* ln2_s      = (const float*)d_in[14];
    const float* ln2_b      = (const float*)d_in[15];
    const float* ff_w1      = (const float*)d_in[16];
    const float* ff_b1      = (const float*)d_in[17];
    const float* ff_w2      = (const float*)d_in[18];
    const float* ff_b2      = (const float*)d_in[19];
    const float* hw1        = (const float*)d_in[20];
    const float* hb1        = (const float*)d_in[21];
    const float* hw2        = (const float*)d_in[22];
    const float* hb2        = (const float*)d_in[23];
    float* out = (float*)d_out;

    cudaFuncSetAttribute(tgemm, cudaFuncAttributeMaxDynamicSharedMemorySize, TGSMEM);
    cudaFuncSetAttribute(fattn, cudaFuncAttributeMaxDynamicSharedMemorySize, FASMEM);

    float *pPOS, *pX, *pZ;
    h16 *pH, *pO, *pF, *pXP, *pQ, *pVt;
    h16 *pWq, *pWp, *pW1, *pW2, *pWt;
    cudaGetSymbolAddress((void**)&pPOS, g_POS);
    cudaGetSymbolAddress((void**)&pX,   g_X);
    cudaGetSymbolAddress((void**)&pZ,   g_Z);
    cudaGetSymbolAddress((void**)&pH,   g_H);
    cudaGetSymbolAddress((void**)&pO,   g_O);
    cudaGetSymbolAddress((void**)&pF,   g_F);
    cudaGetSymbolAddress((void**)&pXP,  g_XP);
    cudaGetSymbolAddress((void**)&pQ,   g_QKV);
    cudaGetSymbolAddress((void**)&pVt,  g_Vt);
    cudaGetSymbolAddress((void**)&pWq,  g_Wqkv);
    cudaGetSymbolAddress((void**)&pWp,  g_Wprj);
    cudaGetSymbolAddress((void**)&pW1,  g_Wf1);
    cudaGetSymbolAddress((void**)&pW2,  g_Wf2);
    cudaGetSymbolAddress((void**)&pWt,  g_Wpat);

    // ---- prep (launch #4 = dummy QKV-shaped tgemm probe for ncu -s 5 -c 1) ----
    pos_kernel    <<<CDIV(Tv*Ev, 256), 256>>>(pPOS);                                  // 1
    conv_wqkv     <<<dim3(2, 24, Lv*3*Hv), dim3(32,8)>>>(wq, wk, wv, pWq);            // 2
    transpose_conv<<<dim3(24, 24, Lv), dim3(32,8)>>>(proj_w, pWp, Ev, Ev);            // 3
    tgemm<<<dim3(QKVLD/128, 10), 256, TGSMEM>>>(                                       // 4 (probe)
        2560, QKVLD, Ev, pXP, pWq,
        nullptr, nullptr, 0, 0, (float*)pF, QKVLD, 0, 0, nullptr);
    transpose_conv<<<dim3(96, 24, Lv), dim3(32,8)>>>(ff_w1, pW1, Ev, E4);             // 5
    transpose_conv<<<dim3(24, 96, Lv), dim3(32,8)>>>(ff_w2, pW2, E4, Ev);             // 6
    transpose_conv<<<dim3(24, 24, 1),  dim3(32,8)>>>(patch_w, pWt, Ev, Ev);
    gather_patches<<<CDIV(MPATCH*Ev, 256), 256>>>(images, goal_imgs, pXP);
    embed_txt_act <<<CDIV(Bv*33*Ev, 256), 256>>>(goals_txt, text_emb, action_emb, pPOS, pX);

    // patch embed -> X rows 32..619 (+bias +POS)
    tgemm<<<dim3(Ev/128, CDIV(MPATCH,256)), 256, TGSMEM>>>(
        MPATCH, Ev, Ev, pXP, pWt,
        patch_b, pPOS, Ev, 1,
        pX, Ev, 0, 0, nullptr);

    for (int l = 0; l < Lv; l++) {
        ln_kernel<<<CDIV(MTv,8), 256>>>(pX, pH, ln1_s + l*Ev, ln1_b + l*Ev);

        tgemm<<<dim3(QKVLD/128, CDIV(MTv,256)), 256, TGSMEM>>>(   // QKV -> fp16
            MTv, QKVLD, Ev, pH, pWq + (size_t)l*QKVLD*Ev,
            nullptr, nullptr, 0, 0,
            nullptr, 0, 0, 0, pQ);

        repack_v<<<dim3(TP/32, HSv/32, ZH), dim3(32,8)>>>(pQ, pVt);
        fattn   <<<dim3(5, ZH), 256, FASMEM>>>(pQ, pVt, pO);

        tgemm<<<dim3(Ev/128, CDIV(MTv,256)), 256, TGSMEM>>>(   // X += O @ proj + b
            MTv, Ev, Ev, pO, pWp + (size_t)l*Ev*Ev,
            proj_b + l*Ev, nullptr, 0, 0,
            pX, Ev, 1, 0, nullptr);

        ln_kernel<<<CDIV(MTv,8), 256>>>(pX, pH, ln2_s + l*Ev, ln2_b + l*Ev);

        tgemm<<<dim3(E4/128, CDIV(MTv,256)), 256, TGSMEM>>>(   // F = relu(h@W1+b1) -> fp16
            MTv, E4, Ev, pH, pW1 + (size_t)l*E4*Ev,
            ff_b1 + l*E4, nullptr, 0, 0,
            nullptr, 0, 0, 1, pF);

        tgemm<<<dim3(Ev/128, CDIV(MTv,256)), 256, TGSMEM>>>(   // X += F @ W2 + b2
            MTv, Ev, E4, pF, pW2 + (size_t)l*Ev*E4,
            ff_b2 + l*Ev, nullptr, 0, 0,
            pX, Ev, 1, 0, nullptr);
    }

    // head
    sgemm128<<<dim3(Ev/128, 1), 256>>>(
        Bv, Ev, Ev, pX + (size_t)620*Ev, Tv*Ev, hw1, Ev, pZ, Ev, hb1, 1);
    sgemm128<<<dim3(1, 1), 256>>>(
        Bv, AOUTv, Ev, pZ, Ev, hw2, AOUTv, out, AOUTv, hb2, 0);

    (void)in_sizes; (void)n_in; (void)out_size;
}

// round 15
// speedup vs baseline: 3.1963x; 1.0111x over previous
#include <cuda_runtime.h>
#include <cuda_fp16.h>
#include <math.h>
#include <stdint.h>
#include <stddef.h>

// ---------------- problem constants ----------------
#define Bv      16
#define Kv      2
#define Ev      768
#define Hv      12
#define HSv     64
#define Lv      12
#define Tv      621
#define TP      640
#define NPATCH  588
#define QKVLD   2304
#define E4      3072
#define AOUTv   64
#define MTv     (Bv*Tv)      // 9936
#define MPATCH  (Bv*NPATCH)  // 9408
#define ZH      (Bv*Hv)      // 192
#define SCALE_QK 0.036084391824351615f

#define CDIV(a,b) (((a)+(b)-1)/(b))
#define TGSMEM   196608      // 2 stages x 96KB (A 64K + B 32K)
#define FASMEM   83968       // Q 16K + 2x(K16K+V16K) + stats 2K

typedef __half h16;

// ---------------- scratch ----------------
__device__ __align__(128) float g_POS[Tv*Ev];
__device__ __align__(128) float g_X  [(size_t)MTv*Ev];
__device__ __align__(128) float g_Z  [Bv*Ev];

__device__ __align__(128) h16 g_H  [(size_t)MTv*Ev];
__device__ __align__(128) h16 g_O  [(size_t)MTv*Ev];
__device__ __align__(128) h16 g_F  [(size_t)MTv*E4];
__device__ __align__(128) h16 g_XP [(size_t)MPATCH*Ev];
__device__ __align__(128) h16 g_QKV[(size_t)MTv*QKVLD];
__device__ __align__(128) h16 g_Vt [(size_t)ZH*HSv*TP];

__device__ __align__(128) h16 g_Wqkv[(size_t)Lv*QKVLD*Ev];
__device__ __align__(128) h16 g_Wprj[(size_t)Lv*Ev*Ev];
__device__ __align__(128) h16 g_Wf1 [(size_t)Lv*E4*Ev];
__device__ __align__(128) h16 g_Wf2 [(size_t)Lv*Ev*E4];
__device__ __align__(128) h16 g_Wpat[(size_t)Ev*Ev];

// ---------------- mask-derived live s-block lists per t-tile ----------------
__constant__ int c_fN[5] = {1, 4, 4, 5, 5};
__constant__ int c_fB[5][5] = {
    {0, 0, 0, 0, 0},
    {0, 1, 2, 3, 0},
    {0, 1, 2, 3, 0},
    {0, 1, 2, 3, 4},
    {0, 1, 2, 3, 4}
};

// ---------------- helpers ----------------
__device__ __forceinline__ uint32_t smem_u32(const void* p) {
    uint32_t a;
    asm("{ .reg .u64 t; cvta.to.shared.u64 t, %1; cvt.u32.u64 %0, t; }" : "=r"(a) : "l"(p));
    return a;
}
__device__ __forceinline__ void cp16(uint32_t sa, const void* ga, bool v) {
    int sz = v ? 16 : 0;
    asm volatile("cp.async.cg.shared.global [%0], [%1], 16, %2;" :: "r"(sa), "l"(ga), "r"(sz) : "memory");
}
#define CP_COMMIT() asm volatile("cp.async.commit_group;" ::: "memory")
#define CP_WAIT0()  asm volatile("cp.async.wait_group 0;" ::: "memory")

#define LDSM4(r, a) \
    asm volatile("ldmatrix.sync.aligned.m8n8.x4.shared.b16 {%0,%1,%2,%3}, [%4];" \
        : "=r"((r)[0]),"=r"((r)[1]),"=r"((r)[2]),"=r"((r)[3]) : "r"(a))

__device__ __forceinline__ void mma16816(float* d, const uint32_t* a, const uint32_t* b) {
    asm volatile("mma.sync.aligned.m16n8k16.row.col.f32.f16.f16.f32 "
        "{%0,%1,%2,%3}, {%4,%5,%6,%7}, {%8,%9}, {%0,%1,%2,%3};"
        : "+f"(d[0]),"+f"(d[1]),"+f"(d[2]),"+f"(d[3])
        : "r"(a[0]),"r"(a[1]),"r"(a[2]),"r"(a[3]), "r"(b[0]),"r"(b[1]));
}

// 256B-row swizzled offset; seg = 16B unit index 0..15
__device__ __forceinline__ uint32_t swz256(int row, int seg) {
    return (uint32_t)(row * 256 + ((seg & 8) << 4) + (((seg & 7) ^ (row & 7)) << 4));
}

// ---------------- mask ----------------
__device__ __forceinline__ bool keep_fn(int t, int s) {
    bool v = (t == s);
    if (s < 32) v = !(t >= 32 && t < 228);
    if (t >= 228 && s >= 228 && s < 424) v = true;
    if (t >= 424 && s >= 424 && s < 620) v = true;
    return v;
}

// ---------------- positional embedding ----------------
__global__ void pos_kernel(float* POS) {
    int idx = blockIdx.x * 256 + threadIdx.x;
    if (idx >= Tv * Ev) return;
    int t = idx / Ev, j = idx % Ev;
    double expo = (double)(j & ~1) / (double)Ev;
    double ang  = (double)t / pow(10000.0, expo);
    POS[idx] = (float)((j & 1) ? cos(ang) : sin(ang));
}

// ---------------- transpose+convert weights ----------------
__global__ void transpose_conv(const float* __restrict__ src, h16* __restrict__ dst, int R, int C) {
    __shared__ float t[32][33];
    int z = blockIdx.z;
    src += (size_t)z * R * C; dst += (size_t)z * R * C;
    int c0 = blockIdx.x * 32, r0 = blockIdx.y * 32;
    int tx = threadIdx.x, ty = threadIdx.y;
    #pragma unroll
    for (int i = 0; i < 4; i++)
        t[ty + 8*i][tx] = src[(size_t)(r0 + ty + 8*i) * C + c0 + tx];
    __syncthreads();
    #pragma unroll
    for (int i = 0; i < 4; i++)
        dst[(size_t)(c0 + ty + 8*i) * R + r0 + tx] = __float2half(t[tx][ty + 8*i]);
}

__global__ void conv_wqkv(const float* __restrict__ wq, const float* __restrict__ wk,
                          const float* __restrict__ wv, h16* __restrict__ dst) {
    __shared__ float t[32][33];
    int z = blockIdx.z;
    int h = z % Hv, which = (z / Hv) % 3, l = z / (3 * Hv);
    const float* src = (which == 0) ? wq : (which == 1) ? wk : wv;
    src += ((size_t)l * Hv + h) * Ev * HSv;
    int d0 = blockIdx.x * 32, e0 = blockIdx.y * 32;
    int tx = threadIdx.x, ty = threadIdx.y;
    #pragma unroll
    for (int i = 0; i < 4; i++)
        t[ty + 8*i][tx] = src[(size_t)(e0 + ty + 8*i) * HSv + d0 + tx];
    __syncthreads();
    #pragma unroll
    for (int i = 0; i < 4; i++) {
        int d = d0 + ty + 8*i, e = e0 + tx;
        dst[((size_t)l * QKVLD + which * Ev + h * HSv + d) * Ev + e] = __float2half(t[tx][ty + 8*i]);
    }
}

// ---------------- gather patches -> fp16 ----------------
__global__ void gather_patches(const float* __restrict__ images, const float* __restrict__ goal_imgs,
                               h16* __restrict__ X) {
    int idx = blockIdx.x * 256 + threadIdx.x;
    if (idx >= MPATCH * Ev) return;
    int f = idx % Ev;
    int r = idx / Ev;
    int p = r % NPATCH;
    int b = r / NPATCH;
    int py = f / 48, px = (f % 48) / 3, c = f % 3;
    float val;
    if (p < 196) {
        int pr = p / 14, pc = p % 14;
        int y = pr * 16 + py, x = pc * 16 + px;
        val = goal_imgs[(((size_t)b * 224 + y) * 224 + x) * 3 + c];
    } else {
        int q = p - 196;
        int k = q / 196, pp = q % 196;
        int pr = pp / 14, pc = pp % 14;
        int y = pr * 16 + py, x = pc * 16 + px;
        val = images[((((size_t)b * Kv + k) * 224 + y) * 224 + x) * 3 + c];
    }
    X[idx] = __float2half(val);
}

// ---------------- text + action embed (+POS) ----------------
__global__ void embed_txt_act(const int* __restrict__ goals_txt, const float* __restrict__ text_emb,
                              const float* __restrict__ action_emb, const float* __restrict__ POS,
                              float* __restrict__ X) {
    int idx = blockIdx.x * 256 + threadIdx.x;
    if (idx >= Bv * 33 * Ev) return;
    int e  = idx % Ev;
    int r  = idx / Ev;
    int tt = r % 33;
    int b  = r / 33;
    int t  = (tt < 32) ? tt : 620;
    float v = (tt < 32) ? text_emb[(size_t)goals_txt[b * 32 + tt] * Ev + e] : action_emb[e];
    X[((size_t)b * Tv + t) * Ev + e] = v + POS[(size_t)t * Ev + e];
}

// ---------------- layernorm: warp per row, shuffle reduce -> fp16 ----------------
__global__ void ln_kernel(const float* __restrict__ X, h16* __restrict__ Out,
                          const float* __restrict__ sc, const float* __restrict__ bi) {
    int w = threadIdx.x >> 5, lane = threadIdx.x & 31;
    int row = blockIdx.x * 8 + w;
    if (row >= MTv) return;
    const float* x = X + (size_t)row * Ev;
    float4 v[6];
    float s = 0.f, ss = 0.f;
    #pragma unroll
    for (int i = 0; i < 6; i++) {
        v[i] = *(const float4*)(x + i * 128 + lane * 4);
        s  += v[i].x + v[i].y + v[i].z + v[i].w;
        ss += v[i].x*v[i].x + v[i].y*v[i].y + v[i].z*v[i].z + v[i].w*v[i].w;
    }
    #pragma unroll
    for (int off = 16; off; off >>= 1) {
        s  += __shfl_xor_sync(0xffffffff, s,  off);
        ss += __shfl_xor_sync(0xffffffff, ss, off);
    }
    float m   = s * (1.f / Ev);
    float var = ss * (1.f / Ev) - m * m;
    float inv = rsqrtf(var + 1e-5f);
    #pragma unroll
    for (int i = 0; i < 6; i++) {
        int col = i * 128 + lane * 4;
        float o0 = (v[i].x - m) * inv * sc[col]   + bi[col];
        float o1 = (v[i].y - m) * inv * sc[col+1] + bi[col+1];
        float o2 = (v[i].z - m) * inv * sc[col+2] + bi[col+2];
        float o3 = (v[i].w - m) * inv * sc[col+3] + bi[col+3];
        __half2 h0 = __floats2half2_rn(o0, o1);
        __half2 h1 = __floats2half2_rn(o2, o3);
        uint2 u = make_uint2(*(uint32_t*)&h0, *(uint32_t*)&h1);
        *(uint2*)(Out + (size_t)row * Ev + col) = u;
    }
}

// =====================================================================
// fp16 GEMM (mma.sync m16n8k16), 256x128 CTA tile, 256 threads,
// warp tile 64x64, Kc=128, 2-stage cp.async pipeline.
// =====================================================================
__global__ void __launch_bounds__(256, 1)
tgemm(int M, int N, int K,
      const h16* __restrict__ A, const h16* __restrict__ B,
      const float* __restrict__ bias,
      const float* __restrict__ rowmat, int ldrm, int rmode,
      float* outF, int ldo, int accf, int reluf,
      h16* outH)
{
    extern __shared__ char sm[];
    uint32_t sbase = smem_u32(sm);
    int tid = threadIdx.x, lane = tid & 31, wid = tid >> 5;
    int m0 = blockIdx.y * 256, n0 = blockIdx.x * 128;
    int wm = wid & 3, wn = wid >> 2;

    float acc[4][8][4];
    #pragma unroll
    for (int i = 0; i < 4; i++)
        #pragma unroll
        for (int j = 0; j < 8; j++)
            #pragma unroll
            for (int q = 0; q < 4; q++) acc[i][j][q] = 0.f;

    int nc = K >> 7;

    auto ld_st = [&](int c, int st, bool active) {
        if (active) {
            uint32_t sb = sbase + st * 98304;
            int k0 = c * 128;
            #pragma unroll
            for (int i = 0; i < 16; i++) {
                int u = i * 256 + tid;
                int row = u >> 4, seg = u & 15;
                uint32_t off = swz256(row, seg);
                bool av = (m0 + row) < M;
                size_t ao = (size_t)(av ? (m0 + row) : 0) * K + k0 + seg * 8;
                cp16(sb + off, A + ao, av);
            }
            #pragma unroll
            for (int i = 0; i < 8; i++) {
                int u = i * 256 + tid;
                int row = u >> 4, seg = u & 15;
                uint32_t off = swz256(row, seg);
                size_t bo = (size_t)(n0 + row) * K + k0 + seg * 8;
                cp16(sb + 65536 + off, B + bo, true);
            }
        }
        CP_COMMIT();
    };

    ld_st(0, 0, true);

    int matA = lane >> 3;
    int matB = lane >> 3;

    for (int c = 0; c < nc; c++) {
        CP_WAIT0();
        __syncthreads();
        ld_st(c + 1, (c + 1) & 1, c + 1 < nc);

        uint32_t sA = sbase + (c & 1) * 98304;
        uint32_t sB = sA + 65536;

        #pragma unroll
        for (int ks = 0; ks < 8; ks++) {
            uint32_t bf[4][4];
            #pragma unroll
            for (int np = 0; np < 4; np++) {
                int brow = wn * 64 + np * 16 + ((matB >> 1) << 3) + (lane & 7);
                int bseg = ks * 2 + (matB & 1);
                LDSM4(bf[np], sB + swz256(brow, bseg));
            }
            uint32_t af[2][4];
            {
                int arow = wm * 64 + (lane & 7) + (matA & 1) * 8;
                int aseg = ks * 2 + (matA >> 1);
                LDSM4(af[0], sA + swz256(arow, aseg));
            }
            #pragma unroll
            for (int mt = 0; mt < 4; mt++) {
                int cur = mt & 1, nxt = cur ^ 1;
                if (mt < 3) {
                    int arow = wm * 64 + (mt + 1) * 16 + (lane & 7) + (matA & 1) * 8;
                    int aseg = ks * 2 + (matA >> 1);
                    LDSM4(af[nxt], sA + swz256(arow, aseg));
                }
                #pragma unroll
                for (int np = 0; np < 4; np++)
                    #pragma unroll
                    for (int t = 0; t < 2; t++)
                        mma16816(acc[mt][np * 2 + t], af[cur], bf[np] + 2 * t);
            }
        }
    }

    int r_l = lane >> 2, c_l = (lane & 3) * 2;
    #pragma unroll
    for (int mt = 0; mt < 4; mt++) {
        #pragma unroll
        for (int h = 0; h < 2; h++) {
            int rr = m0 + wm * 64 + mt * 16 + h * 8 + r_l;
            if (rr >= M) continue;
            int orow = rr, prow = rr;
            if (rmode) {
                int b = rr / NPATCH, p = rr - b * NPATCH;
                orow = b * Tv + 32 + p;
                prow = 32 + p;
            }
            #pragma unroll
            for (int j = 0; j < 8; j++) {
                int col = n0 + wn * 64 + j * 8 + c_l;
                float v0 = acc[mt][j][2 * h];
                float v1 = acc[mt][j][2 * h + 1];
                if (bias)   { v0 += bias[col]; v1 += bias[col + 1]; }
                if (rowmat) { const float* rp = rowmat + (size_t)prow * ldrm + col; v0 += rp[0]; v1 += rp[1]; }
                if (accf)   { const float* op = outF + (size_t)orow * ldo + col;   v0 += op[0]; v1 += op[1]; }
                if (reluf)  { v0 = fmaxf(v0, 0.f); v1 = fmaxf(v1, 0.f); }
                if (outF)   *(float2*)(outF + (size_t)orow * ldo + col) = make_float2(v0, v1);
                if (outH) {
                    size_t o = (size_t)rr * N + col;
                    __half2 hv = __floats2half2_rn(v0, v1);
                    *(__half2*)(outH + o) = hv;
                }
            }
        }
    }
}

// ---------------- V repack: QKV v-part -> Vt[z][d][s] fp16 (s padded 0) ----------------
__global__ void repack_v(const h16* __restrict__ Q, h16* __restrict__ Vt)
{
    __shared__ h16 th[32][33];
    int z = blockIdx.z, b = z / Hv, h = z % Hv;
    int s0 = blockIdx.x * 32, d0 = blockIdx.y * 32;
    int tx = threadIdx.x, ty = threadIdx.y;
    #pragma unroll
    for (int i = 0; i < 4; i++) {
        int s = s0 + ty + 8 * i;
        h16 vh = __float2half(0.f);
        if (s < Tv)
            vh = Q[(size_t)(b * Tv + s) * QKVLD + 2 * Ev + h * HSv + d0 + tx];
        th[ty + 8 * i][tx] = vh;
    }
    __syncthreads();
    #pragma unroll
    for (int i = 0; i < 4; i++)
        Vt[((size_t)z * HSv + d0 + ty + 8 * i) * TP + s0 + tx] = th[tx][ty + 8 * i];
}

// =====================================================================
// fattn v2: fused flash attention, INDEPENDENT online softmax per wn
// s-half (no mid-loop cross-warp exchange; single sync per s-block).
// Final combine rescales the two halves by their running maxima.
// smem: Q @0 (16K), stage{0,1}: K @16K/48K, V @32K/64K,
//       mx @80K, ls @81K, obuf fp32 @16K (reuses stages post-loop).
// =====================================================================
__global__ void __launch_bounds__(256, 1)
fattn(const h16* __restrict__ QKV, const h16* __restrict__ Vt, h16* __restrict__ O)
{
    extern __shared__ char sm[];
    uint32_t sbase = smem_u32(sm);
    float* mxbuf = (float*)(sm + 81920);   // [128]
    float* lsbuf = (float*)(sm + 82944);   // [128]
    float* obuf  = (float*)(sm + 16384);   // [128][64] fp32 (reuse stages)

    int tid = threadIdx.x, lane = tid & 31, wid = tid >> 5;
    int wm = wid >> 1, wn = wid & 1;
    int tt = blockIdx.x, z = blockIdx.y, b = z / Hv, h = z % Hv;
    int t0 = tt * 128;
    int nblk = c_fN[tt];
    int matX = lane >> 3;
    int r_l = lane >> 2, c_l = (lane & 3) * 2;

    auto ldQ = [&]() {
        #pragma unroll
        for (int i = 0; i < 4; i++) {
            int u = i * 256 + tid;
            int row = u >> 3, seg = u & 7;
            uint32_t off = (uint32_t)(row * 128 + ((seg ^ (row & 7)) << 4));
            bool v = (t0 + row) < Tv;
            size_t qo = (size_t)(b * Tv + (v ? t0 + row : 0)) * QKVLD + h * HSv + seg * 8;
            cp16(sbase + off, QKV + qo, v);
        }
    };
    auto ldKV = [&](int blk_i, int st, bool active) {
        if (active) {
            int s0 = c_fB[tt][blk_i] * 128;
            uint32_t kb = sbase + 16384 + st * 32768;
            uint32_t vb = kb + 16384;
            #pragma unroll
            for (int i = 0; i < 4; i++) {
                int u = i * 256 + tid;
                int row = u >> 3, seg = u & 7;
                uint32_t off = (uint32_t)(row * 128 + ((seg ^ (row & 7)) << 4));
                bool v = (s0 + row) < Tv;
                size_t ko = (size_t)(b * Tv + (v ? s0 + row : 0)) * QKVLD + Ev + h * HSv + seg * 8;
                cp16(kb + off, QKV + ko, v);
            }
            #pragma unroll
            for (int i = 0; i < 4; i++) {
                int u = i * 256 + tid;
                int row = u >> 4, seg = u & 15;
                size_t vo = ((size_t)z * HSv + row) * TP + s0 + seg * 8;
                cp16(vb + swz256(row, seg), Vt + vo, true);
            }
        }
        CP_COMMIT();
    };

    float oacc[2][8][4];
    #pragma unroll
    for (int m = 0; m < 2; m++)
        #pragma unroll
        for (int j = 0; j < 8; j++)
            #pragma unroll
            for (int q = 0; q < 4; q++) oacc[m][j][q] = 0.f;
    float mrow[2][2], lrow[2][2];
    #pragma unroll
    for (int m = 0; m < 2; m++) { mrow[m][0] = mrow[m][1] = -3.0e38f; lrow[m][0] = lrow[m][1] = 0.f; }

    uint32_t qf[2][4][4];
    bool qloaded = false;

    ldQ(); ldKV(0, 0, true);

    for (int i = 0; i < nblk; i++) {
        CP_WAIT0();
        __syncthreads();
        ldKV(i + 1, (i + 1) & 1, i + 1 < nblk);

        if (!qloaded) {
            qloaded = true;
            #pragma unroll
            for (int m = 0; m < 2; m++)
                #pragma unroll
                for (int ks = 0; ks < 4; ks++) {
                    int arow = wm * 32 + m * 16 + (lane & 7) + (matX & 1) * 8;
                    int aseg = ks * 2 + (matX >> 1);
                    uint32_t off = (uint32_t)(arow * 128 + ((aseg ^ (arow & 7)) << 4));
                    LDSM4(qf[m][ks], sbase + off);
                }
        }

        int s0 = c_fB[tt][i] * 128;
        uint32_t kb = sbase + 16384 + (i & 1) * 32768;
        uint32_t vb = kb + 16384;

        // ---- S = Q K^T (my m32 x n64 part) ----
        float sacc[2][8][4];
        #pragma unroll
        for (int m = 0; m < 2; m++)
            #pragma unroll
            for (int j = 0; j < 8; j++)
                #pragma unroll
                for (int q = 0; q < 4; q++) sacc[m][j][q] = 0.f;

        #pragma unroll
        for (int ks = 0; ks < 4; ks++) {
            #pragma unroll
            for (int np = 0; np < 4; np++) {
                uint32_t bf[4];
                int brow = wn * 64 + np * 16 + ((matX >> 1) << 3) + (lane & 7);
                int bseg = ks * 2 + (matX & 1);
                uint32_t boff = (uint32_t)(brow * 128 + ((bseg ^ (brow & 7)) << 4));
                LDSM4(bf, kb + boff);
                #pragma unroll
                for (int m = 0; m < 2; m++)
                    #pragma unroll
                    for (int t2 = 0; t2 < 2; t2++)
                        mma16816(sacc[m][np * 2 + t2], qf[m][ks], bf + 2 * t2);
            }
        }

        // ---- scale + mask + local (per-half) row max ----
        float lmax[2][2];
        #pragma unroll
        for (int m = 0; m < 2; m++) { lmax[m][0] = -3.0e38f; lmax[m][1] = -3.0e38f; }
        #pragma unroll
        for (int m = 0; m < 2; m++)
            #pragma unroll
            for (int hh = 0; hh < 2; hh++) {
                int r = t0 + wm * 32 + m * 16 + hh * 8 + r_l;
                #pragma unroll
                for (int j = 0; j < 8; j++) {
                    int cc = s0 + wn * 64 + j * 8 + c_l;
                    float v0 = keep_fn(r, cc)     ? sacc[m][j][2*hh]   * SCALE_QK : -3.0e38f;
                    float v1 = keep_fn(r, cc + 1) ? sacc[m][j][2*hh+1] * SCALE_QK : -3.0e38f;
                    sacc[m][j][2*hh]   = v0;
                    sacc[m][j][2*hh+1] = v1;
                    lmax[m][hh] = fmaxf(lmax[m][hh], fmaxf(v0, v1));
                }
            }
        #pragma unroll
        for (int m = 0; m < 2; m++)
            #pragma unroll
            for (int hh = 0; hh < 2; hh++) {
                float mx = lmax[m][hh];
                mx = fmaxf(mx, __shfl_xor_sync(0xffffffff, mx, 1));
                mx = fmaxf(mx, __shfl_xor_sync(0xffffffff, mx, 2));
                float mn = fmaxf(mrow[m][hh], mx);
                float alpha = __expf(mrow[m][hh] - mn);
                mrow[m][hh] = mn;
                // exp + local sum
                float lsum = 0.f;
                #pragma unroll
                for (int j = 0; j < 8; j++) {
                    float v0 = sacc[m][j][2*hh];
                    float v1 = sacc[m][j][2*hh+1];
                    v0 = (v0 > -1.0e38f) ? __expf(v0 - mn) : 0.f;
                    v1 = (v1 > -1.0e38f) ? __expf(v1 - mn) : 0.f;
                    sacc[m][j][2*hh]   = v0;
                    sacc[m][j][2*hh+1] = v1;
                    lsum += v0 + v1;
                }
                lsum += __shfl_xor_sync(0xffffffff, lsum, 1);
                lsum += __shfl_xor_sync(0xffffffff, lsum, 2);
                lrow[m][hh] = lrow[m][hh] * alpha + lsum;
                // rescale O
                #pragma unroll
                for (int j = 0; j < 8; j++) {
                    oacc[m][j][2*hh]   *= alpha;
                    oacc[m][j][2*hh+1] *= alpha;
                }
            }

        // ---- O += P * V (contraction over my s-half 64) ----
        #pragma unroll
        for (int kf = 0; kf < 4; kf++) {
            uint32_t vf[4][4];
            #pragma unroll
            for (int nf = 0; nf < 4; nf++) {
                int vrow = nf * 16 + ((matX >> 1) << 3) + (lane & 7);
                int vseg = wn * 8 + kf * 2 + (matX & 1);
                LDSM4(vf[nf], vb + swz256(vrow, vseg));
            }
            #pragma unroll
            for (int m = 0; m < 2; m++) {
                uint32_t pf[4];
                __half2 p0 = __floats2half2_rn(sacc[m][2*kf][0],   sacc[m][2*kf][1]);
                __half2 p1 = __floats2half2_rn(sacc[m][2*kf][2],   sacc[m][2*kf][3]);
                __half2 p2 = __floats2half2_rn(sacc[m][2*kf+1][0], sacc[m][2*kf+1][1]);
                __half2 p3 = __floats2half2_rn(sacc[m][2*kf+1][2], sacc[m][2*kf+1][3]);
                pf[0] = *(uint32_t*)&p0; pf[1] = *(uint32_t*)&p1;
                pf[2] = *(uint32_t*)&p2; pf[3] = *(uint32_t*)&p3;
                #pragma unroll
                for (int nf = 0; nf < 4; nf++)
                    #pragma unroll
                    for (int t2 = 0; t2 < 2; t2++)
                        mma16816(oacc[m][nf * 2 + t2], pf, vf[nf] + 2 * t2);
            }
        }
    }

    // ---- combine the two independent halves, divide by l, store ----
    __syncthreads();
    if (wn == 1) {
        #pragma unroll
        for (int m = 0; m < 2; m++)
            #pragma unroll
            for (int hh = 0; hh < 2; hh++) {
                int rl = wm * 32 + m * 16 + hh * 8 + r_l;
                if ((lane & 3) == 0) { mxbuf[rl] = mrow[m][hh]; lsbuf[rl] = lrow[m][hh]; }
                #pragma unroll
                for (int j = 0; j < 8; j++) {
                    obuf[rl * 64 + j * 8 + c_l]     = oacc[m][j][2*hh];
                    obuf[rl * 64 + j * 8 + c_l + 1] = oacc[m][j][2*hh+1];
                }
            }
    }
    __syncthreads();
    if (wn == 0) {
        #pragma unroll
        for (int m = 0; m < 2; m++)
            #pragma unroll
            for (int hh = 0; hh < 2; hh++) {
                int rl = wm * 32 + m * 16 + hh * 8 + r_l;
                int rr = t0 + rl;
                if (rr >= Tv) continue;
                float m1 = mxbuf[rl], l1 = lsbuf[rl];
                float mm = fmaxf(mrow[m][hh], m1);
                float a0 = __expf(mrow[m][hh] - mm);
                float a1 = __expf(m1 - mm);
                float lt = lrow[m][hh] * a0 + l1 * a1;
                float linv = 1.f / lt;
                #pragma unroll
                for (int j = 0; j < 8; j++) {
                    float v0 = (oacc[m][j][2*hh]   * a0 + obuf[rl * 64 + j * 8 + c_l]     * a1) * linv;
                    float v1 = (oacc[m][j][2*hh+1] * a0 + obuf[rl * 64 + j * 8 + c_l + 1] * a1) * linv;
                    __half2 hv = __floats2half2_rn(v0, v1);
                    *(__half2*)(O + ((size_t)(b * Tv + rr)) * Ev + h * HSv + j * 8 + c_l) = hv;
                }
            }
    }
}

// ---------------- fp32 GEMM (head only) ----------------
__global__ void __launch_bounds__(256, 2)
sgemm128(int M, int N, int K,
         const float* __restrict__ A, int lda,
         const float* __restrict__ B, int ldb,
         float* __restrict__ C, int ldc,
         const float* __restrict__ bias, int reluflag)
{
    __shared__ __align__(16) float As[8][128];
    __shared__ __align__(16) float Bs[8][128];
    int n0 = blockIdx.x * 128, m0 = blockIdx.y * 128;
    int tid = threadIdx.x;
    int tx = tid & 15, ty = tid >> 4;
    int arow = tid >> 1,  akk  = (tid & 1) * 4;
    int bkk  = tid >> 5,  bcol = (tid & 31) * 4;
    bool aval = (m0 + arow) < M;
    bool bval = (n0 + bcol) < N;
    const float* Aptr = A + (size_t)(m0 + arow) * lda + akk;
    const float* Bptr = B + (size_t)bkk * ldb + n0 + bcol;
    float acc[8][8];
    #pragma unroll
    for (int i = 0; i < 8; i++)
        #pragma unroll
        for (int j = 0; j < 8; j++) acc[i][j] = 0.f;
    for (int k0 = 0; k0 < K; k0 += 8) {
        float4 av = make_float4(0.f,0.f,0.f,0.f), bv = make_float4(0.f,0.f,0.f,0.f);
        if (aval) av = *(const float4*)(Aptr + k0);
        if (bval) bv = *(const float4*)(Bptr + (size_t)k0 * ldb);
        __syncthreads();
        As[akk+0][arow] = av.x; As[akk+1][arow] = av.y;
        As[akk+2][arow] = av.z; As[akk+3][arow] = av.w;
        *(float4*)&Bs[bkk][bcol] = bv;
        __syncthreads();
        #pragma unroll
        for (int kk = 0; kk < 8; kk++) {
            float a[8], b2[8];
            *(float4*)(a)    = *(const float4*)&As[kk][ty*8];
            *(float4*)(a+4)  = *(const float4*)&As[kk][ty*8+4];
            *(float4*)(b2)   = *(const float4*)&Bs[kk][tx*8];
            *(float4*)(b2+4) = *(const float4*)&Bs[kk][tx*8+4];
            #pragma unroll
            for (int i = 0; i < 8; i++)
                #pragma unroll
                for (int j = 0; j < 8; j++)
                    acc[i][j] += a[i] * b2[j];
        }
    }
    #pragma unroll
    for (int i = 0; i < 8; i++) {
        int r = m0 + ty*8 + i;
        if (r >= M) continue;
        #pragma unroll
        for (int j = 0; j < 8; j++) {
            int c = n0 + tx*8 + j;
            if (c >= N) continue;
            float v = acc[i][j];
            if (bias) v += bias[c];
            if (reluflag) v = fmaxf(v, 0.f);
            C[(size_t)r * ldc + c] = v;
        }
    }
}

// ---------------- launch ----------------
extern "C" void kernel_launch(void* const* d_in, const int* in_sizes, int n_in,
                              void* d_out, int out_size) {
    const float* images     = (const float*)d_in[0];
    const int*   goals_txt  = (const int*)  d_in[1];
    const float* goal_imgs  = (const float*)d_in[2];
    const float* patch_w    = (const float*)d_in[3];
    const float* patch_b    = (const float*)d_in[4];
    const float* text_emb   = (const float*)d_in[5];
    const float* action_emb = (const float*)d_in[6];
    const float* wq         = (const float*)d_in[7];
    const float* wk         = (const float*)d_in[8];
    const float* wv         = (const float*)d_in[9];
    const float* proj_w     = (const float*)d_in[10];
    const float* proj_b     = (const float*)d_in[11];
    const float* ln1_s      = (const float*)d_in[12];
    const float* ln1_b      = (const float*)d_in[13];
    const float* ln2_s      = (const float*)d_in[14];
    const float* ln2_b      = (const float*)d_in[15];
    const float* ff_w1      = (const float*)d_in[16];
    const float* ff_b1      = (const float*)d_in[17];
    const float* ff_w2      = (const float*)d_in[18];
    const float* ff_b2      = (const float*)d_in[19];
    const float* hw1        = (const float*)d_in[20];
    const float* hb1        = (const float*)d_in[21];
    const float* hw2        = (const float*)d_in[22];
    const float* hb2        = (const float*)d_in[23];
    float* out = (float*)d_out;

    cudaFuncSetAttribute(tgemm, cudaFuncAttributeMaxDynamicSharedMemorySize, TGSMEM);
    cudaFuncSetAttribute(fattn, cudaFuncAttributeMaxDynamicSharedMemorySize, FASMEM);

    float *pPOS, *pX, *pZ;
    h16 *pH, *pO, *pF, *pXP, *pQ, *pVt;
    h16 *pWq, *pWp, *pW1, *pW2, *pWt;
    cudaGetSymbolAddress((void**)&pPOS, g_POS);
    cudaGetSymbolAddress((void**)&pX,   g_X);
    cudaGetSymbolAddress((void**)&pZ,   g_Z);
    cudaGetSymbolAddress((void**)&pH,   g_H);
    cudaGetSymbolAddress((void**)&pO,   g_O);
    cudaGetSymbolAddress((void**)&pF,   g_F);
    cudaGetSymbolAddress((void**)&pXP,  g_XP);
    cudaGetSymbolAddress((void**)&pQ,   g_QKV);
    cudaGetSymbolAddress((void**)&pVt,  g_Vt);
    cudaGetSymbolAddress((void**)&pWq,  g_Wqkv);
    cudaGetSymbolAddress((void**)&pWp,  g_Wprj);
    cudaGetSymbolAddress((void**)&pW1,  g_Wf1);
    cudaGetSymbolAddress((void**)&pW2,  g_Wf2);
    cudaGetSymbolAddress((void**)&pWt,  g_Wpat);

    // ---- prep ----
    pos_kernel    <<<CDIV(Tv*Ev, 256), 256>>>(pPOS);
    conv_wqkv     <<<dim3(2, 24, Lv*3*Hv), dim3(32,8)>>>(wq, wk, wv, pWq);
    transpose_conv<<<dim3(24, 24, Lv), dim3(32,8)>>>(proj_w, pWp, Ev, Ev);
    transpose_conv<<<dim3(96, 24, Lv), dim3(32,8)>>>(ff_w1, pW1, Ev, E4);
    transpose_conv<<<dim3(24, 96, Lv), dim3(32,8)>>>(ff_w2, pW2, E4, Ev);
    transpose_conv<<<dim3(24, 24, 1),  dim3(32,8)>>>(patch_w, pWt, Ev, Ev);
    gather_patches<<<CDIV(MPATCH*Ev, 256), 256>>>(images, goal_imgs, pXP);
    embed_txt_act <<<CDIV(Bv*33*Ev, 256), 256>>>(goals_txt, text_emb, action_emb, pPOS, pX);

    // patch embed -> X rows 32..619 (+bias +POS)
    tgemm<<<dim3(Ev/128, CDIV(MPATCH,256)), 256, TGSMEM>>>(
        MPATCH, Ev, Ev, pXP, pWt,
        patch_b, pPOS, Ev, 1,
        pX, Ev, 0, 0, nullptr);

    for (int l = 0; l < Lv; l++) {
        ln_kernel<<<CDIV(MTv,8), 256>>>(pX, pH, ln1_s + l*Ev, ln1_b + l*Ev);

        tgemm<<<dim3(QKVLD/128, CDIV(MTv,256)), 256, TGSMEM>>>(   // QKV -> fp16
            MTv, QKVLD, Ev, pH, pWq + (size_t)l*QKVLD*Ev,
            nullptr, nullptr, 0, 0,
            nullptr, 0, 0, 0, pQ);

        repack_v<<<dim3(TP/32, HSv/32, ZH), dim3(32,8)>>>(pQ, pVt);
        fattn   <<<dim3(5, ZH), 256, FASMEM>>>(pQ, pVt, pO);

        tgemm<<<dim3(Ev/128, CDIV(MTv,256)), 256, TGSMEM>>>(   // X += O @ proj + b
            MTv, Ev, Ev, pO, pWp + (size_t)l*Ev*Ev,
            proj_b + l*Ev, nullptr, 0, 0,
            pX, Ev, 1, 0, nullptr);

        ln_kernel<<<CDIV(MTv,8), 256>>>(pX, pH, ln2_s + l*Ev, ln2_b + l*Ev);

        tgemm<<<dim3(E4/128, CDIV(MTv,256)), 256, TGSMEM>>>(   // F = relu(h@W1+b1) -> fp16
            MTv, E4, Ev, pH, pW1 + (size_t)l*E4*Ev,
            ff_b1 + l*E4, nullptr, 0, 0,
            nullptr, 0, 0, 1, pF);

        tgemm<<<dim3(Ev/128, CDIV(MTv,256)), 256, TGSMEM>>>(   // X += F @ W2 + b2
            MTv, Ev, E4, pF, pW2 + (size_t)l*Ev*E4,
            ff_b2 + l*Ev, nullptr, 0, 0,
            pX, Ev, 1, 0, nullptr);
    }

    // head
    sgemm128<<<dim3(Ev/128, 1), 256>>>(
        Bv, Ev, Ev, pX + (size_t)620*Ev, Tv*Ev, hw1, Ev, pZ, Ev, hb1, 1);
    sgemm128<<<dim3(1, 1), 256>>>(
        Bv, AOUTv, Ev, pZ, Ev, hw2, AOUTv, out, AOUTv, hb2, 0);

    (void)in_sizes; (void)n_in; (void)out_size;
}

// round 16
// speedup vs baseline: 3.2376x; 1.0129x over previous
#include <cuda_runtime.h>
#include <cuda_fp16.h>
#include <math.h>
#include <stdint.h>
#include <stddef.h>

// ---------------- problem constants ----------------
#define Bv      16
#define Kv      2
#define Ev      768
#define Hv      12
#define HSv     64
#define Lv      12
#define Tv      621
#define TP      640
#define NPATCH  588
#define QKVLD   2304
#define E4      3072
#define AOUTv   64
#define MTv     (Bv*Tv)      // 9936
#define MPATCH  (Bv*NPATCH)  // 9408
#define ZH      (Bv*Hv)      // 192
#define SCALE_QK 0.036084391824351615f

#define CDIV(a,b) (((a)+(b)-1)/(b))
#define TGSMEM   196608      // 2 stages x 96KB (A 64K + B 32K)
#define FASMEM   83968       // Q 16K + 2x(K16K+V16K) + stats

typedef __half h16;

// ---------------- scratch ----------------
__device__ __align__(128) float g_POS[Tv*Ev];
__device__ __align__(128) float g_X  [(size_t)MTv*Ev];
__device__ __align__(128) float g_Z  [Bv*Ev];

__device__ __align__(128) h16 g_H  [(size_t)MTv*Ev];
__device__ __align__(128) h16 g_O  [(size_t)MTv*Ev];
__device__ __align__(128) h16 g_F  [(size_t)MTv*E4];
__device__ __align__(128) h16 g_XP [(size_t)MPATCH*Ev];
__device__ __align__(128) h16 g_QKV[(size_t)MTv*QKVLD];

__device__ __align__(128) h16 g_Wqkv[(size_t)Lv*QKVLD*Ev];
__device__ __align__(128) h16 g_Wprj[(size_t)Lv*Ev*Ev];
__device__ __align__(128) h16 g_Wf1 [(size_t)Lv*E4*Ev];
__device__ __align__(128) h16 g_Wf2 [(size_t)Lv*Ev*E4];
__device__ __align__(128) h16 g_Wpat[(size_t)Ev*Ev];

// ---------------- mask-derived live s-block lists per t-tile ----------------
__constant__ int c_fN[5] = {1, 4, 4, 5, 5};
__constant__ int c_fB[5][5] = {
    {0, 0, 0, 0, 0},
    {0, 1, 2, 3, 0},
    {0, 1, 2, 3, 0},
    {0, 1, 2, 3, 4},
    {0, 1, 2, 3, 4}
};

// ---------------- helpers ----------------
__device__ __forceinline__ uint32_t smem_u32(const void* p) {
    uint32_t a;
    asm("{ .reg .u64 t; cvta.to.shared.u64 t, %1; cvt.u32.u64 %0, t; }" : "=r"(a) : "l"(p));
    return a;
}
__device__ __forceinline__ void cp16(uint32_t sa, const void* ga, bool v) {
    int sz = v ? 16 : 0;
    asm volatile("cp.async.cg.shared.global [%0], [%1], 16, %2;" :: "r"(sa), "l"(ga), "r"(sz) : "memory");
}
#define CP_COMMIT() asm volatile("cp.async.commit_group;" ::: "memory")
#define CP_WAIT0()  asm volatile("cp.async.wait_group 0;" ::: "memory")

#define LDSM4(r, a) \
    asm volatile("ldmatrix.sync.aligned.m8n8.x4.shared.b16 {%0,%1,%2,%3}, [%4];" \
        : "=r"((r)[0]),"=r"((r)[1]),"=r"((r)[2]),"=r"((r)[3]) : "r"(a))

#define LDSM4T(r, a) \
    asm volatile("ldmatrix.sync.aligned.m8n8.x4.trans.shared.b16 {%0,%1,%2,%3}, [%4];" \
        : "=r"((r)[0]),"=r"((r)[1]),"=r"((r)[2]),"=r"((r)[3]) : "r"(a))

__device__ __forceinline__ void mma16816(float* d, const uint32_t* a, const uint32_t* b) {
    asm volatile("mma.sync.aligned.m16n8k16.row.col.f32.f16.f16.f32 "
        "{%0,%1,%2,%3}, {%4,%5,%6,%7}, {%8,%9}, {%0,%1,%2,%3};"
        : "+f"(d[0]),"+f"(d[1]),"+f"(d[2]),"+f"(d[3])
        : "r"(a[0]),"r"(a[1]),"r"(a[2]),"r"(a[3]), "r"(b[0]),"r"(b[1]));
}

// 256B-row swizzled offset; seg = 16B unit index 0..15
__device__ __forceinline__ uint32_t swz256(int row, int seg) {
    return (uint32_t)(row * 256 + ((seg & 8) << 4) + (((seg & 7) ^ (row & 7)) << 4));
}

// ---------------- mask ----------------
__device__ __forceinline__ bool keep_fn(int t, int s) {
    bool v = (t == s);
    if (s < 32) v = !(t >= 32 && t < 228);
    if (t >= 228 && s >= 228 && s < 424) v = true;
    if (t >= 424 && s >= 424 && s < 620) v = true;
    return v;
}

// ---------------- positional embedding ----------------
__global__ void pos_kernel(float* POS) {
    int idx = blockIdx.x * 256 + threadIdx.x;
    if (idx >= Tv * Ev) return;
    int t = idx / Ev, j = idx % Ev;
    double expo = (double)(j & ~1) / (double)Ev;
    double ang  = (double)t / pow(10000.0, expo);
    POS[idx] = (float)((j & 1) ? cos(ang) : sin(ang));
}

// ---------------- transpose+convert weights ----------------
__global__ void transpose_conv(const float* __restrict__ src, h16* __restrict__ dst, int R, int C) {
    __shared__ float t[32][33];
    int z = blockIdx.z;
    src += (size_t)z * R * C; dst += (size_t)z * R * C;
    int c0 = blockIdx.x * 32, r0 = blockIdx.y * 32;
    int tx = threadIdx.x, ty = threadIdx.y;
    #pragma unroll
    for (int i = 0; i < 4; i++)
        t[ty + 8*i][tx] = src[(size_t)(r0 + ty + 8*i) * C + c0 + tx];
    __syncthreads();
    #pragma unroll
    for (int i = 0; i < 4; i++)
        dst[(size_t)(c0 + ty + 8*i) * R + r0 + tx] = __float2half(t[tx][ty + 8*i]);
}

__global__ void conv_wqkv(const float* __restrict__ wq, const float* __restrict__ wk,
                          const float* __restrict__ wv, h16* __restrict__ dst) {
    __shared__ float t[32][33];
    int z = blockIdx.z;
    int h = z % Hv, which = (z / Hv) % 3, l = z / (3 * Hv);
    const float* src = (which == 0) ? wq : (which == 1) ? wk : wv;
    src += ((size_t)l * Hv + h) * Ev * HSv;
    int d0 = blockIdx.x * 32, e0 = blockIdx.y * 32;
    int tx = threadIdx.x, ty = threadIdx.y;
    #pragma unroll
    for (int i = 0; i < 4; i++)
        t[ty + 8*i][tx] = src[(size_t)(e0 + ty + 8*i) * HSv + d0 + tx];
    __syncthreads();
    #pragma unroll
    for (int i = 0; i < 4; i++) {
        int d = d0 + ty + 8*i, e = e0 + tx;
        dst[((size_t)l * QKVLD + which * Ev + h * HSv + d) * Ev + e] = __float2half(t[tx][ty + 8*i]);
    }
}

// ---------------- gather patches -> fp16 ----------------
__global__ void gather_patches(const float* __restrict__ images, const float* __restrict__ goal_imgs,
                               h16* __restrict__ X) {
    int idx = blockIdx.x * 256 + threadIdx.x;
    if (idx >= MPATCH * Ev) return;
    int f = idx % Ev;
    int r = idx / Ev;
    int p = r % NPATCH;
    int b = r / NPATCH;
    int py = f / 48, px = (f % 48) / 3, c = f % 3;
    float val;
    if (p < 196) {
        int pr = p / 14, pc = p % 14;
        int y = pr * 16 + py, x = pc * 16 + px;
        val = goal_imgs[(((size_t)b * 224 + y) * 224 + x) * 3 + c];
    } else {
        int q = p - 196;
        int k = q / 196, pp = q % 196;
        int pr = pp / 14, pc = pp % 14;
        int y = pr * 16 + py, x = pc * 16 + px;
        val = images[((((size_t)b * Kv + k) * 224 + y) * 224 + x) * 3 + c];
    }
    X[idx] = __float2half(val);
}

// ---------------- text + action embed (+POS) ----------------
__global__ void embed_txt_act(const int* __restrict__ goals_txt, const float* __restrict__ text_emb,
                              const float* __restrict__ action_emb, const float* __restrict__ POS,
                              float* __restrict__ X) {
    int idx = blockIdx.x * 256 + threadIdx.x;
    if (idx >= Bv * 33 * Ev) return;
    int e  = idx % Ev;
    int r  = idx / Ev;
    int tt = r % 33;
    int b  = r / 33;
    int t  = (tt < 32) ? tt : 620;
    float v = (tt < 32) ? text_emb[(size_t)goals_txt[b * 32 + tt] * Ev + e] : action_emb[e];
    X[((size_t)b * Tv + t) * Ev + e] = v + POS[(size_t)t * Ev + e];
}

// ---------------- layernorm: warp per row, shuffle reduce -> fp16 ----------------
__global__ void ln_kernel(const float* __restrict__ X, h16* __restrict__ Out,
                          const float* __restrict__ sc, const float* __restrict__ bi) {
    int w = threadIdx.x >> 5, lane = threadIdx.x & 31;
    int row = blockIdx.x * 8 + w;
    if (row >= MTv) return;
    const float* x = X + (size_t)row * Ev;
    float4 v[6];
    float s = 0.f, ss = 0.f;
    #pragma unroll
    for (int i = 0; i < 6; i++) {
        v[i] = *(const float4*)(x + i * 128 + lane * 4);
        s  += v[i].x + v[i].y + v[i].z + v[i].w;
        ss += v[i].x*v[i].x + v[i].y*v[i].y + v[i].z*v[i].z + v[i].w*v[i].w;
    }
    #pragma unroll
    for (int off = 16; off; off >>= 1) {
        s  += __shfl_xor_sync(0xffffffff, s,  off);
        ss += __shfl_xor_sync(0xffffffff, ss, off);
    }
    float m   = s * (1.f / Ev);
    float var = ss * (1.f / Ev) - m * m;
    float inv = rsqrtf(var + 1e-5f);
    #pragma unroll
    for (int i = 0; i < 6; i++) {
        int col = i * 128 + lane * 4;
        float o0 = (v[i].x - m) * inv * sc[col]   + bi[col];
        float o1 = (v[i].y - m) * inv * sc[col+1] + bi[col+1];
        float o2 = (v[i].z - m) * inv * sc[col+2] + bi[col+2];
        float o3 = (v[i].w - m) * inv * sc[col+3] + bi[col+3];
        __half2 h0 = __floats2half2_rn(o0, o1);
        __half2 h1 = __floats2half2_rn(o2, o3);
        uint2 u = make_uint2(*(uint32_t*)&h0, *(uint32_t*)&h1);
        *(uint2*)(Out + (size_t)row * Ev + col) = u;
    }
}

// =====================================================================
// fp16 GEMM (mma.sync m16n8k16), 256x128 CTA tile, 256 threads,
// warp tile 64x64, Kc=128, 2-stage cp.async pipeline.
// =====================================================================
__global__ void __launch_bounds__(256, 1)
tgemm(int M, int N, int K,
      const h16* __restrict__ A, const h16* __restrict__ B,
      const float* __restrict__ bias,
      const float* __restrict__ rowmat, int ldrm, int rmode,
      float* outF, int ldo, int accf, int reluf,
      h16* outH)
{
    extern __shared__ char sm[];
    uint32_t sbase = smem_u32(sm);
    int tid = threadIdx.x, lane = tid & 31, wid = tid >> 5;
    int m0 = blockIdx.y * 256, n0 = blockIdx.x * 128;
    int wm = wid & 3, wn = wid >> 2;

    float acc[4][8][4];
    #pragma unroll
    for (int i = 0; i < 4; i++)
        #pragma unroll
        for (int j = 0; j < 8; j++)
            #pragma unroll
            for (int q = 0; q < 4; q++) acc[i][j][q] = 0.f;

    int nc = K >> 7;

    auto ld_st = [&](int c, int st, bool active) {
        if (active) {
            uint32_t sb = sbase + st * 98304;
            int k0 = c * 128;
            #pragma unroll
            for (int i = 0; i < 16; i++) {
                int u = i * 256 + tid;
                int row = u >> 4, seg = u & 15;
                uint32_t off = swz256(row, seg);
                bool av = (m0 + row) < M;
                size_t ao = (size_t)(av ? (m0 + row) : 0) * K + k0 + seg * 8;
                cp16(sb + off, A + ao, av);
            }
            #pragma unroll
            for (int i = 0; i < 8; i++) {
                int u = i * 256 + tid;
                int row = u >> 4, seg = u & 15;
                uint32_t off = swz256(row, seg);
                size_t bo = (size_t)(n0 + row) * K + k0 + seg * 8;
                cp16(sb + 65536 + off, B + bo, true);
            }
        }
        CP_COMMIT();
    };

    ld_st(0, 0, true);

    int matA = lane >> 3;
    int matB = lane >> 3;

    for (int c = 0; c < nc; c++) {
        CP_WAIT0();
        __syncthreads();
        ld_st(c + 1, (c + 1) & 1, c + 1 < nc);

        uint32_t sA = sbase + (c & 1) * 98304;
        uint32_t sB = sA + 65536;

        #pragma unroll
        for (int ks = 0; ks < 8; ks++) {
            uint32_t bf[4][4];
            #pragma unroll
            for (int np = 0; np < 4; np++) {
                int brow = wn * 64 + np * 16 + ((matB >> 1) << 3) + (lane & 7);
                int bseg = ks * 2 + (matB & 1);
                LDSM4(bf[np], sB + swz256(brow, bseg));
            }
            uint32_t af[2][4];
            {
                int arow = wm * 64 + (lane & 7) + (matA & 1) * 8;
                int aseg = ks * 2 + (matA >> 1);
                LDSM4(af[0], sA + swz256(arow, aseg));
            }
            #pragma unroll
            for (int mt = 0; mt < 4; mt++) {
                int cur = mt & 1, nxt = cur ^ 1;
                if (mt < 3) {
                    int arow = wm * 64 + (mt + 1) * 16 + (lane & 7) + (matA & 1) * 8;
                    int aseg = ks * 2 + (matA >> 1);
                    LDSM4(af[nxt], sA + swz256(arow, aseg));
                }
                #pragma unroll
                for (int np = 0; np < 4; np++)
                    #pragma unroll
                    for (int t = 0; t < 2; t++)
                        mma16816(acc[mt][np * 2 + t], af[cur], bf[np] + 2 * t);
            }
        }
    }

    int r_l = lane >> 2, c_l = (lane & 3) * 2;
    #pragma unroll
    for (int mt = 0; mt < 4; mt++) {
        #pragma unroll
        for (int h = 0; h < 2; h++) {
            int rr = m0 + wm * 64 + mt * 16 + h * 8 + r_l;
            if (rr >= M) continue;
            int orow = rr, prow = rr;
            if (rmode) {
                int b = rr / NPATCH, p = rr - b * NPATCH;
                orow = b * Tv + 32 + p;
                prow = 32 + p;
            }
            #pragma unroll
            for (int j = 0; j < 8; j++) {
                int col = n0 + wn * 64 + j * 8 + c_l;
                float v0 = acc[mt][j][2 * h];
                float v1 = acc[mt][j][2 * h + 1];
                if (bias)   { v0 += bias[col]; v1 += bias[col + 1]; }
                if (rowmat) { const float* rp = rowmat + (size_t)prow * ldrm + col; v0 += rp[0]; v1 += rp[1]; }
                if (accf)   { const float* op = outF + (size_t)orow * ldo + col;   v0 += op[0]; v1 += op[1]; }
                if (reluf)  { v0 = fmaxf(v0, 0.f); v1 = fmaxf(v1, 0.f); }
                if (outF)   *(float2*)(outF + (size_t)orow * ldo + col) = make_float2(v0, v1);
                if (outH) {
                    size_t o = (size_t)rr * N + col;
                    __half2 hv = __floats2half2_rn(v0, v1);
                    *(__half2*)(outH + o) = hv;
                }
            }
        }
    }
}

// =====================================================================
// fattn v3: fused flash attention; V staged directly from QKV [s][d]
// and consumed via ldmatrix.trans (repack_v / Vt eliminated).
// Independent online softmax per wn s-half; final rescaled combine.
// smem: Q @0 (16K), stage{0,1}: K @16K/48K (16K), V @32K/64K (16K),
//       mx @80K, ls @81K, obuf fp32 @16K (reuses stages post-loop).
// =====================================================================
__global__ void __launch_bounds__(256, 1)
fattn(const h16* __restrict__ QKV, h16* __restrict__ O)
{
    extern __shared__ char sm[];
    uint32_t sbase = smem_u32(sm);
    float* mxbuf = (float*)(sm + 81920);   // [128]
    float* lsbuf = (float*)(sm + 82944);   // [128]
    float* obuf  = (float*)(sm + 16384);   // [128][64] fp32 (reuse stages)

    int tid = threadIdx.x, lane = tid & 31, wid = tid >> 5;
    int wm = wid >> 1, wn = wid & 1;
    int tt = blockIdx.x, z = blockIdx.y, b = z / Hv, h = z % Hv;
    int t0 = tt * 128;
    int nblk = c_fN[tt];
    int matX = lane >> 3;
    int r_l = lane >> 2, c_l = (lane & 3) * 2;

    auto ldQ = [&]() {
        #pragma unroll
        for (int i = 0; i < 4; i++) {
            int u = i * 256 + tid;
            int row = u >> 3, seg = u & 7;
            uint32_t off = (uint32_t)(row * 128 + ((seg ^ (row & 7)) << 4));
            bool v = (t0 + row) < Tv;
            size_t qo = (size_t)(b * Tv + (v ? t0 + row : 0)) * QKVLD + h * HSv + seg * 8;
            cp16(sbase + off, QKV + qo, v);
        }
    };
    auto ldKV = [&](int blk_i, int st, bool active) {
        if (active) {
            int s0 = c_fB[tt][blk_i] * 128;
            uint32_t kb = sbase + 16384 + st * 32768;
            uint32_t vb = kb + 16384;
            #pragma unroll
            for (int i = 0; i < 4; i++) {   // K: 128 s-rows x 8 segs
                int u = i * 256 + tid;
                int row = u >> 3, seg = u & 7;
                uint32_t off = (uint32_t)(row * 128 + ((seg ^ (row & 7)) << 4));
                bool v = (s0 + row) < Tv;
                size_t ko = (size_t)(b * Tv + (v ? s0 + row : 0)) * QKVLD + Ev + h * HSv + seg * 8;
                cp16(kb + off, QKV + ko, v);
            }
            #pragma unroll
            for (int i = 0; i < 4; i++) {   // V: 128 s-rows x 8 segs (row clamped; pads masked by P=0)
                int u = i * 256 + tid;
                int row = u >> 3, seg = u & 7;
                uint32_t off = (uint32_t)(row * 128 + ((seg ^ (row & 7)) << 4));
                int sr = (s0 + row) < Tv ? (s0 + row) : (Tv - 1);
                size_t vo = (size_t)(b * Tv + sr) * QKVLD + 2 * Ev + h * HSv + seg * 8;
                cp16(vb + off, QKV + vo, true);
            }
        }
        CP_COMMIT();
    };

    float oacc[2][8][4];
    #pragma unroll
    for (int m = 0; m < 2; m++)
        #pragma unroll
        for (int j = 0; j < 8; j++)
            #pragma unroll
            for (int q = 0; q < 4; q++) oacc[m][j][q] = 0.f;
    float mrow[2][2], lrow[2][2];
    #pragma unroll
    for (int m = 0; m < 2; m++) { mrow[m][0] = mrow[m][1] = -3.0e38f; lrow[m][0] = lrow[m][1] = 0.f; }

    uint32_t qf[2][4][4];
    bool qloaded = false;

    ldQ(); ldKV(0, 0, true);

    for (int i = 0; i < nblk; i++) {
        CP_WAIT0();
        __syncthreads();
        ldKV(i + 1, (i + 1) & 1, i + 1 < nblk);

        if (!qloaded) {
            qloaded = true;
            #pragma unroll
            for (int m = 0; m < 2; m++)
                #pragma unroll
                for (int ks = 0; ks < 4; ks++) {
                    int arow = wm * 32 + m * 16 + (lane & 7) + (matX & 1) * 8;
                    int aseg = ks * 2 + (matX >> 1);
                    uint32_t off = (uint32_t)(arow * 128 + ((aseg ^ (arow & 7)) << 4));
                    LDSM4(qf[m][ks], sbase + off);
                }
        }

        int s0 = c_fB[tt][i] * 128;
        uint32_t kb = sbase + 16384 + (i & 1) * 32768;
        uint32_t vb = kb + 16384;

        // ---- S = Q K^T (my m32 x n64 part) ----
        float sacc[2][8][4];
        #pragma unroll
        for (int m = 0; m < 2; m++)
            #pragma unroll
            for (int j = 0; j < 8; j++)
                #pragma unroll
                for (int q = 0; q < 4; q++) sacc[m][j][q] = 0.f;

        #pragma unroll
        for (int ks = 0; ks < 4; ks++) {
            #pragma unroll
            for (int np = 0; np < 4; np++) {
                uint32_t bf[4];
                int brow = wn * 64 + np * 16 + ((matX >> 1) << 3) + (lane & 7);
                int bseg = ks * 2 + (matX & 1);
                uint32_t boff = (uint32_t)(brow * 128 + ((bseg ^ (brow & 7)) << 4));
                LDSM4(bf, kb + boff);
                #pragma unroll
                for (int m = 0; m < 2; m++)
                    #pragma unroll
                    for (int t2 = 0; t2 < 2; t2++)
                        mma16816(sacc[m][np * 2 + t2], qf[m][ks], bf + 2 * t2);
            }
        }

        // ---- scale + mask + per-half online softmax ----
        float lmax[2][2];
        #pragma unroll
        for (int m = 0; m < 2; m++) { lmax[m][0] = -3.0e38f; lmax[m][1] = -3.0e38f; }
        #pragma unroll
        for (int m = 0; m < 2; m++)
            #pragma unroll
            for (int hh = 0; hh < 2; hh++) {
                int r = t0 + wm * 32 + m * 16 + hh * 8 + r_l;
                #pragma unroll
                for (int j = 0; j < 8; j++) {
                    int cc = s0 + wn * 64 + j * 8 + c_l;
                    float v0 = keep_fn(r, cc)     ? sacc[m][j][2*hh]   * SCALE_QK : -3.0e38f;
                    float v1 = keep_fn(r, cc + 1) ? sacc[m][j][2*hh+1] * SCALE_QK : -3.0e38f;
                    sacc[m][j][2*hh]   = v0;
                    sacc[m][j][2*hh+1] = v1;
                    lmax[m][hh] = fmaxf(lmax[m][hh], fmaxf(v0, v1));
                }
            }
        #pragma unroll
        for (int m = 0; m < 2; m++)
            #pragma unroll
            for (int hh = 0; hh < 2; hh++) {
                float mx = lmax[m][hh];
                mx = fmaxf(mx, __shfl_xor_sync(0xffffffff, mx, 1));
                mx = fmaxf(mx, __shfl_xor_sync(0xffffffff, mx, 2));
                float mn = fmaxf(mrow[m][hh], mx);
                float alpha = __expf(mrow[m][hh] - mn);
                mrow[m][hh] = mn;
                float lsum = 0.f;
                #pragma unroll
                for (int j = 0; j < 8; j++) {
                    float v0 = sacc[m][j][2*hh];
                    float v1 = sacc[m][j][2*hh+1];
                    v0 = (v0 > -1.0e38f) ? __expf(v0 - mn) : 0.f;
                    v1 = (v1 > -1.0e38f) ? __expf(v1 - mn) : 0.f;
                    sacc[m][j][2*hh]   = v0;
                    sacc[m][j][2*hh+1] = v1;
                    lsum += v0 + v1;
                }
                lsum += __shfl_xor_sync(0xffffffff, lsum, 1);
                lsum += __shfl_xor_sync(0xffffffff, lsum, 2);
                lrow[m][hh] = lrow[m][hh] * alpha + lsum;
                #pragma unroll
                for (int j = 0; j < 8; j++) {
                    oacc[m][j][2*hh]   *= alpha;
                    oacc[m][j][2*hh+1] *= alpha;
                }
            }

        // ---- O += P * V (contraction over my s-half; V via trans-ldmatrix) ----
        #pragma unroll
        for (int kf = 0; kf < 4; kf++) {
            uint32_t vf[4][4];
            int srow = wn * 64 + kf * 16 + (lane & 15);
            #pragma unroll
            for (int nf = 0; nf < 4; nf++) {
                int dseg = nf * 2 + ((lane >> 4) & 1);
                uint32_t voff = (uint32_t)(srow * 128 + ((dseg ^ (srow & 7)) << 4));
                LDSM4T(vf[nf], vb + voff);
            }
            #pragma unroll
            for (int m = 0; m < 2; m++) {
                uint32_t pf[4];
                __half2 p0 = __floats2half2_rn(sacc[m][2*kf][0],   sacc[m][2*kf][1]);
                __half2 p1 = __floats2half2_rn(sacc[m][2*kf][2],   sacc[m][2*kf][3]);
                __half2 p2 = __floats2half2_rn(sacc[m][2*kf+1][0], sacc[m][2*kf+1][1]);
                __half2 p3 = __floats2half2_rn(sacc[m][2*kf+1][2], sacc[m][2*kf+1][3]);
                pf[0] = *(uint32_t*)&p0; pf[1] = *(uint32_t*)&p1;
                pf[2] = *(uint32_t*)&p2; pf[3] = *(uint32_t*)&p3;
                #pragma unroll
                for (int nf = 0; nf < 4; nf++)
                    #pragma unroll
                    for (int t2 = 0; t2 < 2; t2++)
                        mma16816(oacc[m][nf * 2 + t2], pf, vf[nf] + 2 * t2);
            }
        }
    }

    // ---- combine the two independent halves, divide by l, store ----
    __syncthreads();
    if (wn == 1) {
        #pragma unroll
        for (int m = 0; m < 2; m++)
            #pragma unroll
            for (int hh = 0; hh < 2; hh++) {
                int rl = wm * 32 + m * 16 + hh * 8 + r_l;
                if ((lane & 3) == 0) { mxbuf[rl] = mrow[m][hh]; lsbuf[rl] = lrow[m][hh]; }
                #pragma unroll
                for (int j = 0; j < 8; j++) {
                    obuf[rl * 64 + j * 8 + c_l]     = oacc[m][j][2*hh];
                    obuf[rl * 64 + j * 8 + c_l + 1] = oacc[m][j][2*hh+1];
                }
            }
    }
    __syncthreads();
    if (wn == 0) {
        #pragma unroll
        for (int m = 0; m < 2; m++)
            #pragma unroll
            for (int hh = 0; hh < 2; hh++) {
                int rl = wm * 32 + m * 16 + hh * 8 + r_l;
                int rr = t0 + rl;
                if (rr >= Tv) continue;
                float m1 = mxbuf[rl], l1 = lsbuf[rl];
                float mm = fmaxf(mrow[m][hh], m1);
                float a0 = __expf(mrow[m][hh] - mm);
                float a1 = __expf(m1 - mm);
                float lt = lrow[m][hh] * a0 + l1 * a1;
                float linv = 1.f / lt;
                #pragma unroll
                for (int j = 0; j < 8; j++) {
                    float v0 = (oacc[m][j][2*hh]   * a0 + obuf[rl * 64 + j * 8 + c_l]     * a1) * linv;
                    float v1 = (oacc[m][j][2*hh+1] * a0 + obuf[rl * 64 + j * 8 + c_l + 1] * a1) * linv;
                    __half2 hv = __floats2half2_rn(v0, v1);
                    *(__half2*)(O + ((size_t)(b * Tv + rr)) * Ev + h * HSv + j * 8 + c_l) = hv;
                }
            }
    }
}

// ---------------- fp32 GEMM (head only) ----------------
__global__ void __launch_bounds__(256, 2)
sgemm128(int M, int N, int K,
         const float* __restrict__ A, int lda,
         const float* __restrict__ B, int ldb,
         float* __restrict__ C, int ldc,
         const float* __restrict__ bias, int reluflag)
{
    __shared__ __align__(16) float As[8][128];
    __shared__ __align__(16) float Bs[8][128];
    int n0 = blockIdx.x * 128, m0 = blockIdx.y * 128;
    int tid = threadIdx.x;
    int tx = tid & 15, ty = tid >> 4;
    int arow = tid >> 1,  akk  = (tid & 1) * 4;
    int bkk  = tid >> 5,  bcol = (tid & 31) * 4;
    bool aval = (m0 + arow) < M;
    bool bval = (n0 + bcol) < N;
    const float* Aptr = A + (size_t)(m0 + arow) * lda + akk;
    const float* Bptr = B + (size_t)bkk * ldb + n0 + bcol;
    float acc[8][8];
    #pragma unroll
    for (int i = 0; i < 8; i++)
        #pragma unroll
        for (int j = 0; j < 8; j++) acc[i][j] = 0.f;
    for (int k0 = 0; k0 < K; k0 += 8) {
        float4 av = make_float4(0.f,0.f,0.f,0.f), bv = make_float4(0.f,0.f,0.f,0.f);
        if (aval) av = *(const float4*)(Aptr + k0);
        if (bval) bv = *(const float4*)(Bptr + (size_t)k0 * ldb);
        __syncthreads();
        As[akk+0][arow] = av.x; As[akk+1][arow] = av.y;
        As[akk+2][arow] = av.z; As[akk+3][arow] = av.w;
        *(float4*)&Bs[bkk][bcol] = bv;
        __syncthreads();
        #pragma unroll
        for (int kk = 0; kk < 8; kk++) {
            float a[8], b2[8];
            *(float4*)(a)    = *(const float4*)&As[kk][ty*8];
            *(float4*)(a+4)  = *(const float4*)&As[kk][ty*8+4];
            *(float4*)(b2)   = *(const float4*)&Bs[kk][tx*8];
            *(float4*)(b2+4) = *(const float4*)&Bs[kk][tx*8+4];
            #pragma unroll
            for (int i = 0; i < 8; i++)
                #pragma unroll
                for (int j = 0; j < 8; j++)
                    acc[i][j] += a[i] * b2[j];
        }
    }
    #pragma unroll
    for (int i = 0; i < 8; i++) {
        int r = m0 + ty*8 + i;
        if (r >= M) continue;
        #pragma unroll
        for (int j = 0; j < 8; j++) {
            int c = n0 + tx*8 + j;
            if (c >= N) continue;
            float v = acc[i][j];
            if (bias) v += bias[c];
            if (reluflag) v = fmaxf(v, 0.f);
            C[(size_t)r * ldc + c] = v;
        }
    }
}

// ---------------- launch ----------------
extern "C" void kernel_launch(void* const* d_in, const int* in_sizes, int n_in,
                              void* d_out, int out_size) {
    const float* images     = (const float*)d_in[0];
    const int*   goals_txt  = (const int*)  d_in[1];
    const float* goal_imgs  = (const float*)d_in[2];
    const float* patch_w    = (const float*)d_in[3];
    const float* patch_b    = (const float*)d_in[4];
    const float* text_emb   = (const float*)d_in[5];
    const float* action_emb = (const float*)d_in[6];
    const float* wq         = (const float*)d_in[7];
    const float* wk         = (const float*)d_in[8];
    const float* wv         = (const float*)d_in[9];
    const float* proj_w     = (const float*)d_in[10];
    const float* proj_b     = (const float*)d_in[11];
    const float* ln1_s      = (const float*)d_in[12];
    const float* ln1_b      = (const float*)d_in[13];
    const float* ln2_s      = (const float*)d_in[14];
    const float* ln2_b      = (const float*)d_in[15];
    const float* ff_w1      = (const float*)d_in[16];
    const float* ff_b1      = (const float*)d_in[17];
    const float* ff_w2      = (const float*)d_in[18];
    const float* ff_b2      = (const float*)d_in[19];
    const float* hw1        = (const float*)d_in[20];
    const float* hb1        = (const float*)d_in[21];
    const float* hw2        = (const float*)d_in[22];
    const float* hb2        = (const float*)d_in[23];
    float* out = (float*)d_out;

    cudaFuncSetAttribute(tgemm, cudaFuncAttributeMaxDynamicSharedMemorySize, TGSMEM);
    cudaFuncSetAttribute(fattn, cudaFuncAttributeMaxDynamicSharedMemorySize, FASMEM);

    float *pPOS, *pX, *pZ;
    h16 *pH, *pO, *pF, *pXP, *pQ;
    h16 *pWq, *pWp, *pW1, *pW2, *pWt;
    cudaGetSymbolAddress((void**)&pPOS, g_POS);
    cudaGetSymbolAddress((void**)&pX,   g_X);
    cudaGetSymbolAddress((void**)&pZ,   g_Z);
    cudaGetSymbolAddress((void**)&pH,   g_H);
    cudaGetSymbolAddress((void**)&pO,   g_O);
    cudaGetSymbolAddress((void**)&pF,   g_F);
    cudaGetSymbolAddress((void**)&pXP,  g_XP);
    cudaGetSymbolAddress((void**)&pQ,   g_QKV);
    cudaGetSymbolAddress((void**)&pWq,  g_Wqkv);
    cudaGetSymbolAddress((void**)&pWp,  g_Wprj);
    cudaGetSymbolAddress((void**)&pW1,  g_Wf1);
    cudaGetSymbolAddress((void**)&pW2,  g_Wf2);
    cudaGetSymbolAddress((void**)&pWt,  g_Wpat);

    // ---- prep ----
    pos_kernel    <<<CDIV(Tv*Ev, 256), 256>>>(pPOS);
    conv_wqkv     <<<dim3(2, 24, Lv*3*Hv), dim3(32,8)>>>(wq, wk, wv, pWq);
    transpose_conv<<<dim3(24, 24, Lv), dim3(32,8)>>>(proj_w, pWp, Ev, Ev);
    transpose_conv<<<dim3(96, 24, Lv), dim3(32,8)>>>(ff_w1, pW1, Ev, E4);
    transpose_conv<<<dim3(24, 96, Lv), dim3(32,8)>>>(ff_w2, pW2, E4, Ev);
    transpose_conv<<<dim3(24, 24, 1),  dim3(32,8)>>>(patch_w, pWt, Ev, Ev);
    gather_patches<<<CDIV(MPATCH*Ev, 256), 256>>>(images, goal_imgs, pXP);
    embed_txt_act <<<CDIV(Bv*33*Ev, 256), 256>>>(goals_txt, text_emb, action_emb, pPOS, pX);

    // patch embed -> X rows 32..619 (+bias +POS)
    tgemm<<<dim3(Ev/128, CDIV(MPATCH,256)), 256, TGSMEM>>>(
        MPATCH, Ev, Ev, pXP, pWt,
        patch_b, pPOS, Ev, 1,
        pX, Ev, 0, 0, nullptr);

    for (int l = 0; l < Lv; l++) {
        ln_kernel<<<CDIV(MTv,8), 256>>>(pX, pH, ln1_s + l*Ev, ln1_b + l*Ev);

        tgemm<<<dim3(QKVLD/128, CDIV(MTv,256)), 256, TGSMEM>>>(   // QKV -> fp16
            MTv, QKVLD, Ev, pH, pWq + (size_t)l*QKVLD*Ev,
            nullptr, nullptr, 0, 0,
            nullptr, 0, 0, 0, pQ);

        fattn<<<dim3(5, ZH), 256, FASMEM>>>(pQ, pO);

        tgemm<<<dim3(Ev/128, CDIV(MTv,256)), 256, TGSMEM>>>(   // X += O @ proj + b
            MTv, Ev, Ev, pO, pWp + (size_t)l*Ev*Ev,
            proj_b + l*Ev, nullptr, 0, 0,
            pX, Ev, 1, 0, nullptr);

        ln_kernel<<<CDIV(MTv,8), 256>>>(pX, pH, ln2_s + l*Ev, ln2_b + l*Ev);

        tgemm<<<dim3(E4/128, CDIV(MTv,256)), 256, TGSMEM>>>(   // F = relu(h@W1+b1) -> fp16
            MTv, E4, Ev, pH, pW1 + (size_t)l*E4*Ev,
            ff_b1 + l*E4, nullptr, 0, 0,
            nullptr, 0, 0, 1, pF);

        tgemm<<<dim3(Ev/128, CDIV(MTv,256)), 256, TGSMEM>>>(   // X += F @ W2 + b2
            MTv, Ev, E4, pF, pW2 + (size_t)l*Ev*E4,
            ff_b2 + l*Ev, nullptr, 0, 0,
            pX, Ev, 1, 0, nullptr);
    }

    // head
    sgemm128<<<dim3(Ev/128, 1), 256>>>(
        Bv, Ev, Ev, pX + (size_t)620*Ev, Tv*Ev, hw1, Ev, pZ, Ev, hb1, 1);
    sgemm128<<<dim3(1, 1), 256>>>(
        Bv, AOUTv, Ev, pZ, Ev, hw2, AOUTv, out, AOUTv, hb2, 0);

    (void)in_sizes; (void)n_in; (void)out_size;
}

// round 17
// speedup vs baseline: 3.2423x; 1.0015x over previous
#include <cuda_runtime.h>
#include <cuda_fp16.h>
#include <math.h>
#include <stdint.h>
#include <stddef.h>

// ---------------- problem constants ----------------
#define Bv      16
#define Kv      2
#define Ev      768
#define Hv      12
#define HSv     64
#define Lv      12
#define Tv      621
#define TP      640
#define NPATCH  588
#define QKVLD   2304
#define E4      3072
#define AOUTv   64
#define MTv     (Bv*Tv)      // 9936
#define MPATCH  (Bv*NPATCH)  // 9408
#define ZH      (Bv*Hv)      // 192
#define SCALE_QK 0.036084391824351615f

#define CDIV(a,b) (((a)+(b)-1)/(b))
#define TGSMEM   196608      // 2 stages x 96KB (A 64K + B 32K)
#define FASMEM   83968       // Q 16K + 2x(K16K+V16K) + stats

typedef __half h16;

// ---------------- scratch ----------------
__device__ __align__(128) float  g_POS[Tv*Ev];
__device__ __align__(128) double g_W  [Ev];
__device__ __align__(128) float  g_X  [(size_t)MTv*Ev];
__device__ __align__(128) float  g_Z  [Bv*Ev];

__device__ __align__(128) h16 g_H  [(size_t)MTv*Ev];
__device__ __align__(128) h16 g_O  [(size_t)MTv*Ev];
__device__ __align__(128) h16 g_F  [(size_t)MTv*E4];
__device__ __align__(128) h16 g_XP [(size_t)MPATCH*Ev];
__device__ __align__(128) h16 g_QKV[(size_t)MTv*QKVLD];

__device__ __align__(128) h16 g_Wqkv[(size_t)Lv*QKVLD*Ev];
__device__ __align__(128) h16 g_Wprj[(size_t)Lv*Ev*Ev];
__device__ __align__(128) h16 g_Wf1 [(size_t)Lv*E4*Ev];
__device__ __align__(128) h16 g_Wf2 [(size_t)Lv*Ev*E4];
__device__ __align__(128) h16 g_Wpat[(size_t)Ev*Ev];

// ---------------- mask-derived live s-block lists per t-tile ----------------
__constant__ int c_fN[5] = {1, 4, 4, 5, 5};
__constant__ int c_fB[5][5] = {
    {0, 0, 0, 0, 0},
    {0, 1, 2, 3, 0},
    {0, 1, 2, 3, 0},
    {0, 1, 2, 3, 4},
    {0, 1, 2, 3, 4}
};

// ---------------- helpers ----------------
__device__ __forceinline__ uint32_t smem_u32(const void* p) {
    uint32_t a;
    asm("{ .reg .u64 t; cvta.to.shared.u64 t, %1; cvt.u32.u64 %0, t; }" : "=r"(a) : "l"(p));
    return a;
}
__device__ __forceinline__ void cp16(uint32_t sa, const void* ga, bool v) {
    int sz = v ? 16 : 0;
    asm volatile("cp.async.cg.shared.global [%0], [%1], 16, %2;" :: "r"(sa), "l"(ga), "r"(sz) : "memory");
}
#define CP_COMMIT() asm volatile("cp.async.commit_group;" ::: "memory")
#define CP_WAIT0()  asm volatile("cp.async.wait_group 0;" ::: "memory")

#define LDSM4(r, a) \
    asm volatile("ldmatrix.sync.aligned.m8n8.x4.shared.b16 {%0,%1,%2,%3}, [%4];" \
        : "=r"((r)[0]),"=r"((r)[1]),"=r"((r)[2]),"=r"((r)[3]) : "r"(a))

#define LDSM4T(r, a) \
    asm volatile("ldmatrix.sync.aligned.m8n8.x4.trans.shared.b16 {%0,%1,%2,%3}, [%4];" \
        : "=r"((r)[0]),"=r"((r)[1]),"=r"((r)[2]),"=r"((r)[3]) : "r"(a))

__device__ __forceinline__ void mma16816(float* d, const uint32_t* a, const uint32_t* b) {
    asm volatile("mma.sync.aligned.m16n8k16.row.col.f32.f16.f16.f32 "
        "{%0,%1,%2,%3}, {%4,%5,%6,%7}, {%8,%9}, {%0,%1,%2,%3};"
        : "+f"(d[0]),"+f"(d[1]),"+f"(d[2]),"+f"(d[3])
        : "r"(a[0]),"r"(a[1]),"r"(a[2]),"r"(a[3]), "r"(b[0]),"r"(b[1]));
}

// 256B-row swizzled offset; seg = 16B unit index 0..15
__device__ __forceinline__ uint32_t swz256(int row, int seg) {
    return (uint32_t)(row * 256 + ((seg & 8) << 4) + (((seg & 7) ^ (row & 7)) << 4));
}

// ---------------- mask ----------------
__device__ __forceinline__ bool keep_fn(int t, int s) {
    bool v = (t == s);
    if (s < 32) v = !(t >= 32 && t < 228);
    if (t >= 228 && s >= 228 && s < 424) v = true;
    if (t >= 424 && s >= 424 && s < 620) v = true;
    return v;
}

// ---------------- positional embedding (two-phase; fp64 transcendentals only in phase A) ----------------
__global__ void posA_kernel(double* W) {
    int j = threadIdx.x;
    if (j >= Ev) return;
    double expo = (double)(j & ~1) / (double)Ev;
    W[j] = pow(10000.0, -expo);
}

__global__ void posB_kernel(const double* __restrict__ W, float* __restrict__ POS) {
    int idx = blockIdx.x * 256 + threadIdx.x;
    if (idx >= Tv * Ev) return;
    int t = idx / Ev, j = idx % Ev;
    double ang = (double)t * W[j];
    // range-reduce mod 2*pi in double (HW-rate DP arithmetic only)
    const double TWO_PI = 6.2831853071795864769;
    const double INV_2PI = 0.15915494309189533577;
    double k = floor(ang * INV_2PI);
    float r = (float)(ang - k * TWO_PI);
    POS[idx] = (j & 1) ? cosf(r) : sinf(r);
}

// ---------------- transpose+convert weights ----------------
__global__ void transpose_conv(const float* __restrict__ src, h16* __restrict__ dst, int R, int C) {
    __shared__ float t[32][33];
    int z = blockIdx.z;
    src += (size_t)z * R * C; dst += (size_t)z * R * C;
    int c0 = blockIdx.x * 32, r0 = blockIdx.y * 32;
    int tx = threadIdx.x, ty = threadIdx.y;
    #pragma unroll
    for (int i = 0; i < 4; i++)
        t[ty + 8*i][tx] = src[(size_t)(r0 + ty + 8*i) * C + c0 + tx];
    __syncthreads();
    #pragma unroll
    for (int i = 0; i < 4; i++)
        dst[(size_t)(c0 + ty + 8*i) * R + r0 + tx] = __float2half(t[tx][ty + 8*i]);
}

__global__ void conv_wqkv(const float* __restrict__ wq, const float* __restrict__ wk,
                          const float* __restrict__ wv, h16* __restrict__ dst) {
    __shared__ float t[32][33];
    int z = blockIdx.z;
    int h = z % Hv, which = (z / Hv) % 3, l = z / (3 * Hv);
    const float* src = (which == 0) ? wq : (which == 1) ? wk : wv;
    src += ((size_t)l * Hv + h) * Ev * HSv;
    int d0 = blockIdx.x * 32, e0 = blockIdx.y * 32;
    int tx = threadIdx.x, ty = threadIdx.y;
    #pragma unroll
    for (int i = 0; i < 4; i++)
        t[ty + 8*i][tx] = src[(size_t)(e0 + ty + 8*i) * HSv + d0 + tx];
    __syncthreads();
    #pragma unroll
    for (int i = 0; i < 4; i++) {
        int d = d0 + ty + 8*i, e = e0 + tx;
        dst[((size_t)l * QKVLD + which * Ev + h * HSv + d) * Ev + e] = __float2half(t[tx][ty + 8*i]);
    }
}

// ---------------- gather patches -> fp16 ----------------
__global__ void gather_patches(const float* __restrict__ images, const float* __restrict__ goal_imgs,
                               h16* __restrict__ X) {
    int idx = blockIdx.x * 256 + threadIdx.x;
    if (idx >= MPATCH * Ev) return;
    int f = idx % Ev;
    int r = idx / Ev;
    int p = r % NPATCH;
    int b = r / NPATCH;
    int py = f / 48, px = (f % 48) / 3, c = f % 3;
    float val;
    if (p < 196) {
        int pr = p / 14, pc = p % 14;
        int y = pr * 16 + py, x = pc * 16 + px;
        val = goal_imgs[(((size_t)b * 224 + y) * 224 + x) * 3 + c];
    } else {
        int q = p - 196;
        int k = q / 196, pp = q % 196;
        int pr = pp / 14, pc = pp % 14;
        int y = pr * 16 + py, x = pc * 16 + px;
        val = images[((((size_t)b * Kv + k) * 224 + y) * 224 + x) * 3 + c];
    }
    X[idx] = __float2half(val);
}

// ---------------- text + action embed (+POS) ----------------
__global__ void embed_txt_act(const int* __restrict__ goals_txt, const float* __restrict__ text_emb,
                              const float* __restrict__ action_emb, const float* __restrict__ POS,
                              float* __restrict__ X) {
    int idx = blockIdx.x * 256 + threadIdx.x;
    if (idx >= Bv * 33 * Ev) return;
    int e  = idx % Ev;
    int r  = idx / Ev;
    int tt = r % 33;
    int b  = r / 33;
    int t  = (tt < 32) ? tt : 620;
    float v = (tt < 32) ? text_emb[(size_t)goals_txt[b * 32 + tt] * Ev + e] : action_emb[e];
    X[((size_t)b * Tv + t) * Ev + e] = v + POS[(size_t)t * Ev + e];
}

// ---------------- layernorm: warp per row, shuffle reduce -> fp16 ----------------
__global__ void ln_kernel(const float* __restrict__ X, h16* __restrict__ Out,
                          const float* __restrict__ sc, const float* __restrict__ bi) {
    int w = threadIdx.x >> 5, lane = threadIdx.x & 31;
    int row = blockIdx.x * 8 + w;
    if (row >= MTv) return;
    const float* x = X + (size_t)row * Ev;
    float4 v[6];
    float s = 0.f, ss = 0.f;
    #pragma unroll
    for (int i = 0; i < 6; i++) {
        v[i] = *(const float4*)(x + i * 128 + lane * 4);
        s  += v[i].x + v[i].y + v[i].z + v[i].w;
        ss += v[i].x*v[i].x + v[i].y*v[i].y + v[i].z*v[i].z + v[i].w*v[i].w;
    }
    #pragma unroll
    for (int off = 16; off; off >>= 1) {
        s  += __shfl_xor_sync(0xffffffff, s,  off);
        ss += __shfl_xor_sync(0xffffffff, ss, off);
    }
    float m   = s * (1.f / Ev);
    float var = ss * (1.f / Ev) - m * m;
    float inv = rsqrtf(var + 1e-5f);
    #pragma unroll
    for (int i = 0; i < 6; i++) {
        int col = i * 128 + lane * 4;
        float o0 = (v[i].x - m) * inv * sc[col]   + bi[col];
        float o1 = (v[i].y - m) * inv * sc[col+1] + bi[col+1];
        float o2 = (v[i].z - m) * inv * sc[col+2] + bi[col+2];
        float o3 = (v[i].w - m) * inv * sc[col+3] + bi[col+3];
        __half2 h0 = __floats2half2_rn(o0, o1);
        __half2 h1 = __floats2half2_rn(o2, o3);
        uint2 u = make_uint2(*(uint32_t*)&h0, *(uint32_t*)&h1);
        *(uint2*)(Out + (size_t)row * Ev + col) = u;
    }
}

// =====================================================================
// fp16 GEMM (mma.sync m16n8k16), 256x128 CTA tile, 256 threads,
// warp tile 64x64, Kc=128, 2-stage cp.async pipeline.
// =====================================================================
__global__ void __launch_bounds__(256, 1)
tgemm(int M, int N, int K,
      const h16* __restrict__ A, const h16* __restrict__ B,
      const float* __restrict__ bias,
      const float* __restrict__ rowmat, int ldrm, int rmode,
      float* outF, int ldo, int accf, int reluf,
      h16* outH)
{
    extern __shared__ char sm[];
    uint32_t sbase = smem_u32(sm);
    int tid = threadIdx.x, lane = tid & 31, wid = tid >> 5;
    int m0 = blockIdx.y * 256, n0 = blockIdx.x * 128;
    int wm = wid & 3, wn = wid >> 2;

    float acc[4][8][4];
    #pragma unroll
    for (int i = 0; i < 4; i++)
        #pragma unroll
        for (int j = 0; j < 8; j++)
            #pragma unroll
            for (int q = 0; q < 4; q++) acc[i][j][q] = 0.f;

    int nc = K >> 7;

    auto ld_st = [&](int c, int st, bool active) {
        if (active) {
            uint32_t sb = sbase + st * 98304;
            int k0 = c * 128;
            #pragma unroll
            for (int i = 0; i < 16; i++) {
                int u = i * 256 + tid;
                int row = u >> 4, seg = u & 15;
                uint32_t off = swz256(row, seg);
                bool av = (m0 + row) < M;
                size_t ao = (size_t)(av ? (m0 + row) : 0) * K + k0 + seg * 8;
                cp16(sb + off, A + ao, av);
            }
            #pragma unroll
            for (int i = 0; i < 8; i++) {
                int u = i * 256 + tid;
                int row = u >> 4, seg = u & 15;
                uint32_t off = swz256(row, seg);
                size_t bo = (size_t)(n0 + row) * K + k0 + seg * 8;
                cp16(sb + 65536 + off, B + bo, true);
            }
        }
        CP_COMMIT();
    };

    ld_st(0, 0, true);

    int matA = lane >> 3;
    int matB = lane >> 3;

    for (int c = 0; c < nc; c++) {
        CP_WAIT0();
        __syncthreads();
        ld_st(c + 1, (c + 1) & 1, c + 1 < nc);

        uint32_t sA = sbase + (c & 1) * 98304;
        uint32_t sB = sA + 65536;

        #pragma unroll
        for (int ks = 0; ks < 8; ks++) {
            uint32_t bf[4][4];
            #pragma unroll
            for (int np = 0; np < 4; np++) {
                int brow = wn * 64 + np * 16 + ((matB >> 1) << 3) + (lane & 7);
                int bseg = ks * 2 + (matB & 1);
                LDSM4(bf[np], sB + swz256(brow, bseg));
            }
            uint32_t af[2][4];
            {
                int arow = wm * 64 + (lane & 7) + (matA & 1) * 8;
                int aseg = ks * 2 + (matA >> 1);
                LDSM4(af[0], sA + swz256(arow, aseg));
            }
            #pragma unroll
            for (int mt = 0; mt < 4; mt++) {
                int cur = mt & 1, nxt = cur ^ 1;
                if (mt < 3) {
                    int arow = wm * 64 + (mt + 1) * 16 + (lane & 7) + (matA & 1) * 8;
                    int aseg = ks * 2 + (matA >> 1);
                    LDSM4(af[nxt], sA + swz256(arow, aseg));
                }
                #pragma unroll
                for (int np = 0; np < 4; np++)
                    #pragma unroll
                    for (int t = 0; t < 2; t++)
                        mma16816(acc[mt][np * 2 + t], af[cur], bf[np] + 2 * t);
            }
        }
    }

    int r_l = lane >> 2, c_l = (lane & 3) * 2;
    #pragma unroll
    for (int mt = 0; mt < 4; mt++) {
        #pragma unroll
        for (int h = 0; h < 2; h++) {
            int rr = m0 + wm * 64 + mt * 16 + h * 8 + r_l;
            if (rr >= M) continue;
            int orow = rr, prow = rr;
            if (rmode) {
                int b = rr / NPATCH, p = rr - b * NPATCH;
                orow = b * Tv + 32 + p;
                prow = 32 + p;
            }
            #pragma unroll
            for (int j = 0; j < 8; j++) {
                int col = n0 + wn * 64 + j * 8 + c_l;
                float v0 = acc[mt][j][2 * h];
                float v1 = acc[mt][j][2 * h + 1];
                if (bias)   { v0 += bias[col]; v1 += bias[col + 1]; }
                if (rowmat) { const float* rp = rowmat + (size_t)prow * ldrm + col; v0 += rp[0]; v1 += rp[1]; }
                if (accf)   { const float* op = outF + (size_t)orow * ldo + col;   v0 += op[0]; v1 += op[1]; }
                if (reluf)  { v0 = fmaxf(v0, 0.f); v1 = fmaxf(v1, 0.f); }
                if (outF)   *(float2*)(outF + (size_t)orow * ldo + col) = make_float2(v0, v1);
                if (outH) {
                    size_t o = (size_t)rr * N + col;
                    __half2 hv = __floats2half2_rn(v0, v1);
                    *(__half2*)(outH + o) = hv;
                }
            }
        }
    }
}

// =====================================================================
// fattn v3: fused flash attention; V staged directly from QKV [s][d]
// and consumed via ldmatrix.trans. Independent online softmax per wn
// s-half; final rescaled combine.
// =====================================================================
__global__ void __launch_bounds__(256, 1)
fattn(const h16* __restrict__ QKV, h16* __restrict__ O)
{
    extern __shared__ char sm[];
    uint32_t sbase = smem_u32(sm);
    float* mxbuf = (float*)(sm + 81920);   // [128]
    float* lsbuf = (float*)(sm + 82944);   // [128]
    float* obuf  = (float*)(sm + 16384);   // [128][64] fp32 (reuse stages)

    int tid = threadIdx.x, lane = tid & 31, wid = tid >> 5;
    int wm = wid >> 1, wn = wid & 1;
    int tt = blockIdx.x, z = blockIdx.y, b = z / Hv, h = z % Hv;
    int t0 = tt * 128;
    int nblk = c_fN[tt];
    int matX = lane >> 3;
    int r_l = lane >> 2, c_l = (lane & 3) * 2;

    auto ldQ = [&]() {
        #pragma unroll
        for (int i = 0; i < 4; i++) {
            int u = i * 256 + tid;
            int row = u >> 3, seg = u & 7;
            uint32_t off = (uint32_t)(row * 128 + ((seg ^ (row & 7)) << 4));
            bool v = (t0 + row) < Tv;
            size_t qo = (size_t)(b * Tv + (v ? t0 + row : 0)) * QKVLD + h * HSv + seg * 8;
            cp16(sbase + off, QKV + qo, v);
        }
    };
    auto ldKV = [&](int blk_i, int st, bool active) {
        if (active) {
            int s0 = c_fB[tt][blk_i] * 128;
            uint32_t kb = sbase + 16384 + st * 32768;
            uint32_t vb = kb + 16384;
            #pragma unroll
            for (int i = 0; i < 4; i++) {
                int u = i * 256 + tid;
                int row = u >> 3, seg = u & 7;
                uint32_t off = (uint32_t)(row * 128 + ((seg ^ (row & 7)) << 4));
                bool v = (s0 + row) < Tv;
                size_t ko = (size_t)(b * Tv + (v ? s0 + row : 0)) * QKVLD + Ev + h * HSv + seg * 8;
                cp16(kb + off, QKV + ko, v);
            }
            #pragma unroll
            for (int i = 0; i < 4; i++) {
                int u = i * 256 + tid;
                int row = u >> 3, seg = u & 7;
                uint32_t off = (uint32_t)(row * 128 + ((seg ^ (row & 7)) << 4));
                int sr = (s0 + row) < Tv ? (s0 + row) : (Tv - 1);
                size_t vo = (size_t)(b * Tv + sr) * QKVLD + 2 * Ev + h * HSv + seg * 8;
                cp16(vb + off, QKV + vo, true);
            }
        }
        CP_COMMIT();
    };

    float oacc[2][8][4];
    #pragma unroll
    for (int m = 0; m < 2; m++)
        #pragma unroll
        for (int j = 0; j < 8; j++)
            #pragma unroll
            for (int q = 0; q < 4; q++) oacc[m][j][q] = 0.f;
    float mrow[2][2], lrow[2][2];
    #pragma unroll
    for (int m = 0; m < 2; m++) { mrow[m][0] = mrow[m][1] = -3.0e38f; lrow[m][0] = lrow[m][1] = 0.f; }

    uint32_t qf[2][4][4];
    bool qloaded = false;

    ldQ(); ldKV(0, 0, true);

    for (int i = 0; i < nblk; i++) {
        CP_WAIT0();
        __syncthreads();
        ldKV(i + 1, (i + 1) & 1, i + 1 < nblk);

        if (!qloaded) {
            qloaded = true;
            #pragma unroll
            for (int m = 0; m < 2; m++)
                #pragma unroll
                for (int ks = 0; ks < 4; ks++) {
                    int arow = wm * 32 + m * 16 + (lane & 7) + (matX & 1) * 8;
                    int aseg = ks * 2 + (matX >> 1);
                    uint32_t off = (uint32_t)(arow * 128 + ((aseg ^ (arow & 7)) << 4));
                    LDSM4(qf[m][ks], sbase + off);
                }
        }

        int s0 = c_fB[tt][i] * 128;
        uint32_t kb = sbase + 16384 + (i & 1) * 32768;
        uint32_t vb = kb + 16384;

        float sacc[2][8][4];
        #pragma unroll
        for (int m = 0; m < 2; m++)
            #pragma unroll
            for (int j = 0; j < 8; j++)
                #pragma unroll
                for (int q = 0; q < 4; q++) sacc[m][j][q] = 0.f;

        #pragma unroll
        for (int ks = 0; ks < 4; ks++) {
            #pragma unroll
            for (int np = 0; np < 4; np++) {
                uint32_t bf[4];
                int brow = wn * 64 + np * 16 + ((matX >> 1) << 3) + (lane & 7);
                int bseg = ks * 2 + (matX & 1);
                uint32_t boff = (uint32_t)(brow * 128 + ((bseg ^ (brow & 7)) << 4));
                LDSM4(bf, kb + boff);
                #pragma unroll
                for (int m = 0; m < 2; m++)
                    #pragma unroll
                    for (int t2 = 0; t2 < 2; t2++)
                        mma16816(sacc[m][np * 2 + t2], qf[m][ks], bf + 2 * t2);
            }
        }

        float lmax[2][2];
        #pragma unroll
        for (int m = 0; m < 2; m++) { lmax[m][0] = -3.0e38f; lmax[m][1] = -3.0e38f; }
        #pragma unroll
        for (int m = 0; m < 2; m++)
            #pragma unroll
            for (int hh = 0; hh < 2; hh++) {
                int r = t0 + wm * 32 + m * 16 + hh * 8 + r_l;
                #pragma unroll
                for (int j = 0; j < 8; j++) {
                    int cc = s0 + wn * 64 + j * 8 + c_l;
                    float v0 = keep_fn(r, cc)     ? sacc[m][j][2*hh]   * SCALE_QK : -3.0e38f;
                    float v1 = keep_fn(r, cc + 1) ? sacc[m][j][2*hh+1] * SCALE_QK : -3.0e38f;
                    sacc[m][j][2*hh]   = v0;
                    sacc[m][j][2*hh+1] = v1;
                    lmax[m][hh] = fmaxf(lmax[m][hh], fmaxf(v0, v1));
                }
            }
        #pragma unroll
        for (int m = 0; m < 2; m++)
            #pragma unroll
            for (int hh = 0; hh < 2; hh++) {
                float mx = lmax[m][hh];
                mx = fmaxf(mx, __shfl_xor_sync(0xffffffff, mx, 1));
                mx = fmaxf(mx, __shfl_xor_sync(0xffffffff, mx, 2));
                float mn = fmaxf(mrow[m][hh], mx);
                float alpha = __expf(mrow[m][hh] - mn);
                mrow[m][hh] = mn;
                float lsum = 0.f;
                #pragma unroll
                for (int j = 0; j < 8; j++) {
                    float v0 = sacc[m][j][2*hh];
                    float v1 = sacc[m][j][2*hh+1];
                    v0 = (v0 > -1.0e38f) ? __expf(v0 - mn) : 0.f;
                    v1 = (v1 > -1.0e38f) ? __expf(v1 - mn) : 0.f;
                    sacc[m][j][2*hh]   = v0;
                    sacc[m][j][2*hh+1] = v1;
                    lsum += v0 + v1;
                }
                lsum += __shfl_xor_sync(0xffffffff, lsum, 1);
                lsum += __shfl_xor_sync(0xffffffff, lsum, 2);
                lrow[m][hh] = lrow[m][hh] * alpha + lsum;
                #pragma unroll
                for (int j = 0; j < 8; j++) {
                    oacc[m][j][2*hh]   *= alpha;
                    oacc[m][j][2*hh+1] *= alpha;
                }
            }

        #pragma unroll
        for (int kf = 0; kf < 4; kf++) {
            uint32_t vf[4][4];
            int srow = wn * 64 + kf * 16 + (lane & 15);
            #pragma unroll
            for (int nf = 0; nf < 4; nf++) {
                int dseg = nf * 2 + ((lane >> 4) & 1);
                uint32_t voff = (uint32_t)(srow * 128 + ((dseg ^ (srow & 7)) << 4));
                LDSM4T(vf[nf], vb + voff);
            }
            #pragma unroll
            for (int m = 0; m < 2; m++) {
                uint32_t pf[4];
                __half2 p0 = __floats2half2_rn(sacc[m][2*kf][0],   sacc[m][2*kf][1]);
                __half2 p1 = __floats2half2_rn(sacc[m][2*kf][2],   sacc[m][2*kf][3]);
                __half2 p2 = __floats2half2_rn(sacc[m][2*kf+1][0], sacc[m][2*kf+1][1]);
                __half2 p3 = __floats2half2_rn(sacc[m][2*kf+1][2], sacc[m][2*kf+1][3]);
                pf[0] = *(uint32_t*)&p0; pf[1] = *(uint32_t*)&p1;
                pf[2] = *(uint32_t*)&p2; pf[3] = *(uint32_t*)&p3;
                #pragma unroll
                for (int nf = 0; nf < 4; nf++)
                    #pragma unroll
                    for (int t2 = 0; t2 < 2; t2++)
                        mma16816(oacc[m][nf * 2 + t2], pf, vf[nf] + 2 * t2);
            }
        }
    }

    __syncthreads();
    if (wn == 1) {
        #pragma unroll
        for (int m = 0; m < 2; m++)
            #pragma unroll
            for (int hh = 0; hh < 2; hh++) {
                int rl = wm * 32 + m * 16 + hh * 8 + r_l;
                if ((lane & 3) == 0) { mxbuf[rl] = mrow[m][hh]; lsbuf[rl] = lrow[m][hh]; }
                #pragma unroll
                for (int j = 0; j < 8; j++) {
                    obuf[rl * 64 + j * 8 + c_l]     = oacc[m][j][2*hh];
                    obuf[rl * 64 + j * 8 + c_l + 1] = oacc[m][j][2*hh+1];
                }
            }
    }
    __syncthreads();
    if (wn == 0) {
        #pragma unroll
        for (int m = 0; m < 2; m++)
            #pragma unroll
            for (int hh = 0; hh < 2; hh++) {
                int rl = wm * 32 + m * 16 + hh * 8 + r_l;
                int rr = t0 + rl;
                if (rr >= Tv) continue;
                float m1 = mxbuf[rl], l1 = lsbuf[rl];
                float mm = fmaxf(mrow[m][hh], m1);
                float a0 = __expf(mrow[m][hh] - mm);
                float a1 = __expf(m1 - mm);
                float lt = lrow[m][hh] * a0 + l1 * a1;
                float linv = 1.f / lt;
                #pragma unroll
                for (int j = 0; j < 8; j++) {
                    float v0 = (oacc[m][j][2*hh]   * a0 + obuf[rl * 64 + j * 8 + c_l]     * a1) * linv;
                    float v1 = (oacc[m][j][2*hh+1] * a0 + obuf[rl * 64 + j * 8 + c_l + 1] * a1) * linv;
                    __half2 hv = __floats2half2_rn(v0, v1);
                    *(__half2*)(O + ((size_t)(b * Tv + rr)) * Ev + h * HSv + j * 8 + c_l) = hv;
                }
            }
    }
}

// ---------------- fp32 GEMM (head only) ----------------
__global__ void __launch_bounds__(256, 2)
sgemm128(int M, int N, int K,
         const float* __restrict__ A, int lda,
         const float* __restrict__ B, int ldb,
         float* __restrict__ C, int ldc,
         const float* __restrict__ bias, int reluflag)
{
    __shared__ __align__(16) float As[8][128];
    __shared__ __align__(16) float Bs[8][128];
    int n0 = blockIdx.x * 128, m0 = blockIdx.y * 128;
    int tid = threadIdx.x;
    int tx = tid & 15, ty = tid >> 4;
    int arow = tid >> 1,  akk  = (tid & 1) * 4;
    int bkk  = tid >> 5,  bcol = (tid & 31) * 4;
    bool aval = (m0 + arow) < M;
    bool bval = (n0 + bcol) < N;
    const float* Aptr = A + (size_t)(m0 + arow) * lda + akk;
    const float* Bptr = B + (size_t)bkk * ldb + n0 + bcol;
    float acc[8][8];
    #pragma unroll
    for (int i = 0; i < 8; i++)
        #pragma unroll
        for (int j = 0; j < 8; j++) acc[i][j] = 0.f;
    for (int k0 = 0; k0 < K; k0 += 8) {
        float4 av = make_float4(0.f,0.f,0.f,0.f), bv = make_float4(0.f,0.f,0.f,0.f);
        if (aval) av = *(const float4*)(Aptr + k0);
        if (bval) bv = *(const float4*)(Bptr + (size_t)k0 * ldb);
        __syncthreads();
        As[akk+0][arow] = av.x; As[akk+1][arow] = av.y;
        As[akk+2][arow] = av.z; As[akk+3][arow] = av.w;
        *(float4*)&Bs[bkk][bcol] = bv;
        __syncthreads();
        #pragma unroll
        for (int kk = 0; kk < 8; kk++) {
            float a[8], b2[8];
            *(float4*)(a)    = *(const float4*)&As[kk][ty*8];
            *(float4*)(a+4)  = *(const float4*)&As[kk][ty*8+4];
            *(float4*)(b2)   = *(const float4*)&Bs[kk][tx*8];
            *(float4*)(b2+4) = *(const float4*)&Bs[kk][tx*8+4];
            #pragma unroll
            for (int i = 0; i < 8; i++)
                #pragma unroll
                for (int j = 0; j < 8; j++)
                    acc[i][j] += a[i] * b2[j];
        }
    }
    #pragma unroll
    for (int i = 0; i < 8; i++) {
        int r = m0 + ty*8 + i;
        if (r >= M) continue;
        #pragma unroll
        for (int j = 0; j < 8; j++) {
            int c = n0 + tx*8 + j;
            if (c >= N) continue;
            float v = acc[i][j];
            if (bias) v += bias[c];
            if (reluflag) v = fmaxf(v, 0.f);
            C[(size_t)r * ldc + c] = v;
        }
    }
}

// ---------------- launch ----------------
extern "C" void kernel_launch(void* const* d_in, const int* in_sizes, int n_in,
                              void* d_out, int out_size) {
    const float* images     = (const float*)d_in[0];
    const int*   goals_txt  = (const int*)  d_in[1];
    const float* goal_imgs  = (const float*)d_in[2];
    const float* patch_w    = (const float*)d_in[3];
    const float* patch_b    = (const float*)d_in[4];
    const float* text_emb   = (const float*)d_in[5];
    const float* action_emb = (const float*)d_in[6];
    const float* wq         = (const float*)d_in[7];
    const float* wk         = (const float*)d_in[8];
    const float* wv         = (const float*)d_in[9];
    const float* proj_w     = (const float*)d_in[10];
    const float* proj_b     = (const float*)d_in[11];
    const float* ln1_s      = (const float*)d_in[12];
    const float* ln1_b      = (const float*)d_in[13];
    const float* ln2_s      = (const float*)d_in[14];
    const float* ln2_b      = (const float*)d_in[15];
    const float* ff_w1      = (const float*)d_in[16];
    const float* ff_b1      = (const float*)d_in[17];
    const float* ff_w2      = (const float*)d_in[18];
    const float* ff_b2      = (const float*)d_in[19];
    const float* hw1        = (const float*)d_in[20];
    const float* hb1        = (const float*)d_in[21];
    const float* hw2        = (const float*)d_in[22];
    const float* hb2        = (const float*)d_in[23];
    float* out = (float*)d_out;

    cudaFuncSetAttribute(tgemm, cudaFuncAttributeMaxDynamicSharedMemorySize, TGSMEM);
    cudaFuncSetAttribute(fattn, cudaFuncAttributeMaxDynamicSharedMemorySize, FASMEM);

    float *pPOS, *pX, *pZ;
    double *pW64;
    h16 *pH, *pO, *pF, *pXP, *pQ;
    h16 *pWq, *pWp, *pW1, *pW2, *pWt;
    cudaGetSymbolAddress((void**)&pPOS, g_POS);
    cudaGetSymbolAddress((void**)&pW64, g_W);
    cudaGetSymbolAddress((void**)&pX,   g_X);
    cudaGetSymbolAddress((void**)&pZ,   g_Z);
    cudaGetSymbolAddress((void**)&pH,   g_H);
    cudaGetSymbolAddress((void**)&pO,   g_O);
    cudaGetSymbolAddress((void**)&pF,   g_F);
    cudaGetSymbolAddress((void**)&pXP,  g_XP);
    cudaGetSymbolAddress((void**)&pQ,   g_QKV);
    cudaGetSymbolAddress((void**)&pWq,  g_Wqkv);
    cudaGetSymbolAddress((void**)&pWp,  g_Wprj);
    cudaGetSymbolAddress((void**)&pW1,  g_Wf1);
    cudaGetSymbolAddress((void**)&pW2,  g_Wf2);
    cudaGetSymbolAddress((void**)&pWt,  g_Wpat);

    // ---- prep (launch #4 = posB so ncu -s 5 -c 1 finally profiles POS) ----
    posA_kernel   <<<1, Ev>>>(pW64);                                                  // 1
    conv_wqkv     <<<dim3(2, 24, Lv*3*Hv), dim3(32,8)>>>(wq, wk, wv, pWq);            // 2
    transpose_conv<<<dim3(24, 24, Lv), dim3(32,8)>>>(proj_w, pWp, Ev, Ev);            // 3
    posB_kernel   <<<CDIV(Tv*Ev, 256), 256>>>(pW64, pPOS);                            // 4 (profiled)
    transpose_conv<<<dim3(96, 24, Lv), dim3(32,8)>>>(ff_w1, pW1, Ev, E4);             // 5
    transpose_conv<<<dim3(24, 96, Lv), dim3(32,8)>>>(ff_w2, pW2, E4, Ev);             // 6
    transpose_conv<<<dim3(24, 24, 1),  dim3(32,8)>>>(patch_w, pWt, Ev, Ev);
    gather_patches<<<CDIV(MPATCH*Ev, 256), 256>>>(images, goal_imgs, pXP);
    embed_txt_act <<<CDIV(Bv*33*Ev, 256), 256>>>(goals_txt, text_emb, action_emb, pPOS, pX);

    // patch embed -> X rows 32..619 (+bias +POS)
    tgemm<<<dim3(Ev/128, CDIV(MPATCH,256)), 256, TGSMEM>>>(
        MPATCH, Ev, Ev, pXP, pWt,
        patch_b, pPOS, Ev, 1,
        pX, Ev, 0, 0, nullptr);

    for (int l = 0; l < Lv; l++) {
        ln_kernel<<<CDIV(MTv,8), 256>>>(pX, pH, ln1_s + l*Ev, ln1_b + l*Ev);

        tgemm<<<dim3(QKVLD/128, CDIV(MTv,256)), 256, TGSMEM>>>(   // QKV -> fp16
            MTv, QKVLD, Ev, pH, pWq + (size_t)l*QKVLD*Ev,
            nullptr, nullptr, 0, 0,
            nullptr, 0, 0, 0, pQ);

        fattn<<<dim3(5, ZH), 256, FASMEM>>>(pQ, pO);

        tgemm<<<dim3(Ev/128, CDIV(MTv,256)), 256, TGSMEM>>>(   // X += O @ proj + b
            MTv, Ev, Ev, pO, pWp + (size_t)l*Ev*Ev,
            proj_b + l*Ev, nullptr, 0, 0,
            pX, Ev, 1, 0, nullptr);

        ln_kernel<<<CDIV(MTv,8), 256>>>(pX, pH, ln2_s + l*Ev, ln2_b + l*Ev);

        tgemm<<<dim3(E4/128, CDIV(MTv,256)), 256, TGSMEM>>>(   // F = relu(h@W1+b1) -> fp16
            MTv, E4, Ev, pH, pW1 + (size_t)l*E4*Ev,
            ff_b1 + l*E4, nullptr, 0, 0,
            nullptr, 0, 0, 1, pF);

        tgemm<<<dim3(Ev/128, CDIV(MTv,256)), 256, TGSMEM>>>(   // X += F @ W2 + b2
            MTv, Ev, E4, pF, pW2 + (size_t)l*Ev*E4,
            ff_b2 + l*Ev, nullptr, 0, 0,
            pX, Ev, 1, 0, nullptr);
    }

    // head
    sgemm128<<<dim3(Ev/128, 1), 256>>>(
        Bv, Ev, Ev, pX + (size_t)620*Ev, Tv*Ev, hw1, Ev, pZ, Ev, hb1, 1);
    sgemm128<<<dim3(1, 1), 256>>>(
        Bv, AOUTv, Ev, pZ, Ev, hw2, AOUTv, out, AOUTv, hb2, 0);

    (void)in_sizes; (void)n_in; (void)out_size;
}